// round 1
// baseline (speedup 1.0000x reference)
#include <cuda_runtime.h>
#include <math.h>

// Problem constants
#define BB 4
#define TT 2048
#define CC 1024
#define HH 16
#define DD 64
#define MROWS (BB * TT)   // 8192

// Scratch (device globals — no allocation allowed in kernel_launch)
__device__ float g_q[BB * HH * TT * DD];
__device__ float g_k[BB * HH * TT * DD];
__device__ float g_v[BB * HH * TT * DD];
__device__ float g_att[BB * TT * CC];

// ---------------------------------------------------------------------------
// SGEMM: C = A[M,K] @ B[K,N] + bias[N]
// BM=128, BN=128, BK=16, 256 threads, 8x8 per-thread micro-tile.
// MODE 0: plain row-major output to Cout.
// MODE 1: QKV epilogue — scatter into Q/K/V buffers laid out [B,H,T,D].
// ---------------------------------------------------------------------------
template <int MODE>
__global__ __launch_bounds__(256) void sgemm_kernel(
    const float* __restrict__ A, const float* __restrict__ Bm,
    const float* __restrict__ bias, float* __restrict__ Cout,
    float* __restrict__ Qo, float* __restrict__ Ko, float* __restrict__ Vo,
    int M, int N, int K)
{
    __shared__ float As[16][132];  // transposed, padded for conflict-free stores
    __shared__ float Bs[16][128];

    const int tid = threadIdx.x;
    const int tx = tid & 15;        // 0..15 -> 8 cols each
    const int ty = tid >> 4;        // 0..15 -> 8 rows each
    const int bx = blockIdx.x;
    const int by = blockIdx.y;

    const float* Ablk = A + (size_t)by * 128 * K;
    const float* Bblk = Bm + (size_t)bx * 128;

    float acc[8][8];
#pragma unroll
    for (int i = 0; i < 8; i++)
#pragma unroll
        for (int j = 0; j < 8; j++) acc[i][j] = 0.0f;

    for (int k0 = 0; k0 < K; k0 += 16) {
        // Load A tile 128x16 (transposed into As)
#pragma unroll
        for (int it = 0; it < 2; it++) {
            int slot = tid + it * 256;      // 512 float4 slots
            int ar = slot >> 2;             // 0..127
            int ac4 = slot & 3;             // 0..3
            float4 a = *(const float4*)(Ablk + (size_t)ar * K + k0 + ac4 * 4);
            As[ac4 * 4 + 0][ar] = a.x;
            As[ac4 * 4 + 1][ar] = a.y;
            As[ac4 * 4 + 2][ar] = a.z;
            As[ac4 * 4 + 3][ar] = a.w;
        }
        // Load B tile 16x128
#pragma unroll
        for (int it = 0; it < 2; it++) {
            int slot = tid + it * 256;      // 512 float4 slots
            int br = slot >> 5;             // 0..15
            int bc4 = slot & 31;            // 0..31
            *(float4*)(&Bs[br][bc4 * 4]) =
                *(const float4*)(Bblk + (size_t)(k0 + br) * N + bc4 * 4);
        }
        __syncthreads();

#pragma unroll
        for (int kk = 0; kk < 16; kk++) {
            float a[8], b[8];
            *(float4*)&a[0] = *(const float4*)&As[kk][ty * 8];
            *(float4*)&a[4] = *(const float4*)&As[kk][ty * 8 + 4];
            *(float4*)&b[0] = *(const float4*)&Bs[kk][tx * 8];
            *(float4*)&b[4] = *(const float4*)&Bs[kk][tx * 8 + 4];
#pragma unroll
            for (int i = 0; i < 8; i++)
#pragma unroll
                for (int j = 0; j < 8; j++)
                    acc[i][j] = fmaf(a[i], b[j], acc[i][j]);
        }
        __syncthreads();
    }

    const int row0 = by * 128 + ty * 8;
    const int col0 = bx * 128 + tx * 8;

    float bs[8];
#pragma unroll
    for (int j = 0; j < 8; j++) bs[j] = bias[col0 + j];

    if (MODE == 0) {
#pragma unroll
        for (int i = 0; i < 8; i++) {
            float* dst = Cout + (size_t)(row0 + i) * N + col0;
            float4 o0 = make_float4(acc[i][0] + bs[0], acc[i][1] + bs[1],
                                    acc[i][2] + bs[2], acc[i][3] + bs[3]);
            float4 o1 = make_float4(acc[i][4] + bs[4], acc[i][5] + bs[5],
                                    acc[i][6] + bs[6], acc[i][7] + bs[7]);
            *(float4*)(dst) = o0;
            *(float4*)(dst + 4) = o1;
        }
    } else {
        // QKV scatter: col selects q/k/v and (h, d); the 8 cols share which/h.
        const int which = col0 >> 10;     // /1024
        const int c = col0 & 1023;
        const int h = c >> 6;             // /64
        const int d0 = c & 63;
        float* dstbase = (which == 0) ? Qo : ((which == 1) ? Ko : Vo);
#pragma unroll
        for (int i = 0; i < 8; i++) {
            int m = row0 + i;
            int b = m >> 11;              // /2048
            int t = m & 2047;
            float* dst = dstbase +
                ((((size_t)b * HH + h) * TT) + t) * DD + d0;
            float4 o0 = make_float4(acc[i][0] + bs[0], acc[i][1] + bs[1],
                                    acc[i][2] + bs[2], acc[i][3] + bs[3]);
            float4 o1 = make_float4(acc[i][4] + bs[4], acc[i][5] + bs[5],
                                    acc[i][6] + bs[6], acc[i][7] + bs[7]);
            *(float4*)(dst) = o0;
            *(float4*)(dst + 4) = o1;
        }
    }
}

// ---------------------------------------------------------------------------
// Causal flash attention, fp32. One CTA = one (b,h) x 64-query tile.
// 256 threads: thread t owns query row r = t/4 and a 16-wide slice (jg = t%4)
// of keys (for scores) / head dims (for output accum).
// Dynamic smem: Qs/Ks/Vs/Ps, each [64][68] floats (padded rows).
// ---------------------------------------------------------------------------
__global__ __launch_bounds__(256) void flash_kernel(
    const float* __restrict__ Q, const float* __restrict__ Kg,
    const float* __restrict__ Vg, float* __restrict__ Out)
{
    extern __shared__ float sm[];
    float* Qs = sm;                 // [64][68]
    float* Ks = sm + 64 * 68;
    float* Vs = sm + 2 * 64 * 68;
    float* Ps = sm + 3 * 64 * 68;

    const int tid = threadIdx.x;
    const int r = tid >> 2;         // query row within tile (0..63)
    const int jg = tid & 3;         // 16-wide slice index (0..3)
    const int qt = blockIdx.x;      // query tile
    const int bh = blockIdx.y;      // b*H + h

    const float* Qb = Q + (size_t)bh * TT * DD;
    const float* Kb = Kg + (size_t)bh * TT * DD;
    const float* Vb = Vg + (size_t)bh * TT * DD;

    // Load Q tile (64 x 64)
#pragma unroll
    for (int it = 0; it < 4; it++) {
        int slot = tid + it * 256;  // 1024 float4 slots
        int rr = slot >> 4;
        int c4 = slot & 15;
        *(float4*)(Qs + rr * 68 + c4 * 4) =
            *(const float4*)(Qb + ((size_t)qt * 64 + rr) * DD + c4 * 4);
    }

    float accv[16];
#pragma unroll
    for (int i = 0; i < 16; i++) accv[i] = 0.0f;
    float mrow = -3.0e38f;
    float lrow = 0.0f;

    const int qg = qt * 64 + r;     // global query index for this row

    for (int kv = 0; kv <= qt; kv++) {
        // Load K and V tiles
#pragma unroll
        for (int it = 0; it < 4; it++) {
            int slot = tid + it * 256;
            int rr = slot >> 4;
            int c4 = slot & 15;
            size_t src = ((size_t)kv * 64 + rr) * DD + c4 * 4;
            *(float4*)(Ks + rr * 68 + c4 * 4) = *(const float4*)(Kb + src);
            *(float4*)(Vs + rr * 68 + c4 * 4) = *(const float4*)(Vb + src);
        }
        __syncthreads();

        // Scores for this thread's 16 keys
        float s[16];
#pragma unroll
        for (int jj = 0; jj < 16; jj++) {
            int j = jg * 16 + jj;
            float sum = 0.0f;
#pragma unroll
            for (int k4 = 0; k4 < 16; k4++) {
                float4 q4 = *(const float4*)(Qs + r * 68 + k4 * 4);
                float4 k4v = *(const float4*)(Ks + j * 68 + k4 * 4);
                sum = fmaf(q4.x, k4v.x, sum);
                sum = fmaf(q4.y, k4v.y, sum);
                sum = fmaf(q4.z, k4v.z, sum);
                sum = fmaf(q4.w, k4v.w, sum);
            }
            s[jj] = sum * 0.125f;   // 1/sqrt(64)
        }

        if (kv == qt) {
#pragma unroll
            for (int jj = 0; jj < 16; jj++) {
                int kgl = kv * 64 + jg * 16 + jj;
                if (kgl > qg) s[jj] = -3.0e38f;
            }
        }

        // Row max across this thread's 16 + the other 3 threads of the row
        float mt = s[0];
#pragma unroll
        for (int jj = 1; jj < 16; jj++) mt = fmaxf(mt, s[jj]);
        mt = fmaxf(mt, __shfl_xor_sync(0xffffffffu, mt, 1));
        mt = fmaxf(mt, __shfl_xor_sync(0xffffffffu, mt, 2));

        float mnew = fmaxf(mrow, mt);
        float corr = __expf(mrow - mnew);

        float rs = 0.0f;
#pragma unroll
        for (int jj = 0; jj < 16; jj++) {
            float p = __expf(s[jj] - mnew);
            Ps[r * 68 + jg * 16 + jj] = p;
            rs += p;
        }
        rs += __shfl_xor_sync(0xffffffffu, rs, 1);
        rs += __shfl_xor_sync(0xffffffffu, rs, 2);

        lrow = lrow * corr + rs;
        mrow = mnew;
#pragma unroll
        for (int i = 0; i < 16; i++) accv[i] *= corr;

        __syncwarp();   // Ps row written by the 4 lanes of this row (same warp)

        // O += P @ V  (this thread: its row, dims jg*16 .. jg*16+15)
        const float* vbase = Vs + jg * 16;
#pragma unroll 4
        for (int j = 0; j < 64; j++) {
            float p = Ps[r * 68 + j];
            const float* vr = vbase + j * 68;
            float4 v0 = *(const float4*)(vr);
            float4 v1 = *(const float4*)(vr + 4);
            float4 v2 = *(const float4*)(vr + 8);
            float4 v3 = *(const float4*)(vr + 12);
            accv[0]  = fmaf(p, v0.x, accv[0]);
            accv[1]  = fmaf(p, v0.y, accv[1]);
            accv[2]  = fmaf(p, v0.z, accv[2]);
            accv[3]  = fmaf(p, v0.w, accv[3]);
            accv[4]  = fmaf(p, v1.x, accv[4]);
            accv[5]  = fmaf(p, v1.y, accv[5]);
            accv[6]  = fmaf(p, v1.z, accv[6]);
            accv[7]  = fmaf(p, v1.w, accv[7]);
            accv[8]  = fmaf(p, v2.x, accv[8]);
            accv[9]  = fmaf(p, v2.y, accv[9]);
            accv[10] = fmaf(p, v2.z, accv[10]);
            accv[11] = fmaf(p, v2.w, accv[11]);
            accv[12] = fmaf(p, v3.x, accv[12]);
            accv[13] = fmaf(p, v3.y, accv[13]);
            accv[14] = fmaf(p, v3.z, accv[14]);
            accv[15] = fmaf(p, v3.w, accv[15]);
        }
        __syncthreads();  // before next iteration reloads Ks/Vs
    }

    // Normalize and write out in [B,T,C] layout (c = h*64 + d)
    const float inv = 1.0f / lrow;
    const int b = bh >> 4;          // /16
    const int h = bh & 15;
    const int t = qt * 64 + r;
    float* dst = Out + ((size_t)b * TT + t) * CC + h * DD + jg * 16;
    float4 o;
    o = make_float4(accv[0] * inv, accv[1] * inv, accv[2] * inv, accv[3] * inv);
    *(float4*)(dst) = o;
    o = make_float4(accv[4] * inv, accv[5] * inv, accv[6] * inv, accv[7] * inv);
    *(float4*)(dst + 4) = o;
    o = make_float4(accv[8] * inv, accv[9] * inv, accv[10] * inv, accv[11] * inv);
    *(float4*)(dst + 8) = o;
    o = make_float4(accv[12] * inv, accv[13] * inv, accv[14] * inv, accv[15] * inv);
    *(float4*)(dst + 12) = o;
}

// ---------------------------------------------------------------------------
extern "C" void kernel_launch(void* const* d_in, const int* in_sizes, int n_in,
                              void* d_out, int out_size)
{
    (void)in_sizes; (void)n_in; (void)out_size;
    const float* x      = (const float*)d_in[0];
    const float* W_attn = (const float*)d_in[1];
    const float* b_attn = (const float*)d_in[2];
    const float* W_proj = (const float*)d_in[3];
    const float* b_proj = (const float*)d_in[4];
    float* out = (float*)d_out;

    float *q, *k, *v, *att;
    cudaGetSymbolAddress((void**)&q, g_q);
    cudaGetSymbolAddress((void**)&k, g_k);
    cudaGetSymbolAddress((void**)&v, g_v);
    cudaGetSymbolAddress((void**)&att, g_att);

    // 1) QKV GEMM with scatter epilogue: [8192,1024] @ [1024,3072]
    {
        dim3 grid(3072 / 128, MROWS / 128);
        sgemm_kernel<1><<<grid, 256>>>(x, W_attn, b_attn, nullptr,
                                       q, k, v, MROWS, 3 * CC, CC);
    }

    // 2) Causal flash attention
    {
        const int smem = 4 * 64 * 68 * (int)sizeof(float);  // 69632
        cudaFuncSetAttribute(flash_kernel,
                             cudaFuncAttributeMaxDynamicSharedMemorySize, smem);
        dim3 grid(TT / 64, BB * HH);
        flash_kernel<<<grid, 256, smem>>>(q, k, v, att);
    }

    // 3) Output projection: [8192,1024] @ [1024,1024] -> d_out
    {
        dim3 grid(CC / 128, MROWS / 128);
        sgemm_kernel<0><<<grid, 256>>>(att, W_proj, b_proj, out,
                                       nullptr, nullptr, nullptr,
                                       MROWS, CC, CC);
    }
}

// round 3
// speedup vs baseline: 1.1302x; 1.1302x over previous
#include <cuda_runtime.h>
#include <cuda_bf16.h>
#include <math.h>
#include <stdint.h>

// Problem constants
#define BB 4
#define TT 2048
#define CC 1024
#define HH 16
#define DD 64
#define MROWS (BB * TT)   // 8192

// ---------------------------------------------------------------------------
// Scratch (device globals)
// ---------------------------------------------------------------------------
__device__ __nv_bfloat16 g_xh[MROWS * CC], g_xl[MROWS * CC];        // x split  [M,K]
__device__ __nv_bfloat16 g_wah[3 * CC * CC], g_wal[3 * CC * CC];    // W_attn^T [N=3072,K]
__device__ __nv_bfloat16 g_wph[CC * CC], g_wpl[CC * CC];            // W_proj^T [N=1024,K]
__device__ __nv_bfloat16 g_ath[MROWS * CC], g_atl[MROWS * CC];      // att split [M,K]
__device__ float g_q[BB * HH * TT * DD];
__device__ float g_k[BB * HH * TT * DD];
__device__ float g_v[BB * HH * TT * DD];
__device__ float g_att[BB * TT * CC];

// ---------------------------------------------------------------------------
// mma.sync bf16 (sm_80 baseline PTX — works under compute_103 virtual arch)
// ---------------------------------------------------------------------------
__device__ __forceinline__ void mma_bf16(float* c, const uint32_t* a,
                                         const uint32_t* b) {
    asm volatile(
        "mma.sync.aligned.m16n8k16.row.col.f32.bf16.bf16.f32 "
        "{%0,%1,%2,%3}, {%4,%5,%6,%7}, {%8,%9}, {%0,%1,%2,%3};"
        : "+f"(c[0]), "+f"(c[1]), "+f"(c[2]), "+f"(c[3])
        : "r"(a[0]), "r"(a[1]), "r"(a[2]), "r"(a[3]), "r"(b[0]), "r"(b[1]));
}

// ---------------------------------------------------------------------------
// Prep: fp32 -> (bf16 hi, bf16 lo), elementwise (4 elems/thread)
// ---------------------------------------------------------------------------
__global__ void prep_split(const float* __restrict__ src,
                           __nv_bfloat16* __restrict__ hi,
                           __nv_bfloat16* __restrict__ lo) {
    int idx = blockIdx.x * blockDim.x + threadIdx.x;   // over N/4
    float4 v = ((const float4*)src)[idx];
    __nv_bfloat16 h0 = __float2bfloat16(v.x);
    __nv_bfloat16 h1 = __float2bfloat16(v.y);
    __nv_bfloat16 h2 = __float2bfloat16(v.z);
    __nv_bfloat16 h3 = __float2bfloat16(v.w);
    __nv_bfloat16 l0 = __float2bfloat16(v.x - __bfloat162float(h0));
    __nv_bfloat16 l1 = __float2bfloat16(v.y - __bfloat162float(h1));
    __nv_bfloat16 l2 = __float2bfloat16(v.z - __bfloat162float(h2));
    __nv_bfloat16 l3 = __float2bfloat16(v.w - __bfloat162float(h3));
    ((__nv_bfloat162*)hi)[idx * 2 + 0] = __nv_bfloat162(h0, h1);
    ((__nv_bfloat162*)hi)[idx * 2 + 1] = __nv_bfloat162(h2, h3);
    ((__nv_bfloat162*)lo)[idx * 2 + 0] = __nv_bfloat162(l0, l1);
    ((__nv_bfloat162*)lo)[idx * 2 + 1] = __nv_bfloat162(l2, l3);
}

// ---------------------------------------------------------------------------
// Prep: W [K,N] fp32 -> Wt hi/lo [N,K] bf16 (tiled transpose)
// ---------------------------------------------------------------------------
__global__ void prep_wt(const float* __restrict__ W,
                        __nv_bfloat16* __restrict__ Wht,
                        __nv_bfloat16* __restrict__ Wlt, int K, int N) {
    __shared__ float t[32][33];
    const int tx = threadIdx.x, ty = threadIdx.y;
    const int n0 = blockIdx.x * 32, k0 = blockIdx.y * 32;
#pragma unroll
    for (int i = 0; i < 4; i++)
        t[ty + i * 8][tx] = W[(size_t)(k0 + ty + i * 8) * N + n0 + tx];
    __syncthreads();
#pragma unroll
    for (int i = 0; i < 4; i++) {
        int n = n0 + ty + i * 8;
        int k = k0 + tx;
        float v = t[tx][ty + i * 8];
        __nv_bfloat16 h = __float2bfloat16(v);
        Wht[(size_t)n * K + k] = h;
        Wlt[(size_t)n * K + k] = __float2bfloat16(v - __bfloat162float(h));
    }
}

// ---------------------------------------------------------------------------
// mma.sync bf16 split-3 GEMM: C = A@B^T + bias
// A=[M,K] (Ah,Al), B=[N,K] (Bh,Bl). CTA 128x128, 8 warps 4x2, warp 32x64.
// K-chunk 16, 3-stage smem pipeline, one __syncthreads per chunk.
// Smem rows padded to 48B -> conflict-free fragment LDS.
// MODE 0: row-major out; MODE 1: QKV scatter into [B,H,T,D].
// ---------------------------------------------------------------------------
#define ROWB 48
#define TILE_B (128 * ROWB)       // 6144
#define STAGE_B (4 * TILE_B)      // 24576
#define NSTG 3
#define GEMM_SMEM (NSTG * STAGE_B)  // 73728

template <int MODE>
__global__ void __launch_bounds__(256) mma_gemm(
    const __nv_bfloat16* __restrict__ Ah_, const __nv_bfloat16* __restrict__ Al_,
    const __nv_bfloat16* __restrict__ Bh_, const __nv_bfloat16* __restrict__ Bl_,
    const float* __restrict__ bias,
    float* __restrict__ Cout, float* __restrict__ Qo,
    float* __restrict__ Ko, float* __restrict__ Vo,
    int N, int K)
{
    extern __shared__ char sm[];
    const int tid = threadIdx.x;
    const int wid = tid >> 5, lane = tid & 31;
    const int wm = wid >> 1, wn = wid & 1;
    const int g = lane >> 2, tg = lane & 3;
    const int m0 = blockIdx.y * 128, n0 = blockIdx.x * 128;

    const __nv_bfloat16* Ah = Ah_ + (size_t)m0 * K;
    const __nv_bfloat16* Al = Al_ + (size_t)m0 * K;
    const __nv_bfloat16* Bh = Bh_ + (size_t)n0 * K;
    const __nv_bfloat16* Bl = Bl_ + (size_t)n0 * K;

    // Global <-> smem staging mapping: thread loads 1 uint4 (8 bf16) per tile.
    const int grow = tid >> 1, gkq = tid & 1;
    const size_t goff0 = (size_t)grow * K + gkq * 8;
    const int soff = grow * ROWB + gkq * 16;

    float acc[2][8][4];
#pragma unroll
    for (int mt = 0; mt < 2; mt++)
#pragma unroll
        for (int nt = 0; nt < 8; nt++)
#pragma unroll
            for (int i = 0; i < 4; i++) acc[mt][nt][i] = 0.0f;

    // Prologue: stage chunk 0 into buffer 0
    {
        uint4 ra = *(const uint4*)(Ah + goff0);
        uint4 rb = *(const uint4*)(Al + goff0);
        uint4 rc = *(const uint4*)(Bh + goff0);
        uint4 rd = *(const uint4*)(Bl + goff0);
        *(uint4*)(sm + soff)              = ra;
        *(uint4*)(sm + TILE_B + soff)     = rb;
        *(uint4*)(sm + 2 * TILE_B + soff) = rc;
        *(uint4*)(sm + 3 * TILE_B + soff) = rd;
    }
    __syncthreads();

    const int NCH = K / 16;
    uint4 ra, rb, rc, rd;

    for (int c = 0; c < NCH; c++) {
        if (c + 1 < NCH) {
            size_t o = goff0 + (size_t)(c + 1) * 16;
            ra = *(const uint4*)(Ah + o);
            rb = *(const uint4*)(Al + o);
            rc = *(const uint4*)(Bh + o);
            rd = *(const uint4*)(Bl + o);
        }

        char* st = sm + (c % NSTG) * STAGE_B;

        // A fragments (hi and lo)
        uint32_t ah[2][4], al[2][4];
#pragma unroll
        for (int mt = 0; mt < 2; mt++) {
            char* base = st + (wm * 32 + mt * 16 + g) * ROWB + tg * 4;
            ah[mt][0] = *(const uint32_t*)(base);
            ah[mt][1] = *(const uint32_t*)(base + 8 * ROWB);
            ah[mt][2] = *(const uint32_t*)(base + 16);
            ah[mt][3] = *(const uint32_t*)(base + 8 * ROWB + 16);
            al[mt][0] = *(const uint32_t*)(base + TILE_B);
            al[mt][1] = *(const uint32_t*)(base + TILE_B + 8 * ROWB);
            al[mt][2] = *(const uint32_t*)(base + TILE_B + 16);
            al[mt][3] = *(const uint32_t*)(base + TILE_B + 8 * ROWB + 16);
        }

#pragma unroll
        for (int nt = 0; nt < 8; nt++) {
            char* bb = st + 2 * TILE_B + (wn * 64 + nt * 8 + g) * ROWB + tg * 4;
            uint32_t bh[2], bl[2];
            bh[0] = *(const uint32_t*)(bb);
            bh[1] = *(const uint32_t*)(bb + 16);
            bl[0] = *(const uint32_t*)(bb + TILE_B);
            bl[1] = *(const uint32_t*)(bb + TILE_B + 16);
#pragma unroll
            for (int mt = 0; mt < 2; mt++) {
                mma_bf16(acc[mt][nt], ah[mt], bh);
                mma_bf16(acc[mt][nt], al[mt], bh);
                mma_bf16(acc[mt][nt], ah[mt], bl);
            }
        }

        if (c + 1 < NCH) {
            char* st2 = sm + ((c + 1) % NSTG) * STAGE_B;
            *(uint4*)(st2 + soff)              = ra;
            *(uint4*)(st2 + TILE_B + soff)     = rb;
            *(uint4*)(st2 + 2 * TILE_B + soff) = rc;
            *(uint4*)(st2 + 3 * TILE_B + soff) = rd;
        }
        __syncthreads();
    }

    // Epilogue
#pragma unroll
    for (int mt = 0; mt < 2; mt++) {
#pragma unroll
        for (int nt = 0; nt < 8; nt++) {
            const int cg = n0 + wn * 64 + nt * 8 + tg * 2;
            const int r0g = m0 + wm * 32 + mt * 16 + g;
            const float b0 = __ldg(bias + cg);
            const float b1 = __ldg(bias + cg + 1);
            float2 v0 = make_float2(acc[mt][nt][0] + b0, acc[mt][nt][1] + b1);
            float2 v1 = make_float2(acc[mt][nt][2] + b0, acc[mt][nt][3] + b1);
            if (MODE == 0) {
                *(float2*)(Cout + (size_t)r0g * N + cg) = v0;
                *(float2*)(Cout + (size_t)(r0g + 8) * N + cg) = v1;
            } else {
                const int which = cg >> 10;
                const int c10 = cg & 1023;
                const int h = c10 >> 6;
                const int d = c10 & 63;
                float* base = (which == 0) ? Qo : ((which == 1) ? Ko : Vo);
                const int b0r = r0g >> 11, t0r = r0g & 2047;
                const int b1r = (r0g + 8) >> 11, t1r = (r0g + 8) & 2047;
                *(float2*)(base + ((((size_t)b0r * HH + h) * TT) + t0r) * DD + d) = v0;
                *(float2*)(base + ((((size_t)b1r * HH + h) * TT) + t1r) * DD + d) = v1;
            }
        }
    }
}

// ---------------------------------------------------------------------------
// Causal flash attention, fp32, with register-staged K/V prefetch.
// One CTA = one (b,h) x 64-query tile; 256 threads; thread t owns query row
// t/4 and a 16-wide slice (t%4) of keys/dims.
// ---------------------------------------------------------------------------
__global__ __launch_bounds__(256) void flash_kernel(
    const float* __restrict__ Q, const float* __restrict__ Kg,
    const float* __restrict__ Vg, float* __restrict__ Out)
{
    extern __shared__ float smf[];
    float* Qs = smf;                 // [64][68]
    float* Ks = smf + 64 * 68;
    float* Vs = smf + 2 * 64 * 68;
    float* Ps = smf + 3 * 64 * 68;

    const int tid = threadIdx.x;
    const int r = tid >> 2;
    const int jg = tid & 3;
    const int qt = blockIdx.x;
    const int bh = blockIdx.y;

    const float* Qb = Q + (size_t)bh * TT * DD;
    const float* Kb = Kg + (size_t)bh * TT * DD;
    const float* Vb = Vg + (size_t)bh * TT * DD;

    // Staging map: thread covers 4 float4 slots for K and 4 for V.
    const int srow[4] = { (tid) >> 4, (tid + 256) >> 4, (tid + 512) >> 4, (tid + 768) >> 4 };
    const int sc4 = tid & 15;

    // Prologue: load Q tile and K/V tile 0
#pragma unroll
    for (int it = 0; it < 4; it++) {
        int rr = srow[it];
        *(float4*)(Qs + rr * 68 + sc4 * 4) =
            *(const float4*)(Qb + ((size_t)qt * 64 + rr) * DD + sc4 * 4);
        size_t src = (size_t)rr * DD + sc4 * 4;
        *(float4*)(Ks + rr * 68 + sc4 * 4) = *(const float4*)(Kb + src);
        *(float4*)(Vs + rr * 68 + sc4 * 4) = *(const float4*)(Vb + src);
    }
    __syncthreads();

    float accv[16];
#pragma unroll
    for (int i = 0; i < 16; i++) accv[i] = 0.0f;
    float mrow = -3.0e38f;
    float lrow = 0.0f;

    const int qg = qt * 64 + r;

    for (int kv = 0; kv <= qt; kv++) {
        // Prefetch next K/V tile into registers (hide GMEM latency)
        float4 kpre[4], vpre[4];
        if (kv < qt) {
#pragma unroll
            for (int it = 0; it < 4; it++) {
                size_t src = ((size_t)(kv + 1) * 64 + srow[it]) * DD + sc4 * 4;
                kpre[it] = *(const float4*)(Kb + src);
                vpre[it] = *(const float4*)(Vb + src);
            }
        }

        // Scores for this thread's 16 keys (k4-outer: Q loaded once per k4)
        float s[16];
#pragma unroll
        for (int jj = 0; jj < 16; jj++) s[jj] = 0.0f;
#pragma unroll
        for (int k4 = 0; k4 < 16; k4++) {
            float4 q4 = *(const float4*)(Qs + r * 68 + k4 * 4);
#pragma unroll
            for (int jj = 0; jj < 16; jj++) {
                float4 kk = *(const float4*)(Ks + (jg * 16 + jj) * 68 + k4 * 4);
                s[jj] = fmaf(q4.x, kk.x, s[jj]);
                s[jj] = fmaf(q4.y, kk.y, s[jj]);
                s[jj] = fmaf(q4.z, kk.z, s[jj]);
                s[jj] = fmaf(q4.w, kk.w, s[jj]);
            }
        }
#pragma unroll
        for (int jj = 0; jj < 16; jj++) s[jj] *= 0.125f;

        if (kv == qt) {
#pragma unroll
            for (int jj = 0; jj < 16; jj++) {
                int kgl = kv * 64 + jg * 16 + jj;
                if (kgl > qg) s[jj] = -3.0e38f;
            }
        }

        float mt = s[0];
#pragma unroll
        for (int jj = 1; jj < 16; jj++) mt = fmaxf(mt, s[jj]);
        mt = fmaxf(mt, __shfl_xor_sync(0xffffffffu, mt, 1));
        mt = fmaxf(mt, __shfl_xor_sync(0xffffffffu, mt, 2));

        float mnew = fmaxf(mrow, mt);
        float corr = __expf(mrow - mnew);

        float rs = 0.0f;
#pragma unroll
        for (int jj = 0; jj < 16; jj++) {
            float p = __expf(s[jj] - mnew);
            Ps[r * 68 + jg * 16 + jj] = p;
            rs += p;
        }
        rs += __shfl_xor_sync(0xffffffffu, rs, 1);
        rs += __shfl_xor_sync(0xffffffffu, rs, 2);

        lrow = lrow * corr + rs;
        mrow = mnew;
#pragma unroll
        for (int i = 0; i < 16; i++) accv[i] *= corr;

        __syncwarp();   // Ps row written by the 4 lanes of this row (same warp)

        // O += P @ V
        const float* vbase = Vs + jg * 16;
#pragma unroll 4
        for (int j = 0; j < 64; j++) {
            float p = Ps[r * 68 + j];
            const float* vr = vbase + j * 68;
            float4 v0 = *(const float4*)(vr);
            float4 v1 = *(const float4*)(vr + 4);
            float4 v2 = *(const float4*)(vr + 8);
            float4 v3 = *(const float4*)(vr + 12);
            accv[0]  = fmaf(p, v0.x, accv[0]);
            accv[1]  = fmaf(p, v0.y, accv[1]);
            accv[2]  = fmaf(p, v0.z, accv[2]);
            accv[3]  = fmaf(p, v0.w, accv[3]);
            accv[4]  = fmaf(p, v1.x, accv[4]);
            accv[5]  = fmaf(p, v1.y, accv[5]);
            accv[6]  = fmaf(p, v1.z, accv[6]);
            accv[7]  = fmaf(p, v1.w, accv[7]);
            accv[8]  = fmaf(p, v2.x, accv[8]);
            accv[9]  = fmaf(p, v2.y, accv[9]);
            accv[10] = fmaf(p, v2.z, accv[10]);
            accv[11] = fmaf(p, v2.w, accv[11]);
            accv[12] = fmaf(p, v3.x, accv[12]);
            accv[13] = fmaf(p, v3.y, accv[13]);
            accv[14] = fmaf(p, v3.z, accv[14]);
            accv[15] = fmaf(p, v3.w, accv[15]);
        }

        __syncthreads();   // everyone done reading Ks/Vs
        if (kv < qt) {
#pragma unroll
            for (int it = 0; it < 4; it++) {
                *(float4*)(Ks + srow[it] * 68 + sc4 * 4) = kpre[it];
                *(float4*)(Vs + srow[it] * 68 + sc4 * 4) = vpre[it];
            }
            __syncthreads();  // new tile visible
        }
    }

    const float inv = 1.0f / lrow;
    const int b = bh >> 4;
    const int h = bh & 15;
    const int t = qt * 64 + r;
    float* dst = Out + ((size_t)b * TT + t) * CC + h * DD + jg * 16;
#pragma unroll
    for (int q = 0; q < 4; q++)
        *(float4*)(dst + q * 4) = make_float4(accv[q * 4] * inv, accv[q * 4 + 1] * inv,
                                              accv[q * 4 + 2] * inv, accv[q * 4 + 3] * inv);
}

// ---------------------------------------------------------------------------
extern "C" void kernel_launch(void* const* d_in, const int* in_sizes, int n_in,
                              void* d_out, int out_size)
{
    (void)in_sizes; (void)n_in; (void)out_size;
    const float* x      = (const float*)d_in[0];
    const float* W_attn = (const float*)d_in[1];
    const float* b_attn = (const float*)d_in[2];
    const float* W_proj = (const float*)d_in[3];
    const float* b_proj = (const float*)d_in[4];
    float* out = (float*)d_out;

    __nv_bfloat16 *xh, *xl, *wah, *wal, *wph, *wpl, *ath, *atl;
    float *q, *k, *v, *att;
    cudaGetSymbolAddress((void**)&xh, g_xh);
    cudaGetSymbolAddress((void**)&xl, g_xl);
    cudaGetSymbolAddress((void**)&wah, g_wah);
    cudaGetSymbolAddress((void**)&wal, g_wal);
    cudaGetSymbolAddress((void**)&wph, g_wph);
    cudaGetSymbolAddress((void**)&wpl, g_wpl);
    cudaGetSymbolAddress((void**)&ath, g_ath);
    cudaGetSymbolAddress((void**)&atl, g_atl);
    cudaGetSymbolAddress((void**)&q, g_q);
    cudaGetSymbolAddress((void**)&k, g_k);
    cudaGetSymbolAddress((void**)&v, g_v);
    cudaGetSymbolAddress((void**)&att, g_att);

    cudaFuncSetAttribute(mma_gemm<0>, cudaFuncAttributeMaxDynamicSharedMemorySize, GEMM_SMEM);
    cudaFuncSetAttribute(mma_gemm<1>, cudaFuncAttributeMaxDynamicSharedMemorySize, GEMM_SMEM);

    // 1) Split x into bf16 hi/lo
    prep_split<<<MROWS * CC / 4 / 256, 256>>>(x, xh, xl);

    // 2) Transpose+split weights
    {
        dim3 blk(32, 8);
        prep_wt<<<dim3(3 * CC / 32, CC / 32), blk>>>(W_attn, wah, wal, CC, 3 * CC);
        prep_wt<<<dim3(CC / 32, CC / 32), blk>>>(W_proj, wph, wpl, CC, CC);
    }

    // 3) QKV GEMM (mma.sync, scatter epilogue): [8192,1024] @ [1024,3072]
    mma_gemm<1><<<dim3(3 * CC / 128, MROWS / 128), 256, GEMM_SMEM>>>(
        xh, xl, wah, wal, b_attn, nullptr, q, k, v, 3 * CC, CC);

    // 4) Causal flash attention (fp32, prefetched)
    {
        const int smem = 4 * 64 * 68 * (int)sizeof(float);
        cudaFuncSetAttribute(flash_kernel,
                             cudaFuncAttributeMaxDynamicSharedMemorySize, smem);
        flash_kernel<<<dim3(TT / 64, BB * HH), 256, smem>>>(q, k, v, att);
    }

    // 5) Split att into bf16 hi/lo
    prep_split<<<MROWS * CC / 4 / 256, 256>>>(att, ath, atl);

    // 6) Projection GEMM (mma.sync): [8192,1024] @ [1024,1024] -> out
    mma_gemm<0><<<dim3(CC / 128, MROWS / 128), 256, GEMM_SMEM>>>(
        ath, atl, wph, wpl, b_proj, out, nullptr, nullptr, nullptr, CC, CC);
}

// round 4
// speedup vs baseline: 6.7895x; 6.0075x over previous
#include <cuda_runtime.h>
#include <cuda_bf16.h>
#include <cuda_fp16.h>
#include <math.h>
#include <stdint.h>

// Problem constants
#define BB 4
#define TT 2048
#define CC 1024
#define HH 16
#define DD 64
#define MROWS (BB * TT)   // 8192
#define QSC (0.125f * 1.44269504088896f)   // 1/sqrt(D) * log2(e), folded into Q

// ---------------------------------------------------------------------------
// Scratch (device globals)
// ---------------------------------------------------------------------------
__device__ __nv_bfloat16 g_xh[MROWS * CC], g_xl[MROWS * CC];        // x split  [M,K]
__device__ __nv_bfloat16 g_wah[3 * CC * CC], g_wal[3 * CC * CC];    // W_attn^T [N=3072,K]
__device__ __nv_bfloat16 g_wph[CC * CC], g_wpl[CC * CC];            // W_proj^T [N=1024,K]
__device__ __nv_bfloat16 g_qh[BB * HH * TT * DD], g_ql[BB * HH * TT * DD];  // [B,H,T,D]
__device__ __nv_bfloat16 g_kh[BB * HH * TT * DD], g_kl[BB * HH * TT * DD];  // [B,H,T,D]
__device__ __half        g_vh[BB * HH * DD * TT], g_vl[BB * HH * DD * TT];  // [B,H,D,T] (V^T)
__device__ __nv_bfloat16 g_ath[MROWS * CC], g_atl[MROWS * CC];      // att split [M,K]

// ---------------------------------------------------------------------------
// mma.sync helpers (sm_80 baseline PTX — works under compute_103 virtual arch)
// ---------------------------------------------------------------------------
__device__ __forceinline__ void mma_bf16(float* c, const uint32_t* a,
                                         const uint32_t* b) {
    asm volatile(
        "mma.sync.aligned.m16n8k16.row.col.f32.bf16.bf16.f32 "
        "{%0,%1,%2,%3}, {%4,%5,%6,%7}, {%8,%9}, {%0,%1,%2,%3};"
        : "+f"(c[0]), "+f"(c[1]), "+f"(c[2]), "+f"(c[3])
        : "r"(a[0]), "r"(a[1]), "r"(a[2]), "r"(a[3]), "r"(b[0]), "r"(b[1]));
}
__device__ __forceinline__ void mma_f16(float* c, const uint32_t* a,
                                        const uint32_t* b) {
    asm volatile(
        "mma.sync.aligned.m16n8k16.row.col.f32.f16.f16.f32 "
        "{%0,%1,%2,%3}, {%4,%5,%6,%7}, {%8,%9}, {%0,%1,%2,%3};"
        : "+f"(c[0]), "+f"(c[1]), "+f"(c[2]), "+f"(c[3])
        : "r"(a[0]), "r"(a[1]), "r"(a[2]), "r"(a[3]), "r"(b[0]), "r"(b[1]));
}
__device__ __forceinline__ float ex2f(float x) {
    float y;
    asm("ex2.approx.f32 %0, %1;" : "=f"(y) : "f"(x));
    return y;
}
__device__ __forceinline__ uint32_t pack_bf16(float lo, float hi) {
    __nv_bfloat162 h = __float22bfloat162_rn(make_float2(lo, hi));
    return *(uint32_t*)&h;
}
__device__ __forceinline__ uint32_t pack_f16(float lo, float hi) {
    __half2 h = __float22half2_rn(make_float2(lo, hi));
    return *(uint32_t*)&h;
}
__device__ __forceinline__ void split_store_bf16(__nv_bfloat16* hi, __nv_bfloat16* lo,
                                                 size_t i, float a, float b) {
    uint32_t hp = pack_bf16(a, b);
    float ha = __uint_as_float(hp << 16);
    float hb = __uint_as_float(hp & 0xffff0000u);
    *(uint32_t*)(hi + i) = hp;
    *(uint32_t*)(lo + i) = pack_bf16(a - ha, b - hb);
}
__device__ __forceinline__ void split_store_f16(__half* hi, __half* lo,
                                                size_t i, float v) {
    __half h = __float2half_rn(v);
    hi[i] = h;
    lo[i] = __float2half_rn(v - __half2float(h));
}
__device__ __forceinline__ void cp16(uint32_t s, const void* g) {
    asm volatile("cp.async.cg.shared.global [%0], [%1], 16;" :: "r"(s), "l"(g));
}
__device__ __forceinline__ void cp_commit() {
    asm volatile("cp.async.commit_group;" ::: "memory");
}
__device__ __forceinline__ void cp_wait1() {
    asm volatile("cp.async.wait_group 1;" ::: "memory");
}
__device__ __forceinline__ void cp_wait0() {
    asm volatile("cp.async.wait_group 0;" ::: "memory");
}

// ---------------------------------------------------------------------------
// Prep: fp32 -> (bf16 hi, bf16 lo), elementwise (4 elems/thread)
// ---------------------------------------------------------------------------
__global__ void prep_split(const float* __restrict__ src,
                           __nv_bfloat16* __restrict__ hi,
                           __nv_bfloat16* __restrict__ lo) {
    int idx = blockIdx.x * blockDim.x + threadIdx.x;
    float4 v = ((const float4*)src)[idx];
    split_store_bf16(hi, lo, (size_t)idx * 4, v.x, v.y);
    split_store_bf16(hi, lo, (size_t)idx * 4 + 2, v.z, v.w);
}

// ---------------------------------------------------------------------------
// Prep: W [K,N] fp32 -> Wt hi/lo [N,K] bf16 (tiled transpose)
// ---------------------------------------------------------------------------
__global__ void prep_wt(const float* __restrict__ W,
                        __nv_bfloat16* __restrict__ Wht,
                        __nv_bfloat16* __restrict__ Wlt, int K, int N) {
    __shared__ float t[32][33];
    const int tx = threadIdx.x, ty = threadIdx.y;
    const int n0 = blockIdx.x * 32, k0 = blockIdx.y * 32;
#pragma unroll
    for (int i = 0; i < 4; i++)
        t[ty + i * 8][tx] = W[(size_t)(k0 + ty + i * 8) * N + n0 + tx];
    __syncthreads();
#pragma unroll
    for (int i = 0; i < 4; i++) {
        int n = n0 + ty + i * 8;
        int k = k0 + tx;
        float v = t[tx][ty + i * 8];
        __nv_bfloat16 h = __float2bfloat16(v);
        Wht[(size_t)n * K + k] = h;
        Wlt[(size_t)n * K + k] = __float2bfloat16(v - __bfloat162float(h));
    }
}

// ---------------------------------------------------------------------------
// mma.sync bf16 split-3 GEMM: C = A@B^T + bias
// MODE 0: fp32 row-major out. MODE 1: QKV epilogue — Q,K -> bf16 hi/lo
// [B,H,T,D] (Q scaled by QSC); V -> fp16 hi/lo transposed [B,H,D,T].
// ---------------------------------------------------------------------------
#define ROWB 48
#define TILE_B (128 * ROWB)
#define STAGE_B (4 * TILE_B)
#define NSTG 3
#define GEMM_SMEM (NSTG * STAGE_B)

template <int MODE>
__global__ void __launch_bounds__(256, 2) mma_gemm(
    const __nv_bfloat16* __restrict__ Ah_, const __nv_bfloat16* __restrict__ Al_,
    const __nv_bfloat16* __restrict__ Bh_, const __nv_bfloat16* __restrict__ Bl_,
    const float* __restrict__ bias,
    float* __restrict__ Cout,
    __nv_bfloat16* __restrict__ Qh_o, __nv_bfloat16* __restrict__ Ql_o,
    __nv_bfloat16* __restrict__ Kh_o, __nv_bfloat16* __restrict__ Kl_o,
    __half* __restrict__ Vh_o, __half* __restrict__ Vl_o,
    int N, int K)
{
    extern __shared__ char smg[];
    const int tid = threadIdx.x;
    const int wid = tid >> 5, lane = tid & 31;
    const int wm = wid >> 1, wn = wid & 1;
    const int g = lane >> 2, tg = lane & 3;
    const int m0 = blockIdx.y * 128, n0 = blockIdx.x * 128;

    const __nv_bfloat16* Ah = Ah_ + (size_t)m0 * K;
    const __nv_bfloat16* Al = Al_ + (size_t)m0 * K;
    const __nv_bfloat16* Bh = Bh_ + (size_t)n0 * K;
    const __nv_bfloat16* Bl = Bl_ + (size_t)n0 * K;

    const int grow = tid >> 1, gkq = tid & 1;
    const size_t goff0 = (size_t)grow * K + gkq * 8;
    const int soff = grow * ROWB + gkq * 16;

    float acc[2][8][4];
#pragma unroll
    for (int mt = 0; mt < 2; mt++)
#pragma unroll
        for (int nt = 0; nt < 8; nt++)
#pragma unroll
            for (int i = 0; i < 4; i++) acc[mt][nt][i] = 0.0f;

    {
        uint4 ra = *(const uint4*)(Ah + goff0);
        uint4 rb = *(const uint4*)(Al + goff0);
        uint4 rc = *(const uint4*)(Bh + goff0);
        uint4 rd = *(const uint4*)(Bl + goff0);
        *(uint4*)(smg + soff)              = ra;
        *(uint4*)(smg + TILE_B + soff)     = rb;
        *(uint4*)(smg + 2 * TILE_B + soff) = rc;
        *(uint4*)(smg + 3 * TILE_B + soff) = rd;
    }
    __syncthreads();

    const int NCH = K / 16;
    uint4 ra, rb, rc, rd;

    for (int c = 0; c < NCH; c++) {
        if (c + 1 < NCH) {
            size_t o = goff0 + (size_t)(c + 1) * 16;
            ra = *(const uint4*)(Ah + o);
            rb = *(const uint4*)(Al + o);
            rc = *(const uint4*)(Bh + o);
            rd = *(const uint4*)(Bl + o);
        }

        char* st = smg + (c % NSTG) * STAGE_B;

        uint32_t ah[2][4], al[2][4];
#pragma unroll
        for (int mt = 0; mt < 2; mt++) {
            char* base = st + (wm * 32 + mt * 16 + g) * ROWB + tg * 4;
            ah[mt][0] = *(const uint32_t*)(base);
            ah[mt][1] = *(const uint32_t*)(base + 8 * ROWB);
            ah[mt][2] = *(const uint32_t*)(base + 16);
            ah[mt][3] = *(const uint32_t*)(base + 8 * ROWB + 16);
            al[mt][0] = *(const uint32_t*)(base + TILE_B);
            al[mt][1] = *(const uint32_t*)(base + TILE_B + 8 * ROWB);
            al[mt][2] = *(const uint32_t*)(base + TILE_B + 16);
            al[mt][3] = *(const uint32_t*)(base + TILE_B + 8 * ROWB + 16);
        }

#pragma unroll
        for (int nt = 0; nt < 8; nt++) {
            char* bb = st + 2 * TILE_B + (wn * 64 + nt * 8 + g) * ROWB + tg * 4;
            uint32_t bhf[2], blf[2];
            bhf[0] = *(const uint32_t*)(bb);
            bhf[1] = *(const uint32_t*)(bb + 16);
            blf[0] = *(const uint32_t*)(bb + TILE_B);
            blf[1] = *(const uint32_t*)(bb + TILE_B + 16);
#pragma unroll
            for (int mt = 0; mt < 2; mt++) {
                mma_bf16(acc[mt][nt], ah[mt], bhf);
                mma_bf16(acc[mt][nt], al[mt], bhf);
                mma_bf16(acc[mt][nt], ah[mt], blf);
            }
        }

        if (c + 1 < NCH) {
            char* st2 = smg + ((c + 1) % NSTG) * STAGE_B;
            *(uint4*)(st2 + soff)              = ra;
            *(uint4*)(st2 + TILE_B + soff)     = rb;
            *(uint4*)(st2 + 2 * TILE_B + soff) = rc;
            *(uint4*)(st2 + 3 * TILE_B + soff) = rd;
        }
        __syncthreads();
    }

    // Epilogue
#pragma unroll
    for (int mt = 0; mt < 2; mt++) {
#pragma unroll
        for (int nt = 0; nt < 8; nt++) {
            const int cg = n0 + wn * 64 + nt * 8 + tg * 2;
            const int r0g = m0 + wm * 32 + mt * 16 + g;
            const float b0 = __ldg(bias + cg);
            const float b1 = __ldg(bias + cg + 1);
            float f00 = acc[mt][nt][0] + b0, f01 = acc[mt][nt][1] + b1;
            float f10 = acc[mt][nt][2] + b0, f11 = acc[mt][nt][3] + b1;
            if (MODE == 0) {
                *(float2*)(Cout + (size_t)r0g * N + cg) = make_float2(f00, f01);
                *(float2*)(Cout + (size_t)(r0g + 8) * N + cg) = make_float2(f10, f11);
            } else {
                const int which = cg >> 10;
                const int c10 = cg & 1023;
                const int h = c10 >> 6;
                const int d = c10 & 63;
                const int br = r0g >> 11, tr = r0g & 2047;
                if (which == 0) {
                    size_t i0 = ((((size_t)br * HH + h) * TT) + tr) * DD + d;
                    split_store_bf16(Qh_o, Ql_o, i0, f00 * QSC, f01 * QSC);
                    split_store_bf16(Qh_o, Ql_o, i0 + 8 * DD, f10 * QSC, f11 * QSC);
                } else if (which == 1) {
                    size_t i0 = ((((size_t)br * HH + h) * TT) + tr) * DD + d;
                    split_store_bf16(Kh_o, Kl_o, i0, f00, f01);
                    split_store_bf16(Kh_o, Kl_o, i0 + 8 * DD, f10, f11);
                } else {
                    size_t i0 = (((size_t)br * HH + h) * DD + d) * TT + tr;
                    split_store_f16(Vh_o, Vl_o, i0, f00);
                    split_store_f16(Vh_o, Vl_o, i0 + TT, f01);
                    split_store_f16(Vh_o, Vl_o, i0 + 8, f10);
                    split_store_f16(Vh_o, Vl_o, i0 + TT + 8, f11);
                }
            }
        }
    }
}

// ---------------------------------------------------------------------------
// Flash attention on mma.sync.
// CTA = 64 queries (4 warps x 16 rows), KV tiles of 64, 2-stage cp.async
// double buffer. S = Qh*Kh + Ql*Kh + Qh*Kl (bf16, fp32-exact); softmax in
// log2 domain (Q pre-scaled); P stays in registers (C-frag == next A-frag),
// packed to fp16; O += P*(Vh + Vl) fp16. Output -> att bf16 hi/lo split.
// ---------------------------------------------------------------------------
#define ROWF 144
#define TILEF (64 * ROWF)   // 9216
#define FL_QH 0
#define FL_QL TILEF
#define FL_ST(s) (2 * TILEF + (s) * 4 * TILEF)
#define FL_SMEM (10 * TILEF)  // 92160

__global__ void __launch_bounds__(128) flash_mma(
    const __nv_bfloat16* __restrict__ Qh, const __nv_bfloat16* __restrict__ Ql,
    const __nv_bfloat16* __restrict__ Kh, const __nv_bfloat16* __restrict__ Kl,
    const __half* __restrict__ Vh, const __half* __restrict__ Vl,
    __nv_bfloat16* __restrict__ ath, __nv_bfloat16* __restrict__ atl)
{
    extern __shared__ char smf[];
    const uint32_t sbase = (uint32_t)__cvta_generic_to_shared(smf);
    const int tid = threadIdx.x, wid = tid >> 5, lane = tid & 31;
    const int g = lane >> 2, tg = lane & 3;
    const int qt = 31 - blockIdx.x;     // longest CTAs first
    const int bh = blockIdx.y;

    const __nv_bfloat16* Qhb = Qh + (size_t)bh * TT * DD;
    const __nv_bfloat16* Qlb = Ql + (size_t)bh * TT * DD;
    const __nv_bfloat16* Khb = Kh + (size_t)bh * TT * DD;
    const __nv_bfloat16* Klb = Kl + (size_t)bh * TT * DD;
    const __half* Vhb = Vh + (size_t)bh * DD * TT;
    const __half* Vlb = Vl + (size_t)bh * DD * TT;

#define ISSUE_KV(stg, kvi) do {                                                \
    const uint32_t _sb = sbase + FL_ST(stg);                                   \
    _Pragma("unroll")                                                          \
    for (int _i = 0; _i < 4; _i++) {                                           \
        int _ch = _i * 128 + tid;                                              \
        int _row = _ch >> 3, _c = _ch & 7;                                     \
        uint32_t _so = _sb + _row * ROWF + _c * 16;                            \
        cp16(_so,         Khb + (size_t)(kvi) * 4096 + _ch * 8);               \
        cp16(_so + TILEF, Klb + (size_t)(kvi) * 4096 + _ch * 8);               \
        uint32_t _so2 = _sb + 2 * TILEF + _row * ROWF + _c * 16;               \
        size_t _vo = (size_t)_row * TT + (size_t)(kvi) * 64 + _c * 8;          \
        cp16(_so2,         Vhb + _vo);                                         \
        cp16(_so2 + TILEF, Vlb + _vo);                                         \
    }                                                                          \
} while (0)

    // Prologue: Q tile (group 0), KV tile 0 (group 1)
#pragma unroll
    for (int i = 0; i < 4; i++) {
        int ch = i * 128 + tid;
        int row = ch >> 3, c = ch & 7;
        uint32_t so = sbase + row * ROWF + c * 16;
        cp16(so + FL_QH, Qhb + (size_t)qt * 4096 + ch * 8);
        cp16(so + FL_QL, Qlb + (size_t)qt * 4096 + ch * 8);
    }
    cp_commit();
    ISSUE_KV(0, 0);
    cp_commit();
    cp_wait1();          // Q group done
    __syncthreads();

    // Q fragments (held in registers for the whole kernel)
    uint32_t qfh[4][4], qfl[4][4];
    {
        const int arow = (wid * 16 + g) * ROWF + tg * 4;
#pragma unroll
        for (int j = 0; j < 4; j++) {
            int o = arow + j * 32;
            qfh[j][0] = *(const uint32_t*)(smf + FL_QH + o);
            qfh[j][1] = *(const uint32_t*)(smf + FL_QH + o + 8 * ROWF);
            qfh[j][2] = *(const uint32_t*)(smf + FL_QH + o + 16);
            qfh[j][3] = *(const uint32_t*)(smf + FL_QH + o + 8 * ROWF + 16);
            qfl[j][0] = *(const uint32_t*)(smf + FL_QL + o);
            qfl[j][1] = *(const uint32_t*)(smf + FL_QL + o + 8 * ROWF);
            qfl[j][2] = *(const uint32_t*)(smf + FL_QL + o + 16);
            qfl[j][3] = *(const uint32_t*)(smf + FL_QL + o + 8 * ROWF + 16);
        }
    }

    float oacc[8][4];
#pragma unroll
    for (int i = 0; i < 8; i++)
#pragma unroll
        for (int jj = 0; jj < 4; jj++) oacc[i][jj] = 0.0f;
    float m0 = -1e30f, m1 = -1e30f, l0 = 0.0f, l1 = 0.0f;

    for (int kv = 0; kv <= qt; kv++) {
        const int s = kv & 1;
        if (kv < qt) { ISSUE_KV(s ^ 1, kv + 1); cp_commit(); cp_wait1(); }
        else cp_wait0();
        __syncthreads();

        const char* KHs = smf + FL_ST(s);
        const char* KLs = KHs + TILEF;
        const char* VHs = KHs + 2 * TILEF;
        const char* VLs = KHs + 3 * TILEF;

        // S = Q @ K^T (3-term split)
        float sa[8][4];
#pragma unroll
        for (int nt = 0; nt < 8; nt++)
#pragma unroll
            for (int jj = 0; jj < 4; jj++) sa[nt][jj] = 0.0f;

#pragma unroll
        for (int j = 0; j < 4; j++) {
#pragma unroll
            for (int nt = 0; nt < 8; nt++) {
                int o = (nt * 8 + g) * ROWF + j * 32 + tg * 4;
                uint32_t kb[2], klb2[2];
                kb[0]  = *(const uint32_t*)(KHs + o);
                kb[1]  = *(const uint32_t*)(KHs + o + 16);
                klb2[0] = *(const uint32_t*)(KLs + o);
                klb2[1] = *(const uint32_t*)(KLs + o + 16);
                mma_bf16(sa[nt], qfh[j], kb);
                mma_bf16(sa[nt], qfl[j], kb);
                mma_bf16(sa[nt], qfh[j], klb2);
            }
        }

        // Causal mask (diagonal tile only)
        if (kv == qt) {
            const int r0 = wid * 16 + g, r1 = r0 + 8;
#pragma unroll
            for (int nt = 0; nt < 8; nt++) {
                int c0 = nt * 8 + tg * 2;
                if (c0 > r0)     sa[nt][0] = -1e30f;
                if (c0 + 1 > r0) sa[nt][1] = -1e30f;
                if (c0 > r1)     sa[nt][2] = -1e30f;
                if (c0 + 1 > r1) sa[nt][3] = -1e30f;
            }
        }

        // Online softmax (log2 domain)
        float mt0 = sa[0][0], mt1 = sa[0][2];
#pragma unroll
        for (int nt = 0; nt < 8; nt++) {
            mt0 = fmaxf(mt0, fmaxf(sa[nt][0], sa[nt][1]));
            mt1 = fmaxf(mt1, fmaxf(sa[nt][2], sa[nt][3]));
        }
        mt0 = fmaxf(mt0, __shfl_xor_sync(0xffffffffu, mt0, 1));
        mt0 = fmaxf(mt0, __shfl_xor_sync(0xffffffffu, mt0, 2));
        mt1 = fmaxf(mt1, __shfl_xor_sync(0xffffffffu, mt1, 1));
        mt1 = fmaxf(mt1, __shfl_xor_sync(0xffffffffu, mt1, 2));

        float mn0 = fmaxf(m0, mt0), mn1 = fmaxf(m1, mt1);
        float cr0 = ex2f(m0 - mn0), cr1 = ex2f(m1 - mn1);
        m0 = mn0; m1 = mn1;

        float s0 = 0.0f, s1 = 0.0f;
#pragma unroll
        for (int nt = 0; nt < 8; nt++) {
            sa[nt][0] = ex2f(sa[nt][0] - mn0);
            sa[nt][1] = ex2f(sa[nt][1] - mn0);
            sa[nt][2] = ex2f(sa[nt][2] - mn1);
            sa[nt][3] = ex2f(sa[nt][3] - mn1);
            s0 += sa[nt][0] + sa[nt][1];
            s1 += sa[nt][2] + sa[nt][3];
        }
        s0 += __shfl_xor_sync(0xffffffffu, s0, 1);
        s0 += __shfl_xor_sync(0xffffffffu, s0, 2);
        s1 += __shfl_xor_sync(0xffffffffu, s1, 1);
        s1 += __shfl_xor_sync(0xffffffffu, s1, 2);
        l0 = l0 * cr0 + s0;
        l1 = l1 * cr1 + s1;

#pragma unroll
        for (int nt = 0; nt < 8; nt++) {
            oacc[nt][0] *= cr0; oacc[nt][1] *= cr0;
            oacc[nt][2] *= cr1; oacc[nt][3] *= cr1;
        }

        // Pack P to fp16 A-fragments (C-frag layout == A-frag layout)
        uint32_t pa[4][4];
#pragma unroll
        for (int j = 0; j < 4; j++) {
            pa[j][0] = pack_f16(sa[2 * j][0], sa[2 * j][1]);
            pa[j][1] = pack_f16(sa[2 * j][2], sa[2 * j][3]);
            pa[j][2] = pack_f16(sa[2 * j + 1][0], sa[2 * j + 1][1]);
            pa[j][3] = pack_f16(sa[2 * j + 1][2], sa[2 * j + 1][3]);
        }

        // O += P @ V (V split into fp16 hi+lo)
#pragma unroll
        for (int j = 0; j < 4; j++) {
#pragma unroll
            for (int nt = 0; nt < 8; nt++) {
                int o = (nt * 8 + g) * ROWF + j * 32 + tg * 4;
                uint32_t vb[2];
                vb[0] = *(const uint32_t*)(VHs + o);
                vb[1] = *(const uint32_t*)(VHs + o + 16);
                mma_f16(oacc[nt], pa[j], vb);
                vb[0] = *(const uint32_t*)(VLs + o);
                vb[1] = *(const uint32_t*)(VLs + o + 16);
                mma_f16(oacc[nt], pa[j], vb);
            }
        }
        __syncthreads();   // all reads of stage s done before it is refilled
    }

    // Epilogue: normalize, split to bf16 hi/lo att [M=B*T, C] (c = h*64+d)
    const float i0 = 1.0f / l0, i1 = 1.0f / l1;
    const int b = bh >> 4, h = bh & 15;
    const int t0 = qt * 64 + wid * 16 + g;
    const size_t row0 = ((size_t)b * TT + t0) * CC + h * DD;
    const size_t row1 = row0 + (size_t)8 * CC;
#pragma unroll
    for (int nt = 0; nt < 8; nt++) {
        const int d = nt * 8 + tg * 2;
        split_store_bf16(ath, atl, row0 + d, oacc[nt][0] * i0, oacc[nt][1] * i0);
        split_store_bf16(ath, atl, row1 + d, oacc[nt][2] * i1, oacc[nt][3] * i1);
    }
#undef ISSUE_KV
}

// ---------------------------------------------------------------------------
extern "C" void kernel_launch(void* const* d_in, const int* in_sizes, int n_in,
                              void* d_out, int out_size)
{
    (void)in_sizes; (void)n_in; (void)out_size;
    const float* x      = (const float*)d_in[0];
    const float* W_attn = (const float*)d_in[1];
    const float* b_attn = (const float*)d_in[2];
    const float* W_proj = (const float*)d_in[3];
    const float* b_proj = (const float*)d_in[4];
    float* out = (float*)d_out;

    __nv_bfloat16 *xh, *xl, *wah, *wal, *wph, *wpl, *ath, *atl;
    __nv_bfloat16 *qh, *ql, *kh, *kl;
    __half *vh, *vl;
    cudaGetSymbolAddress((void**)&xh, g_xh);
    cudaGetSymbolAddress((void**)&xl, g_xl);
    cudaGetSymbolAddress((void**)&wah, g_wah);
    cudaGetSymbolAddress((void**)&wal, g_wal);
    cudaGetSymbolAddress((void**)&wph, g_wph);
    cudaGetSymbolAddress((void**)&wpl, g_wpl);
    cudaGetSymbolAddress((void**)&ath, g_ath);
    cudaGetSymbolAddress((void**)&atl, g_atl);
    cudaGetSymbolAddress((void**)&qh, g_qh);
    cudaGetSymbolAddress((void**)&ql, g_ql);
    cudaGetSymbolAddress((void**)&kh, g_kh);
    cudaGetSymbolAddress((void**)&kl, g_kl);
    cudaGetSymbolAddress((void**)&vh, g_vh);
    cudaGetSymbolAddress((void**)&vl, g_vl);

    cudaFuncSetAttribute(mma_gemm<0>, cudaFuncAttributeMaxDynamicSharedMemorySize, GEMM_SMEM);
    cudaFuncSetAttribute(mma_gemm<1>, cudaFuncAttributeMaxDynamicSharedMemorySize, GEMM_SMEM);
    cudaFuncSetAttribute(flash_mma, cudaFuncAttributeMaxDynamicSharedMemorySize, FL_SMEM);

    // 1) Split x into bf16 hi/lo
    prep_split<<<MROWS * CC / 4 / 256, 256>>>(x, xh, xl);

    // 2) Transpose+split weights
    {
        dim3 blk(32, 8);
        prep_wt<<<dim3(3 * CC / 32, CC / 32), blk>>>(W_attn, wah, wal, CC, 3 * CC);
        prep_wt<<<dim3(CC / 32, CC / 32), blk>>>(W_proj, wph, wpl, CC, CC);
    }

    // 3) QKV GEMM -> q/k bf16 hi/lo, v^T fp16 hi/lo
    mma_gemm<1><<<dim3(3 * CC / 128, MROWS / 128), 256, GEMM_SMEM>>>(
        xh, xl, wah, wal, b_attn, nullptr, qh, ql, kh, kl, vh, vl, 3 * CC, CC);

    // 4) Flash attention (tensor cores) -> att bf16 hi/lo
    flash_mma<<<dim3(TT / 64, BB * HH), 128, FL_SMEM>>>(
        qh, ql, kh, kl, vh, vl, ath, atl);

    // 5) Projection GEMM -> out
    mma_gemm<0><<<dim3(CC / 128, MROWS / 128), 256, GEMM_SMEM>>>(
        ath, atl, wph, wpl, b_proj, out,
        nullptr, nullptr, nullptr, nullptr, nullptr, nullptr, CC, CC);
}

// round 5
// speedup vs baseline: 7.5217x; 1.1078x over previous
#include <cuda_runtime.h>
#include <cuda_bf16.h>
#include <cuda_fp16.h>
#include <math.h>
#include <stdint.h>

// Problem constants
#define BB 4
#define TT 2048
#define CC 1024
#define HH 16
#define DD 64
#define MROWS (BB * TT)   // 8192
#define QSC (0.125f * 1.44269504088896f)   // 1/sqrt(D) * log2(e), folded into Q

// ---------------------------------------------------------------------------
// Scratch (device globals)
// ---------------------------------------------------------------------------
__device__ __nv_bfloat16 g_xh[MROWS * CC], g_xl[MROWS * CC];        // x split  [M,K]
__device__ __nv_bfloat16 g_wah[3 * CC * CC], g_wal[3 * CC * CC];    // W_attn^T [N=3072,K]
__device__ __nv_bfloat16 g_wph[CC * CC], g_wpl[CC * CC];            // W_proj^T [N=1024,K]
__device__ __nv_bfloat16 g_qh[BB * HH * TT * DD], g_ql[BB * HH * TT * DD];  // [B,H,T,D]
__device__ __nv_bfloat16 g_kh[BB * HH * TT * DD], g_kl[BB * HH * TT * DD];  // [B,H,T,D]
__device__ __half        g_vh[BB * HH * DD * TT], g_vl[BB * HH * DD * TT];  // [B,H,D,T] (V^T)
__device__ __nv_bfloat16 g_ath[MROWS * CC], g_atl[MROWS * CC];      // att split [M,K]

// ---------------------------------------------------------------------------
// PTX helpers
// ---------------------------------------------------------------------------
__device__ __forceinline__ void mma_bf16(float* c, const uint32_t* a,
                                         const uint32_t* b) {
    asm volatile(
        "mma.sync.aligned.m16n8k16.row.col.f32.bf16.bf16.f32 "
        "{%0,%1,%2,%3}, {%4,%5,%6,%7}, {%8,%9}, {%0,%1,%2,%3};"
        : "+f"(c[0]), "+f"(c[1]), "+f"(c[2]), "+f"(c[3])
        : "r"(a[0]), "r"(a[1]), "r"(a[2]), "r"(a[3]), "r"(b[0]), "r"(b[1]));
}
__device__ __forceinline__ void mma_f16(float* c, const uint32_t* a,
                                        const uint32_t* b) {
    asm volatile(
        "mma.sync.aligned.m16n8k16.row.col.f32.f16.f16.f32 "
        "{%0,%1,%2,%3}, {%4,%5,%6,%7}, {%8,%9}, {%0,%1,%2,%3};"
        : "+f"(c[0]), "+f"(c[1]), "+f"(c[2]), "+f"(c[3])
        : "r"(a[0]), "r"(a[1]), "r"(a[2]), "r"(a[3]), "r"(b[0]), "r"(b[1]));
}
__device__ __forceinline__ void ldsm4(uint32_t* r, uint32_t addr) {
    asm volatile("ldmatrix.sync.aligned.m8n8.x4.shared.b16 {%0,%1,%2,%3}, [%4];"
                 : "=r"(r[0]), "=r"(r[1]), "=r"(r[2]), "=r"(r[3]) : "r"(addr));
}
__device__ __forceinline__ float ex2f(float x) {
    float y;
    asm("ex2.approx.f32 %0, %1;" : "=f"(y) : "f"(x));
    return y;
}
__device__ __forceinline__ uint32_t pack_bf16(float lo, float hi) {
    __nv_bfloat162 h = __float22bfloat162_rn(make_float2(lo, hi));
    return *(uint32_t*)&h;
}
__device__ __forceinline__ uint32_t pack_f16(float lo, float hi) {
    __half2 h = __float22half2_rn(make_float2(lo, hi));
    return *(uint32_t*)&h;
}
__device__ __forceinline__ void split_store_bf16(__nv_bfloat16* hi, __nv_bfloat16* lo,
                                                 size_t i, float a, float b) {
    uint32_t hp = pack_bf16(a, b);
    float ha = __uint_as_float(hp << 16);
    float hb = __uint_as_float(hp & 0xffff0000u);
    *(uint32_t*)(hi + i) = hp;
    *(uint32_t*)(lo + i) = pack_bf16(a - ha, b - hb);
}
__device__ __forceinline__ void split_store_f16(__half* hi, __half* lo,
                                                size_t i, float v) {
    __half h = __float2half_rn(v);
    hi[i] = h;
    lo[i] = __float2half_rn(v - __half2float(h));
}
__device__ __forceinline__ void cp16(uint32_t s, const void* g) {
    asm volatile("cp.async.cg.shared.global [%0], [%1], 16;" :: "r"(s), "l"(g));
}
__device__ __forceinline__ void cp_commit() {
    asm volatile("cp.async.commit_group;" ::: "memory");
}
__device__ __forceinline__ void cp_wait2() {
    asm volatile("cp.async.wait_group 2;" ::: "memory");
}
__device__ __forceinline__ void cp_wait1() {
    asm volatile("cp.async.wait_group 1;" ::: "memory");
}
__device__ __forceinline__ void cp_wait0() {
    asm volatile("cp.async.wait_group 0;" ::: "memory");
}

// ---------------------------------------------------------------------------
// Prep kernels
// ---------------------------------------------------------------------------
__global__ void prep_split(const float* __restrict__ src,
                           __nv_bfloat16* __restrict__ hi,
                           __nv_bfloat16* __restrict__ lo) {
    int idx = blockIdx.x * blockDim.x + threadIdx.x;
    float4 v = ((const float4*)src)[idx];
    split_store_bf16(hi, lo, (size_t)idx * 4, v.x, v.y);
    split_store_bf16(hi, lo, (size_t)idx * 4 + 2, v.z, v.w);
}

__global__ void prep_wt(const float* __restrict__ W,
                        __nv_bfloat16* __restrict__ Wht,
                        __nv_bfloat16* __restrict__ Wlt, int K, int N) {
    __shared__ float t[32][33];
    const int tx = threadIdx.x, ty = threadIdx.y;
    const int n0 = blockIdx.x * 32, k0 = blockIdx.y * 32;
#pragma unroll
    for (int i = 0; i < 4; i++)
        t[ty + i * 8][tx] = W[(size_t)(k0 + ty + i * 8) * N + n0 + tx];
    __syncthreads();
#pragma unroll
    for (int i = 0; i < 4; i++) {
        int n = n0 + ty + i * 8;
        int k = k0 + tx;
        float v = t[tx][ty + i * 8];
        __nv_bfloat16 h = __float2bfloat16(v);
        Wht[(size_t)n * K + k] = h;
        Wlt[(size_t)n * K + k] = __float2bfloat16(v - __bfloat162float(h));
    }
}

// ---------------------------------------------------------------------------
// mma.sync bf16 split-3 GEMM, cp.async 4-stage pipeline + ldmatrix frags.
// C = A@B^T + bias. CTA 128x128, 8 warps (4x2), warp tile 32x64, K-chunk 16.
// MODE 0: fp32 row-major out. MODE 1: QKV epilogue.
// ---------------------------------------------------------------------------
#define ROWB 48
#define TILE_B (128 * ROWB)           // 6144
#define STAGE_B (4 * TILE_B)          // 24576
#define NSTG4 4
#define GEMM_SMEM (NSTG4 * STAGE_B)   // 98304

template <int MODE>
__global__ void __launch_bounds__(256, 2) mma_gemm(
    const __nv_bfloat16* __restrict__ Ah_, const __nv_bfloat16* __restrict__ Al_,
    const __nv_bfloat16* __restrict__ Bh_, const __nv_bfloat16* __restrict__ Bl_,
    const float* __restrict__ bias,
    float* __restrict__ Cout,
    __nv_bfloat16* __restrict__ Qh_o, __nv_bfloat16* __restrict__ Ql_o,
    __nv_bfloat16* __restrict__ Kh_o, __nv_bfloat16* __restrict__ Kl_o,
    __half* __restrict__ Vh_o, __half* __restrict__ Vl_o,
    int N, int K)
{
    extern __shared__ char smg[];
    const uint32_t sbase = (uint32_t)__cvta_generic_to_shared(smg);
    const int tid = threadIdx.x;
    const int wid = tid >> 5, lane = tid & 31;
    const int wm = wid >> 1, wn = wid & 1;
    const int g = lane >> 2, tg = lane & 3;
    const int m0 = blockIdx.y * 128, n0 = blockIdx.x * 128;

    const __nv_bfloat16* Ah = Ah_ + (size_t)m0 * K;
    const __nv_bfloat16* Al = Al_ + (size_t)m0 * K;
    const __nv_bfloat16* Bh = Bh_ + (size_t)n0 * K;
    const __nv_bfloat16* Bl = Bl_ + (size_t)n0 * K;
    const __nv_bfloat16* tp[4] = { Ah, Al, Bh, Bl };

    // cp.async staging map: 1024 x 16B per chunk, 4 per thread
    const int stile = tid >> 6;            // 0..3 (A_h, A_l, B_h, B_l)
    const int srow_base = (tid & 63) >> 1; // rows handled: srow_base + i*32? no:
    // simpler: element index e = i*256 + tid; tile = e>>8; row=(e&255)>>1; half=e&1

    // ldmatrix lane offsets
    const int lrow = lane & 15, lhalf = lane >> 4;
    const uint32_t aoff = (uint32_t)((wm * 32 + lrow) * ROWB + lhalf * 16);
    const uint32_t boff = (uint32_t)((wn * 64 + lrow) * ROWB + lhalf * 16) + 2 * TILE_B;

    float acc[2][8][4];
#pragma unroll
    for (int mt = 0; mt < 2; mt++)
#pragma unroll
        for (int nt = 0; nt < 8; nt++)
#pragma unroll
            for (int i = 0; i < 4; i++) acc[mt][nt][i] = 0.0f;

#define GEMM_ISSUE(chunk) do {                                                 \
    const uint32_t _sb = sbase + ((chunk) % NSTG4) * STAGE_B;                  \
    const int _kc = (chunk) * 16;                                              \
    _Pragma("unroll")                                                          \
    for (int _i = 0; _i < 4; _i++) {                                           \
        int _e = _i * 256 + tid;                                               \
        int _t = _e >> 8, _r = (_e & 255) >> 1, _h = _e & 1;                   \
        cp16(_sb + _t * TILE_B + _r * ROWB + _h * 16,                          \
             tp[_t] + (size_t)_r * K + _kc + _h * 8);                          \
    }                                                                          \
} while (0)

    const int NCH = K / 16;
    GEMM_ISSUE(0); cp_commit();
    GEMM_ISSUE(1); cp_commit();
    GEMM_ISSUE(2); cp_commit();

    for (int c = 0; c < NCH; c++) {
        cp_wait2();
        __syncthreads();

        const uint32_t st = sbase + (c % NSTG4) * STAGE_B;

        // A fragments via ldmatrix.x4 (hi, lo) for mt=0,1
        uint32_t ah[2][4], al[2][4];
#pragma unroll
        for (int mt = 0; mt < 2; mt++) {
            ldsm4(ah[mt], st + aoff + mt * 16 * ROWB);
            ldsm4(al[mt], st + TILE_B + aoff + mt * 16 * ROWB);
        }

#pragma unroll
        for (int p = 0; p < 4; p++) {
            uint32_t rh[4], rl[4];
            ldsm4(rh, st + boff + p * 16 * ROWB);
            ldsm4(rl, st + TILE_B + boff + p * 16 * ROWB);
            uint32_t bhE[2] = { rh[0], rh[2] }, bhO[2] = { rh[1], rh[3] };
            uint32_t blE[2] = { rl[0], rl[2] }, blO[2] = { rl[1], rl[3] };
#pragma unroll
            for (int mt = 0; mt < 2; mt++) {
                mma_bf16(acc[mt][2 * p],     ah[mt], bhE);
                mma_bf16(acc[mt][2 * p],     al[mt], bhE);
                mma_bf16(acc[mt][2 * p],     ah[mt], blE);
                mma_bf16(acc[mt][2 * p + 1], ah[mt], bhO);
                mma_bf16(acc[mt][2 * p + 1], al[mt], bhO);
                mma_bf16(acc[mt][2 * p + 1], ah[mt], blO);
            }
        }

        if (c + 3 < NCH) GEMM_ISSUE(c + 3);
        cp_commit();   // empty group at tail keeps wait accounting uniform
    }
#undef GEMM_ISSUE

    // Epilogue
#pragma unroll
    for (int mt = 0; mt < 2; mt++) {
#pragma unroll
        for (int nt = 0; nt < 8; nt++) {
            const int cg = n0 + wn * 64 + nt * 8 + tg * 2;
            const int r0g = m0 + wm * 32 + mt * 16 + g;
            const float b0 = __ldg(bias + cg);
            const float b1 = __ldg(bias + cg + 1);
            float f00 = acc[mt][nt][0] + b0, f01 = acc[mt][nt][1] + b1;
            float f10 = acc[mt][nt][2] + b0, f11 = acc[mt][nt][3] + b1;
            if (MODE == 0) {
                *(float2*)(Cout + (size_t)r0g * N + cg) = make_float2(f00, f01);
                *(float2*)(Cout + (size_t)(r0g + 8) * N + cg) = make_float2(f10, f11);
            } else {
                const int which = cg >> 10;
                const int c10 = cg & 1023;
                const int h = c10 >> 6;
                const int d = c10 & 63;
                const int br = r0g >> 11, tr = r0g & 2047;
                if (which == 0) {
                    size_t i0 = ((((size_t)br * HH + h) * TT) + tr) * DD + d;
                    split_store_bf16(Qh_o, Ql_o, i0, f00 * QSC, f01 * QSC);
                    split_store_bf16(Qh_o, Ql_o, i0 + 8 * DD, f10 * QSC, f11 * QSC);
                } else if (which == 1) {
                    size_t i0 = ((((size_t)br * HH + h) * TT) + tr) * DD + d;
                    split_store_bf16(Kh_o, Kl_o, i0, f00, f01);
                    split_store_bf16(Kh_o, Kl_o, i0 + 8 * DD, f10, f11);
                } else {
                    size_t i0 = (((size_t)br * HH + h) * DD + d) * TT + tr;
                    split_store_f16(Vh_o, Vl_o, i0, f00);
                    split_store_f16(Vh_o, Vl_o, i0 + TT, f01);
                    split_store_f16(Vh_o, Vl_o, i0 + 8, f10);
                    split_store_f16(Vh_o, Vl_o, i0 + TT + 8, f11);
                }
            }
        }
    }
}

// ---------------------------------------------------------------------------
// Flash attention on mma.sync + ldmatrix.
// CTA = 64 queries (4 warps x 16 rows), KV tiles of 64, 2-stage cp.async.
// ---------------------------------------------------------------------------
#define ROWF 144
#define TILEF (64 * ROWF)   // 9216
#define FL_QH 0
#define FL_QL TILEF
#define FL_ST(s) (2 * TILEF + (s) * 4 * TILEF)
#define FL_SMEM (10 * TILEF)  // 92160

__global__ void __launch_bounds__(128) flash_mma(
    const __nv_bfloat16* __restrict__ Qh, const __nv_bfloat16* __restrict__ Ql,
    const __nv_bfloat16* __restrict__ Kh, const __nv_bfloat16* __restrict__ Kl,
    const __half* __restrict__ Vh, const __half* __restrict__ Vl,
    __nv_bfloat16* __restrict__ ath, __nv_bfloat16* __restrict__ atl)
{
    extern __shared__ char smf[];
    const uint32_t sbase = (uint32_t)__cvta_generic_to_shared(smf);
    const int tid = threadIdx.x, wid = tid >> 5, lane = tid & 31;
    const int g = lane >> 2, tg = lane & 3;
    const int qt = 31 - blockIdx.x;
    const int bh = blockIdx.y;

    const __nv_bfloat16* Qhb = Qh + (size_t)bh * TT * DD;
    const __nv_bfloat16* Qlb = Ql + (size_t)bh * TT * DD;
    const __nv_bfloat16* Khb = Kh + (size_t)bh * TT * DD;
    const __nv_bfloat16* Klb = Kl + (size_t)bh * TT * DD;
    const __half* Vhb = Vh + (size_t)bh * DD * TT;
    const __half* Vlb = Vl + (size_t)bh * DD * TT;

    const int lrow = lane & 15, lhalf = lane >> 4;

#define ISSUE_KV(stg, kvi) do {                                                \
    const uint32_t _sb = sbase + FL_ST(stg);                                   \
    _Pragma("unroll")                                                          \
    for (int _i = 0; _i < 4; _i++) {                                           \
        int _ch = _i * 128 + tid;                                              \
        int _row = _ch >> 3, _c = _ch & 7;                                     \
        uint32_t _so = _sb + _row * ROWF + _c * 16;                            \
        cp16(_so,         Khb + (size_t)(kvi) * 4096 + _ch * 8);               \
        cp16(_so + TILEF, Klb + (size_t)(kvi) * 4096 + _ch * 8);               \
        uint32_t _so2 = _sb + 2 * TILEF + _row * ROWF + _c * 16;               \
        size_t _vo = (size_t)_row * TT + (size_t)(kvi) * 64 + _c * 8;          \
        cp16(_so2,         Vhb + _vo);                                         \
        cp16(_so2 + TILEF, Vlb + _vo);                                         \
    }                                                                          \
} while (0)

    // Prologue: Q tile (group 0), KV tile 0 (group 1)
#pragma unroll
    for (int i = 0; i < 4; i++) {
        int ch = i * 128 + tid;
        int row = ch >> 3, c = ch & 7;
        uint32_t so = sbase + row * ROWF + c * 16;
        cp16(so + FL_QH, Qhb + (size_t)qt * 4096 + ch * 8);
        cp16(so + FL_QL, Qlb + (size_t)qt * 4096 + ch * 8);
    }
    cp_commit();
    ISSUE_KV(0, 0);
    cp_commit();
    cp_wait1();
    __syncthreads();

    // Q fragments via ldmatrix (held for whole kernel)
    uint32_t qfh[4][4], qfl[4][4];
    {
        const uint32_t qoff = sbase + (uint32_t)((wid * 16 + lrow) * ROWF + lhalf * 16);
#pragma unroll
        for (int j = 0; j < 4; j++) {
            ldsm4(qfh[j], qoff + FL_QH + j * 32);
            ldsm4(qfl[j], qoff + FL_QL + j * 32);
        }
    }

    float oacc[8][4];
#pragma unroll
    for (int i = 0; i < 8; i++)
#pragma unroll
        for (int jj = 0; jj < 4; jj++) oacc[i][jj] = 0.0f;
    float m0 = -1e30f, m1 = -1e30f, l0 = 0.0f, l1 = 0.0f;

    const uint32_t foff = (uint32_t)(lrow * ROWF + lhalf * 16);

    for (int kv = 0; kv <= qt; kv++) {
        const int s = kv & 1;
        if (kv < qt) { ISSUE_KV(s ^ 1, kv + 1); cp_commit(); cp_wait1(); }
        else cp_wait0();
        __syncthreads();

        const uint32_t KHs = sbase + FL_ST(s) + foff;
        const uint32_t VHs = KHs + 2 * TILEF;

        // S = Q @ K^T (3-term split)
        float sa[8][4];
#pragma unroll
        for (int nt = 0; nt < 8; nt++)
#pragma unroll
            for (int jj = 0; jj < 4; jj++) sa[nt][jj] = 0.0f;

#pragma unroll
        for (int j = 0; j < 4; j++) {
#pragma unroll
            for (int p = 0; p < 4; p++) {
                uint32_t rh[4], rl[4];
                ldsm4(rh, KHs + p * 16 * ROWF + j * 32);
                ldsm4(rl, KHs + TILEF + p * 16 * ROWF + j * 32);
                uint32_t bE[2] = { rh[0], rh[2] }, bO[2] = { rh[1], rh[3] };
                uint32_t lE[2] = { rl[0], rl[2] }, lO[2] = { rl[1], rl[3] };
                mma_bf16(sa[2 * p],     qfh[j], bE);
                mma_bf16(sa[2 * p],     qfl[j], bE);
                mma_bf16(sa[2 * p],     qfh[j], lE);
                mma_bf16(sa[2 * p + 1], qfh[j], bO);
                mma_bf16(sa[2 * p + 1], qfl[j], bO);
                mma_bf16(sa[2 * p + 1], qfh[j], lO);
            }
        }

        // Causal mask (diagonal tile only)
        if (kv == qt) {
            const int r0 = wid * 16 + g, r1 = r0 + 8;
#pragma unroll
            for (int nt = 0; nt < 8; nt++) {
                int c0 = nt * 8 + tg * 2;
                if (c0 > r0)     sa[nt][0] = -1e30f;
                if (c0 + 1 > r0) sa[nt][1] = -1e30f;
                if (c0 > r1)     sa[nt][2] = -1e30f;
                if (c0 + 1 > r1) sa[nt][3] = -1e30f;
            }
        }

        // Online softmax (log2 domain)
        float mt0 = sa[0][0], mt1 = sa[0][2];
#pragma unroll
        for (int nt = 0; nt < 8; nt++) {
            mt0 = fmaxf(mt0, fmaxf(sa[nt][0], sa[nt][1]));
            mt1 = fmaxf(mt1, fmaxf(sa[nt][2], sa[nt][3]));
        }
        mt0 = fmaxf(mt0, __shfl_xor_sync(0xffffffffu, mt0, 1));
        mt0 = fmaxf(mt0, __shfl_xor_sync(0xffffffffu, mt0, 2));
        mt1 = fmaxf(mt1, __shfl_xor_sync(0xffffffffu, mt1, 1));
        mt1 = fmaxf(mt1, __shfl_xor_sync(0xffffffffu, mt1, 2));

        float mn0 = fmaxf(m0, mt0), mn1 = fmaxf(m1, mt1);
        float cr0 = ex2f(m0 - mn0), cr1 = ex2f(m1 - mn1);
        m0 = mn0; m1 = mn1;

        float s0 = 0.0f, s1 = 0.0f;
#pragma unroll
        for (int nt = 0; nt < 8; nt++) {
            sa[nt][0] = ex2f(sa[nt][0] - mn0);
            sa[nt][1] = ex2f(sa[nt][1] - mn0);
            sa[nt][2] = ex2f(sa[nt][2] - mn1);
            sa[nt][3] = ex2f(sa[nt][3] - mn1);
            s0 += sa[nt][0] + sa[nt][1];
            s1 += sa[nt][2] + sa[nt][3];
        }
        s0 += __shfl_xor_sync(0xffffffffu, s0, 1);
        s0 += __shfl_xor_sync(0xffffffffu, s0, 2);
        s1 += __shfl_xor_sync(0xffffffffu, s1, 1);
        s1 += __shfl_xor_sync(0xffffffffu, s1, 2);
        l0 = l0 * cr0 + s0;
        l1 = l1 * cr1 + s1;

#pragma unroll
        for (int nt = 0; nt < 8; nt++) {
            oacc[nt][0] *= cr0; oacc[nt][1] *= cr0;
            oacc[nt][2] *= cr1; oacc[nt][3] *= cr1;
        }

        // Pack P to fp16 A-fragments (C-frag layout == A-frag layout)
        uint32_t pa[4][4];
#pragma unroll
        for (int j = 0; j < 4; j++) {
            pa[j][0] = pack_f16(sa[2 * j][0], sa[2 * j][1]);
            pa[j][1] = pack_f16(sa[2 * j][2], sa[2 * j][3]);
            pa[j][2] = pack_f16(sa[2 * j + 1][0], sa[2 * j + 1][1]);
            pa[j][3] = pack_f16(sa[2 * j + 1][2], sa[2 * j + 1][3]);
        }

        // O += P @ V (V split into fp16 hi+lo)
#pragma unroll
        for (int j = 0; j < 4; j++) {
#pragma unroll
            for (int p = 0; p < 4; p++) {
                uint32_t rh[4], rl[4];
                ldsm4(rh, VHs + p * 16 * ROWF + j * 32);
                ldsm4(rl, VHs + TILEF + p * 16 * ROWF + j * 32);
                uint32_t bE[2] = { rh[0], rh[2] }, bO[2] = { rh[1], rh[3] };
                uint32_t lE[2] = { rl[0], rl[2] }, lO[2] = { rl[1], rl[3] };
                mma_f16(oacc[2 * p],     pa[j], bE);
                mma_f16(oacc[2 * p],     pa[j], lE);
                mma_f16(oacc[2 * p + 1], pa[j], bO);
                mma_f16(oacc[2 * p + 1], pa[j], lO);
            }
        }
        __syncthreads();
    }

    // Epilogue: normalize, split to bf16 hi/lo att [M=B*T, C] (c = h*64+d)
    const float i0 = 1.0f / l0, i1 = 1.0f / l1;
    const int b = bh >> 4, h = bh & 15;
    const int t0 = qt * 64 + wid * 16 + g;
    const size_t row0 = ((size_t)b * TT + t0) * CC + h * DD;
    const size_t row1 = row0 + (size_t)8 * CC;
#pragma unroll
    for (int nt = 0; nt < 8; nt++) {
        const int d = nt * 8 + tg * 2;
        split_store_bf16(ath, atl, row0 + d, oacc[nt][0] * i0, oacc[nt][1] * i0);
        split_store_bf16(ath, atl, row1 + d, oacc[nt][2] * i1, oacc[nt][3] * i1);
    }
#undef ISSUE_KV
}

// ---------------------------------------------------------------------------
extern "C" void kernel_launch(void* const* d_in, const int* in_sizes, int n_in,
                              void* d_out, int out_size)
{
    (void)in_sizes; (void)n_in; (void)out_size;
    const float* x      = (const float*)d_in[0];
    const float* W_attn = (const float*)d_in[1];
    const float* b_attn = (const float*)d_in[2];
    const float* W_proj = (const float*)d_in[3];
    const float* b_proj = (const float*)d_in[4];
    float* out = (float*)d_out;

    __nv_bfloat16 *xh, *xl, *wah, *wal, *wph, *wpl, *ath, *atl;
    __nv_bfloat16 *qh, *ql, *kh, *kl;
    __half *vh, *vl;
    cudaGetSymbolAddress((void**)&xh, g_xh);
    cudaGetSymbolAddress((void**)&xl, g_xl);
    cudaGetSymbolAddress((void**)&wah, g_wah);
    cudaGetSymbolAddress((void**)&wal, g_wal);
    cudaGetSymbolAddress((void**)&wph, g_wph);
    cudaGetSymbolAddress((void**)&wpl, g_wpl);
    cudaGetSymbolAddress((void**)&ath, g_ath);
    cudaGetSymbolAddress((void**)&atl, g_atl);
    cudaGetSymbolAddress((void**)&qh, g_qh);
    cudaGetSymbolAddress((void**)&ql, g_ql);
    cudaGetSymbolAddress((void**)&kh, g_kh);
    cudaGetSymbolAddress((void**)&kl, g_kl);
    cudaGetSymbolAddress((void**)&vh, g_vh);
    cudaGetSymbolAddress((void**)&vl, g_vl);

    cudaFuncSetAttribute(mma_gemm<0>, cudaFuncAttributeMaxDynamicSharedMemorySize, GEMM_SMEM);
    cudaFuncSetAttribute(mma_gemm<1>, cudaFuncAttributeMaxDynamicSharedMemorySize, GEMM_SMEM);
    cudaFuncSetAttribute(flash_mma, cudaFuncAttributeMaxDynamicSharedMemorySize, FL_SMEM);

    // 1) Split x into bf16 hi/lo
    prep_split<<<MROWS * CC / 4 / 256, 256>>>(x, xh, xl);

    // 2) Transpose+split weights
    {
        dim3 blk(32, 8);
        prep_wt<<<dim3(3 * CC / 32, CC / 32), blk>>>(W_attn, wah, wal, CC, 3 * CC);
        prep_wt<<<dim3(CC / 32, CC / 32), blk>>>(W_proj, wph, wpl, CC, CC);
    }

    // 3) QKV GEMM -> q/k bf16 hi/lo, v^T fp16 hi/lo
    mma_gemm<1><<<dim3(3 * CC / 128, MROWS / 128), 256, GEMM_SMEM>>>(
        xh, xl, wah, wal, b_attn, nullptr, qh, ql, kh, kl, vh, vl, 3 * CC, CC);

    // 4) Flash attention (tensor cores) -> att bf16 hi/lo
    flash_mma<<<dim3(TT / 64, BB * HH), 128, FL_SMEM>>>(
        qh, ql, kh, kl, vh, vl, ath, atl);

    // 5) Projection GEMM -> out
    mma_gemm<0><<<dim3(CC / 128, MROWS / 128), 256, GEMM_SMEM>>>(
        ath, atl, wph, wpl, b_proj, out,
        nullptr, nullptr, nullptr, nullptr, nullptr, nullptr, CC, CC);
}

// round 6
// speedup vs baseline: 9.8747x; 1.3128x over previous
#include <cuda_runtime.h>
#include <cuda_bf16.h>
#include <cuda_fp16.h>
#include <math.h>
#include <stdint.h>

// Problem constants
#define BB 4
#define TT 2048
#define CC 1024
#define HH 16
#define DD 64
#define MROWS (BB * TT)   // 8192
#define QSC (0.125f * 1.44269504088896f)   // 1/sqrt(D) * log2(e), folded into Q

// ---------------------------------------------------------------------------
// Scratch (device globals) — fp16 scheme: activations split-2, weights single
// ---------------------------------------------------------------------------
__device__ __half g_xh[MROWS * CC], g_xl[MROWS * CC];     // x split [M,K]
__device__ __half g_wa[3 * CC * CC];                      // W_attn^T [3072,K]
__device__ __half g_wp[CC * CC];                          // W_proj^T [1024,K]
__device__ __half g_qh[BB * HH * TT * DD], g_ql[BB * HH * TT * DD];  // [B,H,T,D] scaled
__device__ __half g_k[BB * HH * TT * DD];                 // [B,H,T,D]
__device__ __half g_v[BB * HH * DD * TT];                 // [B,H,D,T] (V^T)
__device__ __half g_ath[MROWS * CC], g_atl[MROWS * CC];   // att split [M,K]

// ---------------------------------------------------------------------------
// PTX helpers
// ---------------------------------------------------------------------------
__device__ __forceinline__ void mma_f16(float* c, const uint32_t* a,
                                        const uint32_t* b) {
    asm volatile(
        "mma.sync.aligned.m16n8k16.row.col.f32.f16.f16.f32 "
        "{%0,%1,%2,%3}, {%4,%5,%6,%7}, {%8,%9}, {%0,%1,%2,%3};"
        : "+f"(c[0]), "+f"(c[1]), "+f"(c[2]), "+f"(c[3])
        : "r"(a[0]), "r"(a[1]), "r"(a[2]), "r"(a[3]), "r"(b[0]), "r"(b[1]));
}
__device__ __forceinline__ void ldsm4(uint32_t* r, uint32_t addr) {
    asm volatile("ldmatrix.sync.aligned.m8n8.x4.shared.b16 {%0,%1,%2,%3}, [%4];"
                 : "=r"(r[0]), "=r"(r[1]), "=r"(r[2]), "=r"(r[3]) : "r"(addr));
}
__device__ __forceinline__ float ex2f(float x) {
    float y;
    asm("ex2.approx.f32 %0, %1;" : "=f"(y) : "f"(x));
    return y;
}
__device__ __forceinline__ uint32_t pack_f16(float lo, float hi) {
    __half2 h = __float22half2_rn(make_float2(lo, hi));
    return *(uint32_t*)&h;
}
// Store adjacent pair (a,b) as fp16 hi + fp16 residual lo
__device__ __forceinline__ void split_store_f16x2(__half* hi, __half* lo,
                                                  size_t i, float a, float b) {
    __half2 h = __float22half2_rn(make_float2(a, b));
    float2 hf = __half22float2(h);
    *(uint32_t*)(hi + i) = *(uint32_t*)&h;
    __half2 l = __float22half2_rn(make_float2(a - hf.x, b - hf.y));
    *(uint32_t*)(lo + i) = *(uint32_t*)&l;
}
__device__ __forceinline__ void cp16(uint32_t s, const void* g) {
    asm volatile("cp.async.cg.shared.global [%0], [%1], 16;" :: "r"(s), "l"(g));
}
__device__ __forceinline__ void cp_commit() {
    asm volatile("cp.async.commit_group;" ::: "memory");
}
__device__ __forceinline__ void cp_wait2() {
    asm volatile("cp.async.wait_group 2;" ::: "memory");
}
__device__ __forceinline__ void cp_wait1() {
    asm volatile("cp.async.wait_group 1;" ::: "memory");
}
__device__ __forceinline__ void cp_wait0() {
    asm volatile("cp.async.wait_group 0;" ::: "memory");
}

// ---------------------------------------------------------------------------
// Prep kernels
// ---------------------------------------------------------------------------
__global__ void prep_split(const float* __restrict__ src,
                           __half* __restrict__ hi, __half* __restrict__ lo) {
    int idx = blockIdx.x * blockDim.x + threadIdx.x;
    float4 v = ((const float4*)src)[idx];
    split_store_f16x2(hi, lo, (size_t)idx * 4, v.x, v.y);
    split_store_f16x2(hi, lo, (size_t)idx * 4 + 2, v.z, v.w);
}

__global__ void prep_wt(const float* __restrict__ W,
                        __half* __restrict__ Wt, int K, int N) {
    __shared__ float t[32][33];
    const int tx = threadIdx.x, ty = threadIdx.y;
    const int n0 = blockIdx.x * 32, k0 = blockIdx.y * 32;
#pragma unroll
    for (int i = 0; i < 4; i++)
        t[ty + i * 8][tx] = W[(size_t)(k0 + ty + i * 8) * N + n0 + tx];
    __syncthreads();
#pragma unroll
    for (int i = 0; i < 4; i++)
        Wt[(size_t)(n0 + ty + i * 8) * K + k0 + tx] = __float2half(t[tx][ty + i * 8]);
}

// ---------------------------------------------------------------------------
// fp16 split-2 GEMM: C = (Ah+Al)@Bh^T + bias.
// CTA 128x128, 4 warps (2x2), warp tile 64x64, K-chunk 16,
// 4-stage cp.async, ldmatrix fragments.
// MODE 0: fp32 row-major out. MODE 1: QKV epilogue (fp16 outputs).
// ---------------------------------------------------------------------------
#define ROWB 48
#define TILE_B (128 * ROWB)           // 6144
#define STAGE_B (3 * TILE_B)          // 18432 (Ah, Al, Bh)
#define NSTG4 4
#define GEMM_SMEM (NSTG4 * STAGE_B)   // 73728

template <int MODE>
__global__ void __launch_bounds__(128, 2) mma_gemm(
    const __half* __restrict__ Ah_, const __half* __restrict__ Al_,
    const __half* __restrict__ Bh_,
    const float* __restrict__ bias,
    float* __restrict__ Cout,
    __half* __restrict__ Qh_o, __half* __restrict__ Ql_o,
    __half* __restrict__ K_o, __half* __restrict__ V_o,
    int N, int K)
{
    extern __shared__ char smg[];
    const uint32_t sbase = (uint32_t)__cvta_generic_to_shared(smg);
    const int tid = threadIdx.x;
    const int wid = tid >> 5, lane = tid & 31;
    const int wm = wid >> 1, wn = wid & 1;
    const int g = lane >> 2, tg = lane & 3;
    const int lrow = lane & 15, lhalf = lane >> 4;
    const int m0 = blockIdx.y * 128, n0 = blockIdx.x * 128;

    const __half* Ah = Ah_ + (size_t)m0 * K;
    const __half* Al = Al_ + (size_t)m0 * K;
    const __half* Bh = Bh_ + (size_t)n0 * K;
    const __half* tp[3] = { Ah, Al, Bh };

    const uint32_t aoff = (uint32_t)((wm * 64 + lrow) * ROWB + lhalf * 16);
    const uint32_t boff = (uint32_t)((wn * 64 + lrow) * ROWB + lhalf * 16) + 2 * TILE_B;

    float acc[4][8][4];
#pragma unroll
    for (int mt = 0; mt < 4; mt++)
#pragma unroll
        for (int nt = 0; nt < 8; nt++)
#pragma unroll
            for (int i = 0; i < 4; i++) acc[mt][nt][i] = 0.0f;

#define GEMM_ISSUE(chunk) do {                                                 \
    const uint32_t _sb = sbase + ((chunk) % NSTG4) * STAGE_B;                  \
    const int _kc = (chunk) * 16;                                              \
    _Pragma("unroll")                                                          \
    for (int _i = 0; _i < 6; _i++) {                                           \
        int _e = _i * 128 + tid;                                               \
        int _t = _e >> 8, _r = (_e & 255) >> 1, _h = _e & 1;                   \
        cp16(_sb + _t * TILE_B + _r * ROWB + _h * 16,                          \
             tp[_t] + (size_t)_r * K + _kc + _h * 8);                          \
    }                                                                          \
} while (0)

    const int NCH = K / 16;
    GEMM_ISSUE(0); cp_commit();
    GEMM_ISSUE(1); cp_commit();
    GEMM_ISSUE(2); cp_commit();

    for (int c = 0; c < NCH; c++) {
        cp_wait2();
        __syncthreads();

        const uint32_t st = sbase + (c % NSTG4) * STAGE_B;

        uint32_t ah[4][4], al[4][4];
#pragma unroll
        for (int mt = 0; mt < 4; mt++) {
            ldsm4(ah[mt], st + aoff + mt * 16 * ROWB);
            ldsm4(al[mt], st + TILE_B + aoff + mt * 16 * ROWB);
        }

#pragma unroll
        for (int p = 0; p < 4; p++) {
            uint32_t rb[4];
            ldsm4(rb, st + boff + p * 16 * ROWB);
            uint32_t bE[2] = { rb[0], rb[2] }, bO[2] = { rb[1], rb[3] };
#pragma unroll
            for (int mt = 0; mt < 4; mt++) {
                mma_f16(acc[mt][2 * p],     ah[mt], bE);
                mma_f16(acc[mt][2 * p],     al[mt], bE);
                mma_f16(acc[mt][2 * p + 1], ah[mt], bO);
                mma_f16(acc[mt][2 * p + 1], al[mt], bO);
            }
        }

        if (c + 3 < NCH) GEMM_ISSUE(c + 3);
        cp_commit();
    }
#undef GEMM_ISSUE

    // Epilogue
#pragma unroll
    for (int mt = 0; mt < 4; mt++) {
#pragma unroll
        for (int nt = 0; nt < 8; nt++) {
            const int cg = n0 + wn * 64 + nt * 8 + tg * 2;
            const int r0g = m0 + wm * 64 + mt * 16 + g;
            const float b0 = __ldg(bias + cg);
            const float b1 = __ldg(bias + cg + 1);
            float f00 = acc[mt][nt][0] + b0, f01 = acc[mt][nt][1] + b1;
            float f10 = acc[mt][nt][2] + b0, f11 = acc[mt][nt][3] + b1;
            if (MODE == 0) {
                *(float2*)(Cout + (size_t)r0g * N + cg) = make_float2(f00, f01);
                *(float2*)(Cout + (size_t)(r0g + 8) * N + cg) = make_float2(f10, f11);
            } else {
                const int which = cg >> 10;
                const int c10 = cg & 1023;
                const int h = c10 >> 6;
                const int d = c10 & 63;
                const int br = r0g >> 11, tr = r0g & 2047;
                if (which == 0) {
                    size_t i0 = ((((size_t)br * HH + h) * TT) + tr) * DD + d;
                    split_store_f16x2(Qh_o, Ql_o, i0, f00 * QSC, f01 * QSC);
                    split_store_f16x2(Qh_o, Ql_o, i0 + 8 * DD, f10 * QSC, f11 * QSC);
                } else if (which == 1) {
                    size_t i0 = ((((size_t)br * HH + h) * TT) + tr) * DD + d;
                    __half2 h0 = __float22half2_rn(make_float2(f00, f01));
                    __half2 h1 = __float22half2_rn(make_float2(f10, f11));
                    *(uint32_t*)(K_o + i0) = *(uint32_t*)&h0;
                    *(uint32_t*)(K_o + i0 + 8 * DD) = *(uint32_t*)&h1;
                } else {
                    size_t i0 = (((size_t)br * HH + h) * DD + d) * TT + tr;
                    V_o[i0]          = __float2half(f00);
                    V_o[i0 + TT]     = __float2half(f01);
                    V_o[i0 + 8]      = __float2half(f10);
                    V_o[i0 + TT + 8] = __float2half(f11);
                }
            }
        }
    }
}

// ---------------------------------------------------------------------------
// Flash attention: fp16 mma, Q split-2, K/V single fp16.
// CTA = 64 queries (4 warps x 16 rows), KV tiles of 64, 2-stage cp.async.
// ---------------------------------------------------------------------------
#define ROWF 144
#define TILEF (64 * ROWF)   // 9216
#define FL_QH 0
#define FL_QL TILEF
#define FL_ST(s) (2 * TILEF + (s) * 2 * TILEF)
#define FL_SMEM (6 * TILEF)  // 55296

__global__ void __launch_bounds__(128, 3) flash_mma(
    const __half* __restrict__ Qh, const __half* __restrict__ Ql,
    const __half* __restrict__ Kg, const __half* __restrict__ Vg,
    __half* __restrict__ ath, __half* __restrict__ atl)
{
    extern __shared__ char smf[];
    const uint32_t sbase = (uint32_t)__cvta_generic_to_shared(smf);
    const int tid = threadIdx.x, wid = tid >> 5, lane = tid & 31;
    const int g = lane >> 2, tg = lane & 3;
    const int qt = 31 - blockIdx.x;
    const int bh = blockIdx.y;

    const __half* Qhb = Qh + (size_t)bh * TT * DD;
    const __half* Qlb = Ql + (size_t)bh * TT * DD;
    const __half* Kb = Kg + (size_t)bh * TT * DD;
    const __half* Vb = Vg + (size_t)bh * DD * TT;

    const int lrow = lane & 15, lhalf = lane >> 4;

#define ISSUE_KV(stg, kvi) do {                                                \
    const uint32_t _sb = sbase + FL_ST(stg);                                   \
    _Pragma("unroll")                                                          \
    for (int _i = 0; _i < 4; _i++) {                                           \
        int _ch = _i * 128 + tid;                                              \
        int _row = _ch >> 3, _c = _ch & 7;                                     \
        cp16(_sb + _row * ROWF + _c * 16,                                      \
             Kb + (size_t)(kvi) * 4096 + _ch * 8);                             \
        cp16(_sb + TILEF + _row * ROWF + _c * 16,                              \
             Vb + (size_t)_row * TT + (size_t)(kvi) * 64 + _c * 8);            \
    }                                                                          \
} while (0)

    // Prologue: Q tiles (group 0), KV tile 0 (group 1)
#pragma unroll
    for (int i = 0; i < 4; i++) {
        int ch = i * 128 + tid;
        int row = ch >> 3, c = ch & 7;
        uint32_t so = sbase + row * ROWF + c * 16;
        cp16(so + FL_QH, Qhb + (size_t)qt * 4096 + ch * 8);
        cp16(so + FL_QL, Qlb + (size_t)qt * 4096 + ch * 8);
    }
    cp_commit();
    ISSUE_KV(0, 0);
    cp_commit();
    cp_wait1();
    __syncthreads();

    // Q fragments via ldmatrix (held for whole kernel)
    uint32_t qfh[4][4], qfl[4][4];
    {
        const uint32_t qoff = sbase + (uint32_t)((wid * 16 + lrow) * ROWF + lhalf * 16);
#pragma unroll
        for (int j = 0; j < 4; j++) {
            ldsm4(qfh[j], qoff + FL_QH + j * 32);
            ldsm4(qfl[j], qoff + FL_QL + j * 32);
        }
    }

    float oacc[8][4];
#pragma unroll
    for (int i = 0; i < 8; i++)
#pragma unroll
        for (int jj = 0; jj < 4; jj++) oacc[i][jj] = 0.0f;
    float m0 = -1e30f, m1 = -1e30f, l0 = 0.0f, l1 = 0.0f;

    const uint32_t foff = (uint32_t)(lrow * ROWF + lhalf * 16);

    for (int kv = 0; kv <= qt; kv++) {
        const int s = kv & 1;
        if (kv < qt) { ISSUE_KV(s ^ 1, kv + 1); cp_commit(); cp_wait1(); }
        else cp_wait0();
        __syncthreads();

        const uint32_t KHs = sbase + FL_ST(s) + foff;
        const uint32_t VHs = KHs + TILEF;

        // S = (Qh + Ql) @ K^T
        float sa[8][4];
#pragma unroll
        for (int nt = 0; nt < 8; nt++)
#pragma unroll
            for (int jj = 0; jj < 4; jj++) sa[nt][jj] = 0.0f;

#pragma unroll
        for (int j = 0; j < 4; j++) {
#pragma unroll
            for (int p = 0; p < 4; p++) {
                uint32_t rk[4];
                ldsm4(rk, KHs + p * 16 * ROWF + j * 32);
                uint32_t bE[2] = { rk[0], rk[2] }, bO[2] = { rk[1], rk[3] };
                mma_f16(sa[2 * p],     qfh[j], bE);
                mma_f16(sa[2 * p],     qfl[j], bE);
                mma_f16(sa[2 * p + 1], qfh[j], bO);
                mma_f16(sa[2 * p + 1], qfl[j], bO);
            }
        }

        // Causal mask (diagonal tile only)
        if (kv == qt) {
            const int r0 = wid * 16 + g, r1 = r0 + 8;
#pragma unroll
            for (int nt = 0; nt < 8; nt++) {
                int c0 = nt * 8 + tg * 2;
                if (c0 > r0)     sa[nt][0] = -1e30f;
                if (c0 + 1 > r0) sa[nt][1] = -1e30f;
                if (c0 > r1)     sa[nt][2] = -1e30f;
                if (c0 + 1 > r1) sa[nt][3] = -1e30f;
            }
        }

        // Online softmax (log2 domain)
        float mt0 = sa[0][0], mt1 = sa[0][2];
#pragma unroll
        for (int nt = 0; nt < 8; nt++) {
            mt0 = fmaxf(mt0, fmaxf(sa[nt][0], sa[nt][1]));
            mt1 = fmaxf(mt1, fmaxf(sa[nt][2], sa[nt][3]));
        }
        mt0 = fmaxf(mt0, __shfl_xor_sync(0xffffffffu, mt0, 1));
        mt0 = fmaxf(mt0, __shfl_xor_sync(0xffffffffu, mt0, 2));
        mt1 = fmaxf(mt1, __shfl_xor_sync(0xffffffffu, mt1, 1));
        mt1 = fmaxf(mt1, __shfl_xor_sync(0xffffffffu, mt1, 2));

        float mn0 = fmaxf(m0, mt0), mn1 = fmaxf(m1, mt1);
        float cr0 = ex2f(m0 - mn0), cr1 = ex2f(m1 - mn1);
        m0 = mn0; m1 = mn1;

        float s0 = 0.0f, s1 = 0.0f;
#pragma unroll
        for (int nt = 0; nt < 8; nt++) {
            sa[nt][0] = ex2f(sa[nt][0] - mn0);
            sa[nt][1] = ex2f(sa[nt][1] - mn0);
            sa[nt][2] = ex2f(sa[nt][2] - mn1);
            sa[nt][3] = ex2f(sa[nt][3] - mn1);
            s0 += sa[nt][0] + sa[nt][1];
            s1 += sa[nt][2] + sa[nt][3];
        }
        s0 += __shfl_xor_sync(0xffffffffu, s0, 1);
        s0 += __shfl_xor_sync(0xffffffffu, s0, 2);
        s1 += __shfl_xor_sync(0xffffffffu, s1, 1);
        s1 += __shfl_xor_sync(0xffffffffu, s1, 2);
        l0 = l0 * cr0 + s0;
        l1 = l1 * cr1 + s1;

#pragma unroll
        for (int nt = 0; nt < 8; nt++) {
            oacc[nt][0] *= cr0; oacc[nt][1] *= cr0;
            oacc[nt][2] *= cr1; oacc[nt][3] *= cr1;
        }

        // Pack P to fp16 A-fragments
        uint32_t pa[4][4];
#pragma unroll
        for (int j = 0; j < 4; j++) {
            pa[j][0] = pack_f16(sa[2 * j][0], sa[2 * j][1]);
            pa[j][1] = pack_f16(sa[2 * j][2], sa[2 * j][3]);
            pa[j][2] = pack_f16(sa[2 * j + 1][0], sa[2 * j + 1][1]);
            pa[j][3] = pack_f16(sa[2 * j + 1][2], sa[2 * j + 1][3]);
        }

        // O += P @ V
#pragma unroll
        for (int j = 0; j < 4; j++) {
#pragma unroll
            for (int p = 0; p < 4; p++) {
                uint32_t rv[4];
                ldsm4(rv, VHs + p * 16 * ROWF + j * 32);
                uint32_t bE[2] = { rv[0], rv[2] }, bO[2] = { rv[1], rv[3] };
                mma_f16(oacc[2 * p],     pa[j], bE);
                mma_f16(oacc[2 * p + 1], pa[j], bO);
            }
        }
        __syncthreads();
    }

    // Epilogue: normalize, split to fp16 hi/lo att [M=B*T, C] (c = h*64+d)
    const float i0 = 1.0f / l0, i1 = 1.0f / l1;
    const int b = bh >> 4, h = bh & 15;
    const int t0 = qt * 64 + wid * 16 + g;
    const size_t row0 = ((size_t)b * TT + t0) * CC + h * DD;
    const size_t row1 = row0 + (size_t)8 * CC;
#pragma unroll
    for (int nt = 0; nt < 8; nt++) {
        const int d = nt * 8 + tg * 2;
        split_store_f16x2(ath, atl, row0 + d, oacc[nt][0] * i0, oacc[nt][1] * i0);
        split_store_f16x2(ath, atl, row1 + d, oacc[nt][2] * i1, oacc[nt][3] * i1);
    }
#undef ISSUE_KV
}

// ---------------------------------------------------------------------------
extern "C" void kernel_launch(void* const* d_in, const int* in_sizes, int n_in,
                              void* d_out, int out_size)
{
    (void)in_sizes; (void)n_in; (void)out_size;
    const float* x      = (const float*)d_in[0];
    const float* W_attn = (const float*)d_in[1];
    const float* b_attn = (const float*)d_in[2];
    const float* W_proj = (const float*)d_in[3];
    const float* b_proj = (const float*)d_in[4];
    float* out = (float*)d_out;

    __half *xh, *xl, *wa, *wp, *ath, *atl, *qh, *ql, *k, *v;
    cudaGetSymbolAddress((void**)&xh, g_xh);
    cudaGetSymbolAddress((void**)&xl, g_xl);
    cudaGetSymbolAddress((void**)&wa, g_wa);
    cudaGetSymbolAddress((void**)&wp, g_wp);
    cudaGetSymbolAddress((void**)&ath, g_ath);
    cudaGetSymbolAddress((void**)&atl, g_atl);
    cudaGetSymbolAddress((void**)&qh, g_qh);
    cudaGetSymbolAddress((void**)&ql, g_ql);
    cudaGetSymbolAddress((void**)&k, g_k);
    cudaGetSymbolAddress((void**)&v, g_v);

    cudaFuncSetAttribute(mma_gemm<0>, cudaFuncAttributeMaxDynamicSharedMemorySize, GEMM_SMEM);
    cudaFuncSetAttribute(mma_gemm<1>, cudaFuncAttributeMaxDynamicSharedMemorySize, GEMM_SMEM);
    cudaFuncSetAttribute(flash_mma, cudaFuncAttributeMaxDynamicSharedMemorySize, FL_SMEM);

    // 1) Split x into fp16 hi/lo
    prep_split<<<MROWS * CC / 4 / 256, 256>>>(x, xh, xl);

    // 2) Transpose weights to fp16 [N,K]
    {
        dim3 blk(32, 8);
        prep_wt<<<dim3(3 * CC / 32, CC / 32), blk>>>(W_attn, wa, CC, 3 * CC);
        prep_wt<<<dim3(CC / 32, CC / 32), blk>>>(W_proj, wp, CC, CC);
    }

    // 3) QKV GEMM -> q fp16 hi/lo (scaled), k fp16, v^T fp16
    mma_gemm<1><<<dim3(3 * CC / 128, MROWS / 128), 128, GEMM_SMEM>>>(
        xh, xl, wa, b_attn, nullptr, qh, ql, k, v, 3 * CC, CC);

    // 4) Flash attention -> att fp16 hi/lo
    flash_mma<<<dim3(TT / 64, BB * HH), 128, FL_SMEM>>>(
        qh, ql, k, v, ath, atl);

    // 5) Projection GEMM -> out (fp32)
    mma_gemm<0><<<dim3(CC / 128, MROWS / 128), 128, GEMM_SMEM>>>(
        ath, atl, wp, b_proj, out,
        nullptr, nullptr, nullptr, nullptr, CC, CC);
}

// round 7
// speedup vs baseline: 11.4036x; 1.1548x over previous
#include <cuda_runtime.h>
#include <cuda_bf16.h>
#include <cuda_fp16.h>
#include <math.h>
#include <stdint.h>

// Problem constants
#define BB 4
#define TT 2048
#define CC 1024
#define HH 16
#define DD 64
#define MROWS (BB * TT)   // 8192
#define QSC (0.125f * 1.44269504088896f)   // 1/sqrt(D) * log2(e), folded into Q

// ---------------------------------------------------------------------------
// Scratch (device globals) — fp16 scheme: activations split-2, weights single
// ---------------------------------------------------------------------------
__device__ __half g_xh[MROWS * CC], g_xl[MROWS * CC];     // x split [M,K]
__device__ __half g_wa[3 * CC * CC];                      // W_attn^T [3072,K]
__device__ __half g_wp[CC * CC];                          // W_proj^T [1024,K]
__device__ __half g_qh[BB * HH * TT * DD], g_ql[BB * HH * TT * DD];  // [B,H,T,D] scaled
__device__ __half g_k[BB * HH * TT * DD];                 // [B,H,T,D]
__device__ __half g_v[BB * HH * DD * TT];                 // [B,H,D,T] (V^T)
__device__ __half g_ath[MROWS * CC], g_atl[MROWS * CC];   // att split [M,K]

// ---------------------------------------------------------------------------
// PTX helpers
// ---------------------------------------------------------------------------
__device__ __forceinline__ void mma_f16(float* c, const uint32_t* a,
                                        const uint32_t* b) {
    asm volatile(
        "mma.sync.aligned.m16n8k16.row.col.f32.f16.f16.f32 "
        "{%0,%1,%2,%3}, {%4,%5,%6,%7}, {%8,%9}, {%0,%1,%2,%3};"
        : "+f"(c[0]), "+f"(c[1]), "+f"(c[2]), "+f"(c[3])
        : "r"(a[0]), "r"(a[1]), "r"(a[2]), "r"(a[3]), "r"(b[0]), "r"(b[1]));
}
__device__ __forceinline__ void ldsm4(uint32_t* r, uint32_t addr) {
    asm volatile("ldmatrix.sync.aligned.m8n8.x4.shared.b16 {%0,%1,%2,%3}, [%4];"
                 : "=r"(r[0]), "=r"(r[1]), "=r"(r[2]), "=r"(r[3]) : "r"(addr));
}
__device__ __forceinline__ float ex2f(float x) {
    float y;
    asm("ex2.approx.f32 %0, %1;" : "=f"(y) : "f"(x));
    return y;
}
__device__ __forceinline__ uint32_t pack_f16(float lo, float hi) {
    __half2 h = __float22half2_rn(make_float2(lo, hi));
    return *(uint32_t*)&h;
}
__device__ __forceinline__ void split_store_f16x2(__half* hi, __half* lo,
                                                  size_t i, float a, float b) {
    __half2 h = __float22half2_rn(make_float2(a, b));
    float2 hf = __half22float2(h);
    *(uint32_t*)(hi + i) = *(uint32_t*)&h;
    __half2 l = __float22half2_rn(make_float2(a - hf.x, b - hf.y));
    *(uint32_t*)(lo + i) = *(uint32_t*)&l;
}
__device__ __forceinline__ void cp16(uint32_t s, const void* g) {
    asm volatile("cp.async.cg.shared.global [%0], [%1], 16;" :: "r"(s), "l"(g));
}
__device__ __forceinline__ void cp_commit() {
    asm volatile("cp.async.commit_group;" ::: "memory");
}
__device__ __forceinline__ void cp_wait1() {
    asm volatile("cp.async.wait_group 1;" ::: "memory");
}
__device__ __forceinline__ void cp_wait0() {
    asm volatile("cp.async.wait_group 0;" ::: "memory");
}

// ---------------------------------------------------------------------------
// Prep kernels
// ---------------------------------------------------------------------------
__global__ void prep_split(const float* __restrict__ src,
                           __half* __restrict__ hi, __half* __restrict__ lo) {
    int idx = blockIdx.x * blockDim.x + threadIdx.x;
    float4 v = ((const float4*)src)[idx];
    split_store_f16x2(hi, lo, (size_t)idx * 4, v.x, v.y);
    split_store_f16x2(hi, lo, (size_t)idx * 4 + 2, v.z, v.w);
}

__global__ void prep_wt(const float* __restrict__ W,
                        __half* __restrict__ Wt, int K, int N) {
    __shared__ float t[32][33];
    const int tx = threadIdx.x, ty = threadIdx.y;
    const int n0 = blockIdx.x * 32, k0 = blockIdx.y * 32;
#pragma unroll
    for (int i = 0; i < 4; i++)
        t[ty + i * 8][tx] = W[(size_t)(k0 + ty + i * 8) * N + n0 + tx];
    __syncthreads();
#pragma unroll
    for (int i = 0; i < 4; i++)
        Wt[(size_t)(n0 + ty + i * 8) * K + k0 + tx] = __float2half(t[tx][ty + i * 8]);
}

// ---------------------------------------------------------------------------
// fp16 split-2 GEMM: C = (Ah+Al)@Bh^T + bias.
// CTA 128x128, 4 warps (2x2), warp tile 64x64, K-chunk 32,
// 3-stage cp.async, ldmatrix fragments. Issue-at-end pipeline.
// MODE 0: fp32 row-major out. MODE 1: QKV epilogue (fp16 outputs).
// ---------------------------------------------------------------------------
#define ROWB 80
#define TILE_B (128 * ROWB)           // 10240
#define STAGE_B (3 * TILE_B)          // 30720 (Ah, Al, Bh)
#define NSTG 3
#define GEMM_SMEM (NSTG * STAGE_B)    // 92160

template <int MODE>
__global__ void __launch_bounds__(128, 2) mma_gemm(
    const __half* __restrict__ Ah_, const __half* __restrict__ Al_,
    const __half* __restrict__ Bh_,
    const float* __restrict__ bias,
    float* __restrict__ Cout,
    __half* __restrict__ Qh_o, __half* __restrict__ Ql_o,
    __half* __restrict__ K_o, __half* __restrict__ V_o,
    int N, int K)
{
    extern __shared__ char smg[];
    const uint32_t sbase = (uint32_t)__cvta_generic_to_shared(smg);
    const int tid = threadIdx.x;
    const int wid = tid >> 5, lane = tid & 31;
    const int wm = wid >> 1, wn = wid & 1;
    const int g = lane >> 2, tg = lane & 3;
    const int lrow = lane & 15, lhalf = lane >> 4;
    const int m0 = blockIdx.y * 128, n0 = blockIdx.x * 128;

    const __half* Ah = Ah_ + (size_t)m0 * K;
    const __half* Al = Al_ + (size_t)m0 * K;
    const __half* Bh = Bh_ + (size_t)n0 * K;
    const __half* tp[3] = { Ah, Al, Bh };

    const uint32_t aoff = (uint32_t)((wm * 64 + lrow) * ROWB + lhalf * 16);
    const uint32_t boff = (uint32_t)((wn * 64 + lrow) * ROWB + lhalf * 16) + 2 * TILE_B;

    float acc[4][8][4];
#pragma unroll
    for (int mt = 0; mt < 4; mt++)
#pragma unroll
        for (int nt = 0; nt < 8; nt++)
#pragma unroll
            for (int i = 0; i < 4; i++) acc[mt][nt][i] = 0.0f;

    // chunk = 32 K-elems: 3 tiles x 128 rows x 64B = 1536 x 16B ops, 12/thread
#define GEMM_ISSUE(chunk) do {                                                 \
    const uint32_t _sb = sbase + ((chunk) % NSTG) * STAGE_B;                   \
    const int _kc = (chunk) * 32;                                              \
    _Pragma("unroll")                                                          \
    for (int _i = 0; _i < 12; _i++) {                                          \
        int _e = _i * 128 + tid;                                               \
        int _t = _e >> 9, _r = (_e & 511) >> 2, _h = _e & 3;                   \
        cp16(_sb + _t * TILE_B + _r * ROWB + _h * 16,                          \
             tp[_t] + (size_t)_r * K + _kc + _h * 8);                          \
    }                                                                          \
} while (0)

    const int NCH = K / 32;
    GEMM_ISSUE(0); cp_commit();
    GEMM_ISSUE(1); cp_commit();

    for (int c = 0; c < NCH; c++) {
        cp_wait1();
        __syncthreads();

        const uint32_t st = sbase + (c % NSTG) * STAGE_B;

#pragma unroll
        for (int ks = 0; ks < 2; ks++) {
            uint32_t ah[4][4], al[4][4];
#pragma unroll
            for (int mt = 0; mt < 4; mt++) {
                ldsm4(ah[mt], st + aoff + mt * 16 * ROWB + ks * 32);
                ldsm4(al[mt], st + TILE_B + aoff + mt * 16 * ROWB + ks * 32);
            }
#pragma unroll
            for (int p = 0; p < 4; p++) {
                uint32_t rb[4];
                ldsm4(rb, st + boff + p * 16 * ROWB + ks * 32);
                uint32_t bE[2] = { rb[0], rb[2] }, bO[2] = { rb[1], rb[3] };
#pragma unroll
                for (int mt = 0; mt < 4; mt++) {
                    mma_f16(acc[mt][2 * p],     ah[mt], bE);
                    mma_f16(acc[mt][2 * p],     al[mt], bE);
                    mma_f16(acc[mt][2 * p + 1], ah[mt], bO);
                    mma_f16(acc[mt][2 * p + 1], al[mt], bO);
                }
            }
        }

        if (c + 2 < NCH) GEMM_ISSUE(c + 2);
        cp_commit();   // empty group at tail keeps wait accounting uniform
    }
#undef GEMM_ISSUE

    // Epilogue
#pragma unroll
    for (int mt = 0; mt < 4; mt++) {
#pragma unroll
        for (int nt = 0; nt < 8; nt++) {
            const int cg = n0 + wn * 64 + nt * 8 + tg * 2;
            const int r0g = m0 + wm * 64 + mt * 16 + g;
            const float b0 = __ldg(bias + cg);
            const float b1 = __ldg(bias + cg + 1);
            float f00 = acc[mt][nt][0] + b0, f01 = acc[mt][nt][1] + b1;
            float f10 = acc[mt][nt][2] + b0, f11 = acc[mt][nt][3] + b1;
            if (MODE == 0) {
                *(float2*)(Cout + (size_t)r0g * N + cg) = make_float2(f00, f01);
                *(float2*)(Cout + (size_t)(r0g + 8) * N + cg) = make_float2(f10, f11);
            } else {
                const int which = cg >> 10;
                const int c10 = cg & 1023;
                const int h = c10 >> 6;
                const int d = c10 & 63;
                const int br = r0g >> 11, tr = r0g & 2047;
                if (which == 0) {
                    size_t i0 = ((((size_t)br * HH + h) * TT) + tr) * DD + d;
                    split_store_f16x2(Qh_o, Ql_o, i0, f00 * QSC, f01 * QSC);
                    split_store_f16x2(Qh_o, Ql_o, i0 + 8 * DD, f10 * QSC, f11 * QSC);
                } else if (which == 1) {
                    size_t i0 = ((((size_t)br * HH + h) * TT) + tr) * DD + d;
                    __half2 h0 = __float22half2_rn(make_float2(f00, f01));
                    __half2 h1 = __float22half2_rn(make_float2(f10, f11));
                    *(uint32_t*)(K_o + i0) = *(uint32_t*)&h0;
                    *(uint32_t*)(K_o + i0 + 8 * DD) = *(uint32_t*)&h1;
                } else {
                    size_t i0 = (((size_t)br * HH + h) * DD + d) * TT + tr;
                    V_o[i0]          = __float2half(f00);
                    V_o[i0 + TT]     = __float2half(f01);
                    V_o[i0 + 8]      = __float2half(f10);
                    V_o[i0 + TT + 8] = __float2half(f11);
                }
            }
        }
    }
}

// ---------------------------------------------------------------------------
// Flash attention: fp16 mma, Q split-2, K/V single fp16.
// CTA = 64 queries (4 warps x 16 rows), KV tiles of 64, 2-stage cp.async.
// ---------------------------------------------------------------------------
#define ROWF 144
#define TILEF (64 * ROWF)   // 9216
#define FL_QH 0
#define FL_QL TILEF
#define FL_ST(s) (2 * TILEF + (s) * 2 * TILEF)
#define FL_SMEM (6 * TILEF)  // 55296

__global__ void __launch_bounds__(128, 3) flash_mma(
    const __half* __restrict__ Qh, const __half* __restrict__ Ql,
    const __half* __restrict__ Kg, const __half* __restrict__ Vg,
    __half* __restrict__ ath, __half* __restrict__ atl)
{
    extern __shared__ char smf[];
    const uint32_t sbase = (uint32_t)__cvta_generic_to_shared(smf);
    const int tid = threadIdx.x, wid = tid >> 5, lane = tid & 31;
    const int g = lane >> 2, tg = lane & 3;
    const int qt = 31 - blockIdx.x;
    const int bh = blockIdx.y;

    const __half* Qhb = Qh + (size_t)bh * TT * DD;
    const __half* Qlb = Ql + (size_t)bh * TT * DD;
    const __half* Kb = Kg + (size_t)bh * TT * DD;
    const __half* Vb = Vg + (size_t)bh * DD * TT;

    const int lrow = lane & 15, lhalf = lane >> 4;

#define ISSUE_KV(stg, kvi) do {                                                \
    const uint32_t _sb = sbase + FL_ST(stg);                                   \
    _Pragma("unroll")                                                          \
    for (int _i = 0; _i < 4; _i++) {                                           \
        int _ch = _i * 128 + tid;                                              \
        int _row = _ch >> 3, _c = _ch & 7;                                     \
        cp16(_sb + _row * ROWF + _c * 16,                                      \
             Kb + (size_t)(kvi) * 4096 + _ch * 8);                             \
        cp16(_sb + TILEF + _row * ROWF + _c * 16,                              \
             Vb + (size_t)_row * TT + (size_t)(kvi) * 64 + _c * 8);            \
    }                                                                          \
} while (0)

    // Prologue: Q tiles (group 0), KV tile 0 (group 1)
#pragma unroll
    for (int i = 0; i < 4; i++) {
        int ch = i * 128 + tid;
        int row = ch >> 3, c = ch & 7;
        uint32_t so = sbase + row * ROWF + c * 16;
        cp16(so + FL_QH, Qhb + (size_t)qt * 4096 + ch * 8);
        cp16(so + FL_QL, Qlb + (size_t)qt * 4096 + ch * 8);
    }
    cp_commit();
    ISSUE_KV(0, 0);
    cp_commit();
    cp_wait1();
    __syncthreads();

    // Q fragments via ldmatrix (held for whole kernel)
    uint32_t qfh[4][4], qfl[4][4];
    {
        const uint32_t qoff = sbase + (uint32_t)((wid * 16 + lrow) * ROWF + lhalf * 16);
#pragma unroll
        for (int j = 0; j < 4; j++) {
            ldsm4(qfh[j], qoff + FL_QH + j * 32);
            ldsm4(qfl[j], qoff + FL_QL + j * 32);
        }
    }

    float oacc[8][4];
#pragma unroll
    for (int i = 0; i < 8; i++)
#pragma unroll
        for (int jj = 0; jj < 4; jj++) oacc[i][jj] = 0.0f;
    float m0 = -1e30f, m1 = -1e30f, l0 = 0.0f, l1 = 0.0f;

    const uint32_t foff = (uint32_t)(lrow * ROWF + lhalf * 16);

    for (int kv = 0; kv <= qt; kv++) {
        const int s = kv & 1;
        if (kv < qt) { ISSUE_KV(s ^ 1, kv + 1); cp_commit(); cp_wait1(); }
        else cp_wait0();
        __syncthreads();

        const uint32_t KHs = sbase + FL_ST(s) + foff;
        const uint32_t VHs = KHs + TILEF;

        // S = (Qh + Ql) @ K^T
        float sa[8][4];
#pragma unroll
        for (int nt = 0; nt < 8; nt++)
#pragma unroll
            for (int jj = 0; jj < 4; jj++) sa[nt][jj] = 0.0f;

#pragma unroll
        for (int j = 0; j < 4; j++) {
#pragma unroll
            for (int p = 0; p < 4; p++) {
                uint32_t rk[4];
                ldsm4(rk, KHs + p * 16 * ROWF + j * 32);
                uint32_t bE[2] = { rk[0], rk[2] }, bO[2] = { rk[1], rk[3] };
                mma_f16(sa[2 * p],     qfh[j], bE);
                mma_f16(sa[2 * p],     qfl[j], bE);
                mma_f16(sa[2 * p + 1], qfh[j], bO);
                mma_f16(sa[2 * p + 1], qfl[j], bO);
            }
        }

        // Causal mask (diagonal tile only)
        if (kv == qt) {
            const int r0 = wid * 16 + g, r1 = r0 + 8;
#pragma unroll
            for (int nt = 0; nt < 8; nt++) {
                int c0 = nt * 8 + tg * 2;
                if (c0 > r0)     sa[nt][0] = -1e30f;
                if (c0 + 1 > r0) sa[nt][1] = -1e30f;
                if (c0 > r1)     sa[nt][2] = -1e30f;
                if (c0 + 1 > r1) sa[nt][3] = -1e30f;
            }
        }

        // Online softmax (log2 domain)
        float mt0 = sa[0][0], mt1 = sa[0][2];
#pragma unroll
        for (int nt = 0; nt < 8; nt++) {
            mt0 = fmaxf(mt0, fmaxf(sa[nt][0], sa[nt][1]));
            mt1 = fmaxf(mt1, fmaxf(sa[nt][2], sa[nt][3]));
        }
        mt0 = fmaxf(mt0, __shfl_xor_sync(0xffffffffu, mt0, 1));
        mt0 = fmaxf(mt0, __shfl_xor_sync(0xffffffffu, mt0, 2));
        mt1 = fmaxf(mt1, __shfl_xor_sync(0xffffffffu, mt1, 1));
        mt1 = fmaxf(mt1, __shfl_xor_sync(0xffffffffu, mt1, 2));

        float mn0 = fmaxf(m0, mt0), mn1 = fmaxf(m1, mt1);
        float cr0 = ex2f(m0 - mn0), cr1 = ex2f(m1 - mn1);
        m0 = mn0; m1 = mn1;

        float s0 = 0.0f, s1 = 0.0f;
#pragma unroll
        for (int nt = 0; nt < 8; nt++) {
            sa[nt][0] = ex2f(sa[nt][0] - mn0);
            sa[nt][1] = ex2f(sa[nt][1] - mn0);
            sa[nt][2] = ex2f(sa[nt][2] - mn1);
            sa[nt][3] = ex2f(sa[nt][3] - mn1);
            s0 += sa[nt][0] + sa[nt][1];
            s1 += sa[nt][2] + sa[nt][3];
        }
        s0 += __shfl_xor_sync(0xffffffffu, s0, 1);
        s0 += __shfl_xor_sync(0xffffffffu, s0, 2);
        s1 += __shfl_xor_sync(0xffffffffu, s1, 1);
        s1 += __shfl_xor_sync(0xffffffffu, s1, 2);
        l0 = l0 * cr0 + s0;
        l1 = l1 * cr1 + s1;

#pragma unroll
        for (int nt = 0; nt < 8; nt++) {
            oacc[nt][0] *= cr0; oacc[nt][1] *= cr0;
            oacc[nt][2] *= cr1; oacc[nt][3] *= cr1;
        }

        // Pack P to fp16 A-fragments
        uint32_t pa[4][4];
#pragma unroll
        for (int j = 0; j < 4; j++) {
            pa[j][0] = pack_f16(sa[2 * j][0], sa[2 * j][1]);
            pa[j][1] = pack_f16(sa[2 * j][2], sa[2 * j][3]);
            pa[j][2] = pack_f16(sa[2 * j + 1][0], sa[2 * j + 1][1]);
            pa[j][3] = pack_f16(sa[2 * j + 1][2], sa[2 * j + 1][3]);
        }

        // O += P @ V
#pragma unroll
        for (int j = 0; j < 4; j++) {
#pragma unroll
            for (int p = 0; p < 4; p++) {
                uint32_t rv[4];
                ldsm4(rv, VHs + p * 16 * ROWF + j * 32);
                uint32_t bE[2] = { rv[0], rv[2] }, bO[2] = { rv[1], rv[3] };
                mma_f16(oacc[2 * p],     pa[j], bE);
                mma_f16(oacc[2 * p + 1], pa[j], bO);
            }
        }
        __syncthreads();
    }

    // Epilogue: normalize, split to fp16 hi/lo att [M=B*T, C] (c = h*64+d)
    const float i0 = 1.0f / l0, i1 = 1.0f / l1;
    const int b = bh >> 4, h = bh & 15;
    const int t0 = qt * 64 + wid * 16 + g;
    const size_t row0 = ((size_t)b * TT + t0) * CC + h * DD;
    const size_t row1 = row0 + (size_t)8 * CC;
#pragma unroll
    for (int nt = 0; nt < 8; nt++) {
        const int d = nt * 8 + tg * 2;
        split_store_f16x2(ath, atl, row0 + d, oacc[nt][0] * i0, oacc[nt][1] * i0);
        split_store_f16x2(ath, atl, row1 + d, oacc[nt][2] * i1, oacc[nt][3] * i1);
    }
#undef ISSUE_KV
}

// ---------------------------------------------------------------------------
extern "C" void kernel_launch(void* const* d_in, const int* in_sizes, int n_in,
                              void* d_out, int out_size)
{
    (void)in_sizes; (void)n_in; (void)out_size;
    const float* x      = (const float*)d_in[0];
    const float* W_attn = (const float*)d_in[1];
    const float* b_attn = (const float*)d_in[2];
    const float* W_proj = (const float*)d_in[3];
    const float* b_proj = (const float*)d_in[4];
    float* out = (float*)d_out;

    __half *xh, *xl, *wa, *wp, *ath, *atl, *qh, *ql, *k, *v;
    cudaGetSymbolAddress((void**)&xh, g_xh);
    cudaGetSymbolAddress((void**)&xl, g_xl);
    cudaGetSymbolAddress((void**)&wa, g_wa);
    cudaGetSymbolAddress((void**)&wp, g_wp);
    cudaGetSymbolAddress((void**)&ath, g_ath);
    cudaGetSymbolAddress((void**)&atl, g_atl);
    cudaGetSymbolAddress((void**)&qh, g_qh);
    cudaGetSymbolAddress((void**)&ql, g_ql);
    cudaGetSymbolAddress((void**)&k, g_k);
    cudaGetSymbolAddress((void**)&v, g_v);

    cudaFuncSetAttribute(mma_gemm<0>, cudaFuncAttributeMaxDynamicSharedMemorySize, GEMM_SMEM);
    cudaFuncSetAttribute(mma_gemm<1>, cudaFuncAttributeMaxDynamicSharedMemorySize, GEMM_SMEM);
    cudaFuncSetAttribute(flash_mma, cudaFuncAttributeMaxDynamicSharedMemorySize, FL_SMEM);

    // 1) Split x into fp16 hi/lo
    prep_split<<<MROWS * CC / 4 / 256, 256>>>(x, xh, xl);

    // 2) Transpose weights to fp16 [N,K]
    {
        dim3 blk(32, 8);
        prep_wt<<<dim3(3 * CC / 32, CC / 32), blk>>>(W_attn, wa, CC, 3 * CC);
        prep_wt<<<dim3(CC / 32, CC / 32), blk>>>(W_proj, wp, CC, CC);
    }

    // 3) QKV GEMM -> q fp16 hi/lo (scaled), k fp16, v^T fp16
    mma_gemm<1><<<dim3(3 * CC / 128, MROWS / 128), 128, GEMM_SMEM>>>(
        xh, xl, wa, b_attn, nullptr, qh, ql, k, v, 3 * CC, CC);

    // 4) Flash attention -> att fp16 hi/lo
    flash_mma<<<dim3(TT / 64, BB * HH), 128, FL_SMEM>>>(
        qh, ql, k, v, ath, atl);

    // 5) Projection GEMM -> out (fp32)
    mma_gemm<0><<<dim3(CC / 128, MROWS / 128), 128, GEMM_SMEM>>>(
        ath, atl, wp, b_proj, out,
        nullptr, nullptr, nullptr, nullptr, CC, CC);
}

// round 8
// speedup vs baseline: 11.4556x; 1.0046x over previous
#include <cuda_runtime.h>
#include <cuda_bf16.h>
#include <cuda_fp16.h>
#include <math.h>
#include <stdint.h>

// Problem constants
#define BB 4
#define TT 2048
#define CC 1024
#define HH 16
#define DD 64
#define MROWS (BB * TT)   // 8192
#define QSC (0.125f * 1.44269504088896f)   // 1/sqrt(D) * log2(e), folded into Q

// ---------------------------------------------------------------------------
// Scratch (device globals) — fp16 scheme: activations split-2, weights single
// ---------------------------------------------------------------------------
__device__ __half g_xh[MROWS * CC], g_xl[MROWS * CC];     // x split [M,K]
__device__ __half g_wa[3 * CC * CC];                      // W_attn^T [3072,K]
__device__ __half g_wp[CC * CC];                          // W_proj^T [1024,K]
__device__ __half g_qh[BB * HH * TT * DD], g_ql[BB * HH * TT * DD];  // [B,H,T,D] scaled
__device__ __half g_k[BB * HH * TT * DD];                 // [B,H,T,D]
__device__ __half g_v[BB * HH * DD * TT];                 // [B,H,D,T] (V^T)
__device__ __half g_ath[MROWS * CC], g_atl[MROWS * CC];   // att split [M,K]

// ---------------------------------------------------------------------------
// PTX helpers
// ---------------------------------------------------------------------------
__device__ __forceinline__ void mma_f16(float* c, const uint32_t* a,
                                        const uint32_t* b) {
    asm volatile(
        "mma.sync.aligned.m16n8k16.row.col.f32.f16.f16.f32 "
        "{%0,%1,%2,%3}, {%4,%5,%6,%7}, {%8,%9}, {%0,%1,%2,%3};"
        : "+f"(c[0]), "+f"(c[1]), "+f"(c[2]), "+f"(c[3])
        : "r"(a[0]), "r"(a[1]), "r"(a[2]), "r"(a[3]), "r"(b[0]), "r"(b[1]));
}
__device__ __forceinline__ void ldsm4(uint32_t* r, uint32_t addr) {
    asm volatile("ldmatrix.sync.aligned.m8n8.x4.shared.b16 {%0,%1,%2,%3}, [%4];"
                 : "=r"(r[0]), "=r"(r[1]), "=r"(r[2]), "=r"(r[3]) : "r"(addr));
}
__device__ __forceinline__ float ex2f(float x) {
    float y;
    asm("ex2.approx.f32 %0, %1;" : "=f"(y) : "f"(x));
    return y;
}
__device__ __forceinline__ uint32_t pack_f16(float lo, float hi) {
    __half2 h = __float22half2_rn(make_float2(lo, hi));
    return *(uint32_t*)&h;
}
__device__ __forceinline__ void split_store_f16x2(__half* hi, __half* lo,
                                                  size_t i, float a, float b) {
    __half2 h = __float22half2_rn(make_float2(a, b));
    float2 hf = __half22float2(h);
    *(uint32_t*)(hi + i) = *(uint32_t*)&h;
    __half2 l = __float22half2_rn(make_float2(a - hf.x, b - hf.y));
    *(uint32_t*)(lo + i) = *(uint32_t*)&l;
}
__device__ __forceinline__ void cp16(uint32_t s, const void* g) {
    asm volatile("cp.async.cg.shared.global [%0], [%1], 16;" :: "r"(s), "l"(g));
}
__device__ __forceinline__ void cp_commit() {
    asm volatile("cp.async.commit_group;" ::: "memory");
}
__device__ __forceinline__ void cp_wait1() {
    asm volatile("cp.async.wait_group 1;" ::: "memory");
}
__device__ __forceinline__ void cp_wait0() {
    asm volatile("cp.async.wait_group 0;" ::: "memory");
}

// ---------------------------------------------------------------------------
// Prep kernels
// ---------------------------------------------------------------------------
__global__ void prep_split(const float* __restrict__ src,
                           __half* __restrict__ hi, __half* __restrict__ lo) {
    int idx = blockIdx.x * blockDim.x + threadIdx.x;
    float4 v = ((const float4*)src)[idx];
    split_store_f16x2(hi, lo, (size_t)idx * 4, v.x, v.y);
    split_store_f16x2(hi, lo, (size_t)idx * 4 + 2, v.z, v.w);
}

__global__ void prep_wt(const float* __restrict__ W,
                        __half* __restrict__ Wt, int K, int N) {
    __shared__ float t[32][33];
    const int tx = threadIdx.x, ty = threadIdx.y;
    const int n0 = blockIdx.x * 32, k0 = blockIdx.y * 32;
#pragma unroll
    for (int i = 0; i < 4; i++)
        t[ty + i * 8][tx] = W[(size_t)(k0 + ty + i * 8) * N + n0 + tx];
    __syncthreads();
#pragma unroll
    for (int i = 0; i < 4; i++)
        Wt[(size_t)(n0 + ty + i * 8) * K + k0 + tx] = __float2half(t[tx][ty + i * 8]);
}

// ---------------------------------------------------------------------------
// fp16 split-2 GEMM: C = (Ah+Al)@Bh^T + bias.
// CTA 128x128, 4 warps (2x2), warp tile 64x64, K-chunk 32, 3-stage cp.async.
// Hand-scheduled: B-fragment ping-pong, A-fragment cross-substep prefetch,
// mma grouped so same-acc reuse distance is 8 instructions.
// MODE 0: fp32 row-major out. MODE 1: QKV epilogue (fp16 outputs).
// ---------------------------------------------------------------------------
#define ROWB 80
#define TILE_B (128 * ROWB)           // 10240
#define STAGE_B (3 * TILE_B)          // 30720 (Ah, Al, Bh)
#define NSTG 3
#define GEMM_SMEM (NSTG * STAGE_B)    // 92160

template <int MODE>
__global__ void __launch_bounds__(128, 2) mma_gemm(
    const __half* __restrict__ Ah_, const __half* __restrict__ Al_,
    const __half* __restrict__ Bh_,
    const float* __restrict__ bias,
    float* __restrict__ Cout,
    __half* __restrict__ Qh_o, __half* __restrict__ Ql_o,
    __half* __restrict__ K_o, __half* __restrict__ V_o,
    int N, int K)
{
    extern __shared__ char smg[];
    const uint32_t sbase = (uint32_t)__cvta_generic_to_shared(smg);
    const int tid = threadIdx.x;
    const int wid = tid >> 5, lane = tid & 31;
    const int wm = wid >> 1, wn = wid & 1;
    const int g = lane >> 2, tg = lane & 3;
    const int lrow = lane & 15, lhalf = lane >> 4;
    const int m0 = blockIdx.y * 128, n0 = blockIdx.x * 128;

    const __half* Ah = Ah_ + (size_t)m0 * K;
    const __half* Al = Al_ + (size_t)m0 * K;
    const __half* Bh = Bh_ + (size_t)n0 * K;
    const __half* tp[3] = { Ah, Al, Bh };

    const uint32_t aoff = (uint32_t)((wm * 64 + lrow) * ROWB + lhalf * 16);
    const uint32_t boff = (uint32_t)((wn * 64 + lrow) * ROWB + lhalf * 16) + 2 * TILE_B;

    float acc[4][8][4];
#pragma unroll
    for (int mt = 0; mt < 4; mt++)
#pragma unroll
        for (int nt = 0; nt < 8; nt++)
#pragma unroll
            for (int i = 0; i < 4; i++) acc[mt][nt][i] = 0.0f;

#define GEMM_ISSUE(chunk) do {                                                 \
    const uint32_t _sb = sbase + ((chunk) % NSTG) * STAGE_B;                   \
    const int _kc = (chunk) * 32;                                              \
    _Pragma("unroll")                                                          \
    for (int _i = 0; _i < 12; _i++) {                                          \
        int _e = _i * 128 + tid;                                               \
        int _t = _e >> 9, _r = (_e & 511) >> 2, _h = _e & 3;                   \
        cp16(_sb + _t * TILE_B + _r * ROWB + _h * 16,                          \
             tp[_t] + (size_t)_r * K + _kc + _h * 8);                          \
    }                                                                          \
} while (0)

    const int NCH = K / 32;
    GEMM_ISSUE(0); cp_commit();
    GEMM_ISSUE(1); cp_commit();

    uint32_t ah[2][4][4], al[2][4][4], rb[2][4];

    for (int c = 0; c < NCH; c++) {
        cp_wait1();
        __syncthreads();

        const uint32_t st = sbase + (c % NSTG) * STAGE_B;

        // A fragments for substep 0; first B fragment
#pragma unroll
        for (int mt = 0; mt < 4; mt++) {
            ldsm4(ah[0][mt], st + aoff + mt * 16 * ROWB);
            ldsm4(al[0][mt], st + TILE_B + aoff + mt * 16 * ROWB);
        }
        ldsm4(rb[0], st + boff);

#pragma unroll
        for (int ks = 0; ks < 2; ks++) {
#pragma unroll
            for (int p = 0; p < 4; p++) {
                const int idx = ks * 4 + p;
                const int cur = idx & 1;
                if (idx < 7) {
                    const int nk = (idx + 1) >> 2, np = (idx + 1) & 3;
                    ldsm4(rb[cur ^ 1], st + boff + np * 16 * ROWB + nk * 32);
                }
                if (ks == 0 && p == 1) {
                    // Prefetch substep-1 A fragments mid-stream
#pragma unroll
                    for (int mt = 0; mt < 4; mt++) {
                        ldsm4(ah[1][mt], st + aoff + mt * 16 * ROWB + 32);
                        ldsm4(al[1][mt], st + TILE_B + aoff + mt * 16 * ROWB + 32);
                    }
                }
                uint32_t bE[2] = { rb[cur][0], rb[cur][2] };
                uint32_t bO[2] = { rb[cur][1], rb[cur][3] };
                // 4 groups of 4 independent mma; acc reuse distance = 8
#pragma unroll
                for (int mt = 0; mt < 4; mt++) mma_f16(acc[mt][2 * p],     ah[ks][mt], bE);
#pragma unroll
                for (int mt = 0; mt < 4; mt++) mma_f16(acc[mt][2 * p + 1], ah[ks][mt], bO);
#pragma unroll
                for (int mt = 0; mt < 4; mt++) mma_f16(acc[mt][2 * p],     al[ks][mt], bE);
#pragma unroll
                for (int mt = 0; mt < 4; mt++) mma_f16(acc[mt][2 * p + 1], al[ks][mt], bO);
            }
        }

        if (c + 2 < NCH) GEMM_ISSUE(c + 2);
        cp_commit();   // empty group at tail keeps wait accounting uniform
    }
#undef GEMM_ISSUE

    // Epilogue
#pragma unroll
    for (int mt = 0; mt < 4; mt++) {
#pragma unroll
        for (int nt = 0; nt < 8; nt++) {
            const int cg = n0 + wn * 64 + nt * 8 + tg * 2;
            const int r0g = m0 + wm * 64 + mt * 16 + g;
            const float b0 = __ldg(bias + cg);
            const float b1 = __ldg(bias + cg + 1);
            float f00 = acc[mt][nt][0] + b0, f01 = acc[mt][nt][1] + b1;
            float f10 = acc[mt][nt][2] + b0, f11 = acc[mt][nt][3] + b1;
            if (MODE == 0) {
                *(float2*)(Cout + (size_t)r0g * N + cg) = make_float2(f00, f01);
                *(float2*)(Cout + (size_t)(r0g + 8) * N + cg) = make_float2(f10, f11);
            } else {
                const int which = cg >> 10;
                const int c10 = cg & 1023;
                const int h = c10 >> 6;
                const int d = c10 & 63;
                const int br = r0g >> 11, tr = r0g & 2047;
                if (which == 0) {
                    size_t i0 = ((((size_t)br * HH + h) * TT) + tr) * DD + d;
                    split_store_f16x2(Qh_o, Ql_o, i0, f00 * QSC, f01 * QSC);
                    split_store_f16x2(Qh_o, Ql_o, i0 + 8 * DD, f10 * QSC, f11 * QSC);
                } else if (which == 1) {
                    size_t i0 = ((((size_t)br * HH + h) * TT) + tr) * DD + d;
                    __half2 h0 = __float22half2_rn(make_float2(f00, f01));
                    __half2 h1 = __float22half2_rn(make_float2(f10, f11));
                    *(uint32_t*)(K_o + i0) = *(uint32_t*)&h0;
                    *(uint32_t*)(K_o + i0 + 8 * DD) = *(uint32_t*)&h1;
                } else {
                    size_t i0 = (((size_t)br * HH + h) * DD + d) * TT + tr;
                    V_o[i0]          = __float2half(f00);
                    V_o[i0 + TT]     = __float2half(f01);
                    V_o[i0 + 8]      = __float2half(f10);
                    V_o[i0 + TT + 8] = __float2half(f11);
                }
            }
        }
    }
}

// ---------------------------------------------------------------------------
// Flash attention: fp16 mma, Q split-2, K/V single fp16.
// CTA = 64 queries (4 warps x 16 rows), KV tiles of 64, 2-stage cp.async.
// Hand-scheduled fragment preloads + independent mma sweeps.
// ---------------------------------------------------------------------------
#define ROWF 144
#define TILEF (64 * ROWF)   // 9216
#define FL_QH 0
#define FL_QL TILEF
#define FL_ST(s) (2 * TILEF + (s) * 2 * TILEF)
#define FL_SMEM (6 * TILEF)  // 55296

__global__ void __launch_bounds__(128, 3) flash_mma(
    const __half* __restrict__ Qh, const __half* __restrict__ Ql,
    const __half* __restrict__ Kg, const __half* __restrict__ Vg,
    __half* __restrict__ ath, __half* __restrict__ atl)
{
    extern __shared__ char smf[];
    const uint32_t sbase = (uint32_t)__cvta_generic_to_shared(smf);
    const int tid = threadIdx.x, wid = tid >> 5, lane = tid & 31;
    const int g = lane >> 2, tg = lane & 3;
    const int qt = 31 - blockIdx.x;
    const int bh = blockIdx.y;

    const __half* Qhb = Qh + (size_t)bh * TT * DD;
    const __half* Qlb = Ql + (size_t)bh * TT * DD;
    const __half* Kb = Kg + (size_t)bh * TT * DD;
    const __half* Vb = Vg + (size_t)bh * DD * TT;

    const int lrow = lane & 15, lhalf = lane >> 4;

#define ISSUE_KV(stg, kvi) do {                                                \
    const uint32_t _sb = sbase + FL_ST(stg);                                   \
    _Pragma("unroll")                                                          \
    for (int _i = 0; _i < 4; _i++) {                                           \
        int _ch = _i * 128 + tid;                                              \
        int _row = _ch >> 3, _c = _ch & 7;                                     \
        cp16(_sb + _row * ROWF + _c * 16,                                      \
             Kb + (size_t)(kvi) * 4096 + _ch * 8);                             \
        cp16(_sb + TILEF + _row * ROWF + _c * 16,                              \
             Vb + (size_t)_row * TT + (size_t)(kvi) * 64 + _c * 8);            \
    }                                                                          \
} while (0)

    // Prologue: Q tiles (group 0), KV tile 0 (group 1)
#pragma unroll
    for (int i = 0; i < 4; i++) {
        int ch = i * 128 + tid;
        int row = ch >> 3, c = ch & 7;
        uint32_t so = sbase + row * ROWF + c * 16;
        cp16(so + FL_QH, Qhb + (size_t)qt * 4096 + ch * 8);
        cp16(so + FL_QL, Qlb + (size_t)qt * 4096 + ch * 8);
    }
    cp_commit();
    ISSUE_KV(0, 0);
    cp_commit();
    cp_wait1();
    __syncthreads();

    // Q fragments via ldmatrix (held for whole kernel)
    uint32_t qfh[4][4], qfl[4][4];
    {
        const uint32_t qoff = sbase + (uint32_t)((wid * 16 + lrow) * ROWF + lhalf * 16);
#pragma unroll
        for (int j = 0; j < 4; j++) {
            ldsm4(qfh[j], qoff + FL_QH + j * 32);
            ldsm4(qfl[j], qoff + FL_QL + j * 32);
        }
    }

    float oacc[8][4];
#pragma unroll
    for (int i = 0; i < 8; i++)
#pragma unroll
        for (int jj = 0; jj < 4; jj++) oacc[i][jj] = 0.0f;
    float m0 = -1e30f, m1 = -1e30f, l0 = 0.0f, l1 = 0.0f;

    const uint32_t foff = (uint32_t)(lrow * ROWF + lhalf * 16);

    for (int kv = 0; kv <= qt; kv++) {
        const int s = kv & 1;
        if (kv < qt) { ISSUE_KV(s ^ 1, kv + 1); cp_commit(); cp_wait1(); }
        else cp_wait0();
        __syncthreads();

        const uint32_t KHs = sbase + FL_ST(s) + foff;
        const uint32_t VHs = KHs + TILEF;

        // S = (Qh + Ql) @ K^T — preload 4 K-frags per j, two indep sweeps
        float sa[8][4];
#pragma unroll
        for (int nt = 0; nt < 8; nt++)
#pragma unroll
            for (int jj = 0; jj < 4; jj++) sa[nt][jj] = 0.0f;

#pragma unroll
        for (int j = 0; j < 4; j++) {
            uint32_t rk[4][4];
#pragma unroll
            for (int p = 0; p < 4; p++) ldsm4(rk[p], KHs + p * 16 * ROWF + j * 32);
#pragma unroll
            for (int p = 0; p < 4; p++) {
                uint32_t bE[2] = { rk[p][0], rk[p][2] }, bO[2] = { rk[p][1], rk[p][3] };
                mma_f16(sa[2 * p],     qfh[j], bE);
                mma_f16(sa[2 * p + 1], qfh[j], bO);
            }
#pragma unroll
            for (int p = 0; p < 4; p++) {
                uint32_t bE[2] = { rk[p][0], rk[p][2] }, bO[2] = { rk[p][1], rk[p][3] };
                mma_f16(sa[2 * p],     qfl[j], bE);
                mma_f16(sa[2 * p + 1], qfl[j], bO);
            }
        }

        // Causal mask (diagonal tile only)
        if (kv == qt) {
            const int r0 = wid * 16 + g, r1 = r0 + 8;
#pragma unroll
            for (int nt = 0; nt < 8; nt++) {
                int c0 = nt * 8 + tg * 2;
                if (c0 > r0)     sa[nt][0] = -1e30f;
                if (c0 + 1 > r0) sa[nt][1] = -1e30f;
                if (c0 > r1)     sa[nt][2] = -1e30f;
                if (c0 + 1 > r1) sa[nt][3] = -1e30f;
            }
        }

        // Online softmax (log2 domain)
        float mt0 = sa[0][0], mt1 = sa[0][2];
#pragma unroll
        for (int nt = 0; nt < 8; nt++) {
            mt0 = fmaxf(mt0, fmaxf(sa[nt][0], sa[nt][1]));
            mt1 = fmaxf(mt1, fmaxf(sa[nt][2], sa[nt][3]));
        }
        mt0 = fmaxf(mt0, __shfl_xor_sync(0xffffffffu, mt0, 1));
        mt0 = fmaxf(mt0, __shfl_xor_sync(0xffffffffu, mt0, 2));
        mt1 = fmaxf(mt1, __shfl_xor_sync(0xffffffffu, mt1, 1));
        mt1 = fmaxf(mt1, __shfl_xor_sync(0xffffffffu, mt1, 2));

        float mn0 = fmaxf(m0, mt0), mn1 = fmaxf(m1, mt1);
        float cr0 = ex2f(m0 - mn0), cr1 = ex2f(m1 - mn1);
        m0 = mn0; m1 = mn1;

        float s0 = 0.0f, s1 = 0.0f;
#pragma unroll
        for (int nt = 0; nt < 8; nt++) {
            sa[nt][0] = ex2f(sa[nt][0] - mn0);
            sa[nt][1] = ex2f(sa[nt][1] - mn0);
            sa[nt][2] = ex2f(sa[nt][2] - mn1);
            sa[nt][3] = ex2f(sa[nt][3] - mn1);
            s0 += sa[nt][0] + sa[nt][1];
            s1 += sa[nt][2] + sa[nt][3];
        }
        s0 += __shfl_xor_sync(0xffffffffu, s0, 1);
        s0 += __shfl_xor_sync(0xffffffffu, s0, 2);
        s1 += __shfl_xor_sync(0xffffffffu, s1, 1);
        s1 += __shfl_xor_sync(0xffffffffu, s1, 2);
        l0 = l0 * cr0 + s0;
        l1 = l1 * cr1 + s1;

#pragma unroll
        for (int nt = 0; nt < 8; nt++) {
            oacc[nt][0] *= cr0; oacc[nt][1] *= cr0;
            oacc[nt][2] *= cr1; oacc[nt][3] *= cr1;
        }

        // Pack P to fp16 A-fragments
        uint32_t pa[4][4];
#pragma unroll
        for (int j = 0; j < 4; j++) {
            pa[j][0] = pack_f16(sa[2 * j][0], sa[2 * j][1]);
            pa[j][1] = pack_f16(sa[2 * j][2], sa[2 * j][3]);
            pa[j][2] = pack_f16(sa[2 * j + 1][0], sa[2 * j + 1][1]);
            pa[j][3] = pack_f16(sa[2 * j + 1][2], sa[2 * j + 1][3]);
        }

        // O += P @ V — preload 4 V-frags per j, one indep sweep
#pragma unroll
        for (int j = 0; j < 4; j++) {
            uint32_t rv[4][4];
#pragma unroll
            for (int p = 0; p < 4; p++) ldsm4(rv[p], VHs + p * 16 * ROWF + j * 32);
#pragma unroll
            for (int p = 0; p < 4; p++) {
                uint32_t bE[2] = { rv[p][0], rv[p][2] }, bO[2] = { rv[p][1], rv[p][3] };
                mma_f16(oacc[2 * p],     pa[j], bE);
                mma_f16(oacc[2 * p + 1], pa[j], bO);
            }
        }
        __syncthreads();
    }

    // Epilogue: normalize, split to fp16 hi/lo att [M=B*T, C] (c = h*64+d)
    const float i0 = 1.0f / l0, i1 = 1.0f / l1;
    const int b = bh >> 4, h = bh & 15;
    const int t0 = qt * 64 + wid * 16 + g;
    const size_t row0 = ((size_t)b * TT + t0) * CC + h * DD;
    const size_t row1 = row0 + (size_t)8 * CC;
#pragma unroll
    for (int nt = 0; nt < 8; nt++) {
        const int d = nt * 8 + tg * 2;
        split_store_f16x2(ath, atl, row0 + d, oacc[nt][0] * i0, oacc[nt][1] * i0);
        split_store_f16x2(ath, atl, row1 + d, oacc[nt][2] * i1, oacc[nt][3] * i1);
    }
#undef ISSUE_KV
}

// ---------------------------------------------------------------------------
extern "C" void kernel_launch(void* const* d_in, const int* in_sizes, int n_in,
                              void* d_out, int out_size)
{
    (void)in_sizes; (void)n_in; (void)out_size;
    const float* x      = (const float*)d_in[0];
    const float* W_attn = (const float*)d_in[1];
    const float* b_attn = (const float*)d_in[2];
    const float* W_proj = (const float*)d_in[3];
    const float* b_proj = (const float*)d_in[4];
    float* out = (float*)d_out;

    __half *xh, *xl, *wa, *wp, *ath, *atl, *qh, *ql, *k, *v;
    cudaGetSymbolAddress((void**)&xh, g_xh);
    cudaGetSymbolAddress((void**)&xl, g_xl);
    cudaGetSymbolAddress((void**)&wa, g_wa);
    cudaGetSymbolAddress((void**)&wp, g_wp);
    cudaGetSymbolAddress((void**)&ath, g_ath);
    cudaGetSymbolAddress((void**)&atl, g_atl);
    cudaGetSymbolAddress((void**)&qh, g_qh);
    cudaGetSymbolAddress((void**)&ql, g_ql);
    cudaGetSymbolAddress((void**)&k, g_k);
    cudaGetSymbolAddress((void**)&v, g_v);

    cudaFuncSetAttribute(mma_gemm<0>, cudaFuncAttributeMaxDynamicSharedMemorySize, GEMM_SMEM);
    cudaFuncSetAttribute(mma_gemm<1>, cudaFuncAttributeMaxDynamicSharedMemorySize, GEMM_SMEM);
    cudaFuncSetAttribute(flash_mma, cudaFuncAttributeMaxDynamicSharedMemorySize, FL_SMEM);

    // 1) Split x into fp16 hi/lo
    prep_split<<<MROWS * CC / 4 / 256, 256>>>(x, xh, xl);

    // 2) Transpose weights to fp16 [N,K]
    {
        dim3 blk(32, 8);
        prep_wt<<<dim3(3 * CC / 32, CC / 32), blk>>>(W_attn, wa, CC, 3 * CC);
        prep_wt<<<dim3(CC / 32, CC / 32), blk>>>(W_proj, wp, CC, CC);
    }

    // 3) QKV GEMM -> q fp16 hi/lo (scaled), k fp16, v^T fp16
    mma_gemm<1><<<dim3(3 * CC / 128, MROWS / 128), 128, GEMM_SMEM>>>(
        xh, xl, wa, b_attn, nullptr, qh, ql, k, v, 3 * CC, CC);

    // 4) Flash attention -> att fp16 hi/lo
    flash_mma<<<dim3(TT / 64, BB * HH), 128, FL_SMEM>>>(
        qh, ql, k, v, ath, atl);

    // 5) Projection GEMM -> out (fp32)
    mma_gemm<0><<<dim3(CC / 128, MROWS / 128), 128, GEMM_SMEM>>>(
        ath, atl, wp, b_proj, out,
        nullptr, nullptr, nullptr, nullptr, CC, CC);
}

// round 9
// speedup vs baseline: 13.4030x; 1.1700x over previous
#include <cuda_runtime.h>
#include <cuda_bf16.h>
#include <cuda_fp16.h>
#include <math.h>
#include <stdint.h>

// Problem constants
#define BB 4
#define TT 2048
#define CC 1024
#define HH 16
#define DD 64
#define MROWS (BB * TT)   // 8192
#define QSC (0.125f * 1.44269504088896f)   // 1/sqrt(D) * log2(e), folded into Q

// ---------------------------------------------------------------------------
// Scratch (device globals)
// ---------------------------------------------------------------------------
__device__ __half g_xh[MROWS * CC], g_xl[MROWS * CC];     // x split [M,K]
__device__ __half g_wa[3 * CC * CC];                      // W_attn^T [3072,K]
__device__ __half g_wp[CC * CC];                          // W_proj^T [1024,K]
__device__ __half g_q[BB * HH * TT * DD];                 // [B,H,T,D] scaled fp16
__device__ __half g_k[BB * HH * TT * DD];                 // [B,H,T,D]
__device__ __half g_v[BB * HH * DD * TT];                 // [B,H,D,T] (V^T)
__device__ __half g_at[MROWS * CC];                       // att fp16 [M,K]

// ---------------------------------------------------------------------------
// PTX helpers
// ---------------------------------------------------------------------------
__device__ __forceinline__ void mma_f16(float* c, const uint32_t* a,
                                        const uint32_t* b) {
    asm volatile(
        "mma.sync.aligned.m16n8k16.row.col.f32.f16.f16.f32 "
        "{%0,%1,%2,%3}, {%4,%5,%6,%7}, {%8,%9}, {%0,%1,%2,%3};"
        : "+f"(c[0]), "+f"(c[1]), "+f"(c[2]), "+f"(c[3])
        : "r"(a[0]), "r"(a[1]), "r"(a[2]), "r"(a[3]), "r"(b[0]), "r"(b[1]));
}
__device__ __forceinline__ void ldsm4(uint32_t* r, uint32_t addr) {
    asm volatile("ldmatrix.sync.aligned.m8n8.x4.shared.b16 {%0,%1,%2,%3}, [%4];"
                 : "=r"(r[0]), "=r"(r[1]), "=r"(r[2]), "=r"(r[3]) : "r"(addr));
}
__device__ __forceinline__ float ex2f(float x) {
    float y;
    asm("ex2.approx.f32 %0, %1;" : "=f"(y) : "f"(x));
    return y;
}
__device__ __forceinline__ uint32_t pack_f16(float lo, float hi) {
    __half2 h = __float22half2_rn(make_float2(lo, hi));
    return *(uint32_t*)&h;
}
__device__ __forceinline__ void split_store_f16x2(__half* hi, __half* lo,
                                                  size_t i, float a, float b) {
    __half2 h = __float22half2_rn(make_float2(a, b));
    float2 hf = __half22float2(h);
    *(uint32_t*)(hi + i) = *(uint32_t*)&h;
    __half2 l = __float22half2_rn(make_float2(a - hf.x, b - hf.y));
    *(uint32_t*)(lo + i) = *(uint32_t*)&l;
}
__device__ __forceinline__ void cp16(uint32_t s, const void* g) {
    asm volatile("cp.async.cg.shared.global [%0], [%1], 16;" :: "r"(s), "l"(g));
}
__device__ __forceinline__ void cp_commit() {
    asm volatile("cp.async.commit_group;" ::: "memory");
}
__device__ __forceinline__ void cp_wait1() {
    asm volatile("cp.async.wait_group 1;" ::: "memory");
}
__device__ __forceinline__ void cp_wait0() {
    asm volatile("cp.async.wait_group 0;" ::: "memory");
}

// ---------------------------------------------------------------------------
// Prep kernels
// ---------------------------------------------------------------------------
__global__ void prep_split(const float* __restrict__ src,
                           __half* __restrict__ hi, __half* __restrict__ lo) {
    int idx = blockIdx.x * blockDim.x + threadIdx.x;
    float4 v = ((const float4*)src)[idx];
    split_store_f16x2(hi, lo, (size_t)idx * 4, v.x, v.y);
    split_store_f16x2(hi, lo, (size_t)idx * 4 + 2, v.z, v.w);
}

__global__ void prep_wt(const float* __restrict__ W,
                        __half* __restrict__ Wt, int K, int N) {
    __shared__ float t[32][33];
    const int tx = threadIdx.x, ty = threadIdx.y;
    const int n0 = blockIdx.x * 32, k0 = blockIdx.y * 32;
#pragma unroll
    for (int i = 0; i < 4; i++)
        t[ty + i * 8][tx] = W[(size_t)(k0 + ty + i * 8) * N + n0 + tx];
    __syncthreads();
#pragma unroll
    for (int i = 0; i < 4; i++)
        Wt[(size_t)(n0 + ty + i * 8) * K + k0 + tx] = __float2half(t[tx][ty + i * 8]);
}

// ---------------------------------------------------------------------------
// fp16 GEMM: C = (A [+ Al]) @ B^T + bias, NSPLIT = 1 or 2 A-terms.
// CTA 128x128, 4 warps (2x2), warp tile 64x64, K-chunk 32, 3-stage cp.async.
// MODE 0: fp32 row-major out. MODE 1: QKV epilogue (fp16 q/k/v^T outputs).
// ---------------------------------------------------------------------------
#define ROWB 80
#define TILE_B (128 * ROWB)           // 10240
#define NSTG 3

template <int MODE, int NSPLIT>
__global__ void __launch_bounds__(128, 2) mma_gemm(
    const __half* __restrict__ Ah_, const __half* __restrict__ Al_,
    const __half* __restrict__ Bh_,
    const float* __restrict__ bias,
    float* __restrict__ Cout,
    __half* __restrict__ Q_o, __half* __restrict__ K_o, __half* __restrict__ V_o,
    int N, int K)
{
    extern __shared__ char smg[];
    const uint32_t sbase = (uint32_t)__cvta_generic_to_shared(smg);
    const int tid = threadIdx.x;
    const int wid = tid >> 5, lane = tid & 31;
    const int wm = wid >> 1, wn = wid & 1;
    const int g = lane >> 2, tg = lane & 3;
    const int lrow = lane & 15, lhalf = lane >> 4;
    const int m0 = blockIdx.y * 128, n0 = blockIdx.x * 128;
    const int STAGE_B = (NSPLIT + 1) * TILE_B;

    const __half* Ah = Ah_ + (size_t)m0 * K;
    const __half* Al = (NSPLIT == 2) ? (Al_ + (size_t)m0 * K) : nullptr;
    const __half* Bh = Bh_ + (size_t)n0 * K;
    const __half* tp[3];
    tp[0] = Ah;
    tp[1] = (NSPLIT == 2) ? Al : Bh;
    tp[2] = Bh;

    const uint32_t aoff = (uint32_t)((wm * 64 + lrow) * ROWB + lhalf * 16);
    const uint32_t boff = (uint32_t)((wn * 64 + lrow) * ROWB + lhalf * 16)
                          + NSPLIT * TILE_B;

    float acc[4][8][4];
#pragma unroll
    for (int mt = 0; mt < 4; mt++)
#pragma unroll
        for (int nt = 0; nt < 8; nt++)
#pragma unroll
            for (int i = 0; i < 4; i++) acc[mt][nt][i] = 0.0f;

#define GEMM_ISSUE(chunk) do {                                                 \
    const uint32_t _sb = sbase + ((chunk) % NSTG) * STAGE_B;                   \
    const int _kc = (chunk) * 32;                                              \
    _Pragma("unroll")                                                          \
    for (int _i = 0; _i < (NSPLIT + 1) * 4; _i++) {                            \
        int _e = _i * 128 + tid;                                               \
        int _t = _e >> 9, _r = (_e & 511) >> 2, _h = _e & 3;                   \
        cp16(_sb + _t * TILE_B + _r * ROWB + _h * 16,                          \
             tp[_t] + (size_t)_r * K + _kc + _h * 8);                          \
    }                                                                          \
} while (0)

    const int NCH = K / 32;
    GEMM_ISSUE(0); cp_commit();
    GEMM_ISSUE(1); cp_commit();

    for (int c = 0; c < NCH; c++) {
        cp_wait1();
        __syncthreads();

        const uint32_t st = sbase + (c % NSTG) * STAGE_B;

#pragma unroll
        for (int ks = 0; ks < 2; ks++) {
            uint32_t ah[4][4], al[4][4];
#pragma unroll
            for (int mt = 0; mt < 4; mt++) {
                ldsm4(ah[mt], st + aoff + mt * 16 * ROWB + ks * 32);
                if (NSPLIT == 2)
                    ldsm4(al[mt], st + TILE_B + aoff + mt * 16 * ROWB + ks * 32);
            }
#pragma unroll
            for (int p = 0; p < 4; p++) {
                uint32_t rb[4];
                ldsm4(rb, st + boff + p * 16 * ROWB + ks * 32);
                uint32_t bE[2] = { rb[0], rb[2] }, bO[2] = { rb[1], rb[3] };
#pragma unroll
                for (int mt = 0; mt < 4; mt++) mma_f16(acc[mt][2 * p],     ah[mt], bE);
#pragma unroll
                for (int mt = 0; mt < 4; mt++) mma_f16(acc[mt][2 * p + 1], ah[mt], bO);
                if (NSPLIT == 2) {
#pragma unroll
                    for (int mt = 0; mt < 4; mt++) mma_f16(acc[mt][2 * p],     al[mt], bE);
#pragma unroll
                    for (int mt = 0; mt < 4; mt++) mma_f16(acc[mt][2 * p + 1], al[mt], bO);
                }
            }
        }

        if (c + 2 < NCH) GEMM_ISSUE(c + 2);
        cp_commit();   // empty group at tail keeps wait accounting uniform
    }
#undef GEMM_ISSUE

    // Epilogue
#pragma unroll
    for (int mt = 0; mt < 4; mt++) {
#pragma unroll
        for (int nt = 0; nt < 8; nt++) {
            const int cg = n0 + wn * 64 + nt * 8 + tg * 2;
            const int r0g = m0 + wm * 64 + mt * 16 + g;
            const float b0 = __ldg(bias + cg);
            const float b1 = __ldg(bias + cg + 1);
            float f00 = acc[mt][nt][0] + b0, f01 = acc[mt][nt][1] + b1;
            float f10 = acc[mt][nt][2] + b0, f11 = acc[mt][nt][3] + b1;
            if (MODE == 0) {
                *(float2*)(Cout + (size_t)r0g * N + cg) = make_float2(f00, f01);
                *(float2*)(Cout + (size_t)(r0g + 8) * N + cg) = make_float2(f10, f11);
            } else {
                const int which = cg >> 10;
                const int c10 = cg & 1023;
                const int h = c10 >> 6;
                const int d = c10 & 63;
                const int br = r0g >> 11, tr = r0g & 2047;
                if (which == 0) {
                    size_t i0 = ((((size_t)br * HH + h) * TT) + tr) * DD + d;
                    *(uint32_t*)(Q_o + i0)          = pack_f16(f00 * QSC, f01 * QSC);
                    *(uint32_t*)(Q_o + i0 + 8 * DD) = pack_f16(f10 * QSC, f11 * QSC);
                } else if (which == 1) {
                    size_t i0 = ((((size_t)br * HH + h) * TT) + tr) * DD + d;
                    *(uint32_t*)(K_o + i0)          = pack_f16(f00, f01);
                    *(uint32_t*)(K_o + i0 + 8 * DD) = pack_f16(f10, f11);
                } else {
                    size_t i0 = (((size_t)br * HH + h) * DD + d) * TT + tr;
                    V_o[i0]          = __float2half(f00);
                    V_o[i0 + TT]     = __float2half(f01);
                    V_o[i0 + 8]      = __float2half(f10);
                    V_o[i0 + TT + 8] = __float2half(f11);
                }
            }
        }
    }
}

// ---------------------------------------------------------------------------
// Flash attention: fp16 mma, Q/K/V single fp16 (Q pre-scaled).
// CTA = 64 queries (4 warps x 16 rows), KV tiles of 64, 2-stage cp.async.
// ---------------------------------------------------------------------------
#define ROWF 144
#define TILEF (64 * ROWF)   // 9216
#define FL_QH 0
#define FL_ST(s) (TILEF + (s) * 2 * TILEF)
#define FL_SMEM (5 * TILEF)  // 46080

__global__ void __launch_bounds__(128, 3) flash_mma(
    const __half* __restrict__ Qg,
    const __half* __restrict__ Kg, const __half* __restrict__ Vg,
    __half* __restrict__ at_o)
{
    extern __shared__ char smf[];
    const uint32_t sbase = (uint32_t)__cvta_generic_to_shared(smf);
    const int tid = threadIdx.x, wid = tid >> 5, lane = tid & 31;
    const int g = lane >> 2, tg = lane & 3;
    const int qt = 31 - blockIdx.x;
    const int bh = blockIdx.y;

    const __half* Qb = Qg + (size_t)bh * TT * DD;
    const __half* Kb = Kg + (size_t)bh * TT * DD;
    const __half* Vb = Vg + (size_t)bh * DD * TT;

    const int lrow = lane & 15, lhalf = lane >> 4;

#define ISSUE_KV(stg, kvi) do {                                                \
    const uint32_t _sb = sbase + FL_ST(stg);                                   \
    _Pragma("unroll")                                                          \
    for (int _i = 0; _i < 4; _i++) {                                           \
        int _ch = _i * 128 + tid;                                              \
        int _row = _ch >> 3, _c = _ch & 7;                                     \
        cp16(_sb + _row * ROWF + _c * 16,                                      \
             Kb + (size_t)(kvi) * 4096 + _ch * 8);                             \
        cp16(_sb + TILEF + _row * ROWF + _c * 16,                              \
             Vb + (size_t)_row * TT + (size_t)(kvi) * 64 + _c * 8);            \
    }                                                                          \
} while (0)

    // Prologue: Q tile (group 0), KV tile 0 (group 1)
#pragma unroll
    for (int i = 0; i < 4; i++) {
        int ch = i * 128 + tid;
        int row = ch >> 3, c = ch & 7;
        cp16(sbase + FL_QH + row * ROWF + c * 16, Qb + (size_t)qt * 4096 + ch * 8);
    }
    cp_commit();
    ISSUE_KV(0, 0);
    cp_commit();
    cp_wait1();
    __syncthreads();

    // Q fragments via ldmatrix (held for whole kernel)
    uint32_t qf[4][4];
    {
        const uint32_t qoff = sbase + (uint32_t)((wid * 16 + lrow) * ROWF + lhalf * 16);
#pragma unroll
        for (int j = 0; j < 4; j++) ldsm4(qf[j], qoff + FL_QH + j * 32);
    }

    float oacc[8][4];
#pragma unroll
    for (int i = 0; i < 8; i++)
#pragma unroll
        for (int jj = 0; jj < 4; jj++) oacc[i][jj] = 0.0f;
    float m0 = -1e30f, m1 = -1e30f, l0 = 0.0f, l1 = 0.0f;

    const uint32_t foff = (uint32_t)(lrow * ROWF + lhalf * 16);

    for (int kv = 0; kv <= qt; kv++) {
        const int s = kv & 1;
        if (kv < qt) { ISSUE_KV(s ^ 1, kv + 1); cp_commit(); cp_wait1(); }
        else cp_wait0();
        __syncthreads();

        const uint32_t KHs = sbase + FL_ST(s) + foff;
        const uint32_t VHs = KHs + TILEF;

        // S = Q @ K^T
        float sa[8][4];
#pragma unroll
        for (int nt = 0; nt < 8; nt++)
#pragma unroll
            for (int jj = 0; jj < 4; jj++) sa[nt][jj] = 0.0f;

#pragma unroll
        for (int j = 0; j < 4; j++) {
            uint32_t rk[4][4];
#pragma unroll
            for (int p = 0; p < 4; p++) ldsm4(rk[p], KHs + p * 16 * ROWF + j * 32);
#pragma unroll
            for (int p = 0; p < 4; p++) {
                uint32_t bE[2] = { rk[p][0], rk[p][2] }, bO[2] = { rk[p][1], rk[p][3] };
                mma_f16(sa[2 * p],     qf[j], bE);
                mma_f16(sa[2 * p + 1], qf[j], bO);
            }
        }

        // Causal mask (diagonal tile only)
        if (kv == qt) {
            const int r0 = wid * 16 + g, r1 = r0 + 8;
#pragma unroll
            for (int nt = 0; nt < 8; nt++) {
                int c0 = nt * 8 + tg * 2;
                if (c0 > r0)     sa[nt][0] = -1e30f;
                if (c0 + 1 > r0) sa[nt][1] = -1e30f;
                if (c0 > r1)     sa[nt][2] = -1e30f;
                if (c0 + 1 > r1) sa[nt][3] = -1e30f;
            }
        }

        // Online softmax (log2 domain)
        float mt0 = sa[0][0], mt1 = sa[0][2];
#pragma unroll
        for (int nt = 0; nt < 8; nt++) {
            mt0 = fmaxf(mt0, fmaxf(sa[nt][0], sa[nt][1]));
            mt1 = fmaxf(mt1, fmaxf(sa[nt][2], sa[nt][3]));
        }
        mt0 = fmaxf(mt0, __shfl_xor_sync(0xffffffffu, mt0, 1));
        mt0 = fmaxf(mt0, __shfl_xor_sync(0xffffffffu, mt0, 2));
        mt1 = fmaxf(mt1, __shfl_xor_sync(0xffffffffu, mt1, 1));
        mt1 = fmaxf(mt1, __shfl_xor_sync(0xffffffffu, mt1, 2));

        float mn0 = fmaxf(m0, mt0), mn1 = fmaxf(m1, mt1);
        float cr0 = ex2f(m0 - mn0), cr1 = ex2f(m1 - mn1);
        m0 = mn0; m1 = mn1;

        float s0 = 0.0f, s1 = 0.0f;
#pragma unroll
        for (int nt = 0; nt < 8; nt++) {
            sa[nt][0] = ex2f(sa[nt][0] - mn0);
            sa[nt][1] = ex2f(sa[nt][1] - mn0);
            sa[nt][2] = ex2f(sa[nt][2] - mn1);
            sa[nt][3] = ex2f(sa[nt][3] - mn1);
            s0 += sa[nt][0] + sa[nt][1];
            s1 += sa[nt][2] + sa[nt][3];
        }
        s0 += __shfl_xor_sync(0xffffffffu, s0, 1);
        s0 += __shfl_xor_sync(0xffffffffu, s0, 2);
        s1 += __shfl_xor_sync(0xffffffffu, s1, 1);
        s1 += __shfl_xor_sync(0xffffffffu, s1, 2);
        l0 = l0 * cr0 + s0;
        l1 = l1 * cr1 + s1;

#pragma unroll
        for (int nt = 0; nt < 8; nt++) {
            oacc[nt][0] *= cr0; oacc[nt][1] *= cr0;
            oacc[nt][2] *= cr1; oacc[nt][3] *= cr1;
        }

        // Pack P to fp16 A-fragments
        uint32_t pa[4][4];
#pragma unroll
        for (int j = 0; j < 4; j++) {
            pa[j][0] = pack_f16(sa[2 * j][0], sa[2 * j][1]);
            pa[j][1] = pack_f16(sa[2 * j][2], sa[2 * j][3]);
            pa[j][2] = pack_f16(sa[2 * j + 1][0], sa[2 * j + 1][1]);
            pa[j][3] = pack_f16(sa[2 * j + 1][2], sa[2 * j + 1][3]);
        }

        // O += P @ V
#pragma unroll
        for (int j = 0; j < 4; j++) {
            uint32_t rv[4][4];
#pragma unroll
            for (int p = 0; p < 4; p++) ldsm4(rv[p], VHs + p * 16 * ROWF + j * 32);
#pragma unroll
            for (int p = 0; p < 4; p++) {
                uint32_t bE[2] = { rv[p][0], rv[p][2] }, bO[2] = { rv[p][1], rv[p][3] };
                mma_f16(oacc[2 * p],     pa[j], bE);
                mma_f16(oacc[2 * p + 1], pa[j], bO);
            }
        }
        __syncthreads();
    }

    // Epilogue: normalize, write att fp16 [M=B*T, C] (c = h*64+d)
    const float i0 = 1.0f / l0, i1 = 1.0f / l1;
    const int b = bh >> 4, h = bh & 15;
    const int t0 = qt * 64 + wid * 16 + g;
    const size_t row0 = ((size_t)b * TT + t0) * CC + h * DD;
    const size_t row1 = row0 + (size_t)8 * CC;
#pragma unroll
    for (int nt = 0; nt < 8; nt++) {
        const int d = nt * 8 + tg * 2;
        *(uint32_t*)(at_o + row0 + d) = pack_f16(oacc[nt][0] * i0, oacc[nt][1] * i0);
        *(uint32_t*)(at_o + row1 + d) = pack_f16(oacc[nt][2] * i1, oacc[nt][3] * i1);
    }
#undef ISSUE_KV
}

// ---------------------------------------------------------------------------
extern "C" void kernel_launch(void* const* d_in, const int* in_sizes, int n_in,
                              void* d_out, int out_size)
{
    (void)in_sizes; (void)n_in; (void)out_size;
    const float* x      = (const float*)d_in[0];
    const float* W_attn = (const float*)d_in[1];
    const float* b_attn = (const float*)d_in[2];
    const float* W_proj = (const float*)d_in[3];
    const float* b_proj = (const float*)d_in[4];
    float* out = (float*)d_out;

    __half *xh, *xl, *wa, *wp, *at, *q, *k, *v;
    cudaGetSymbolAddress((void**)&xh, g_xh);
    cudaGetSymbolAddress((void**)&xl, g_xl);
    cudaGetSymbolAddress((void**)&wa, g_wa);
    cudaGetSymbolAddress((void**)&wp, g_wp);
    cudaGetSymbolAddress((void**)&at, g_at);
    cudaGetSymbolAddress((void**)&q, g_q);
    cudaGetSymbolAddress((void**)&k, g_k);
    cudaGetSymbolAddress((void**)&v, g_v);

    const int SM_QKV = NSTG * 3 * TILE_B;   // 92160
    const int SM_PRJ = NSTG * 2 * TILE_B;   // 61440
    cudaFuncSetAttribute((const void*)mma_gemm<1, 2>,
                         cudaFuncAttributeMaxDynamicSharedMemorySize, SM_QKV);
    cudaFuncSetAttribute((const void*)mma_gemm<0, 1>,
                         cudaFuncAttributeMaxDynamicSharedMemorySize, SM_PRJ);
    cudaFuncSetAttribute((const void*)flash_mma,
                         cudaFuncAttributeMaxDynamicSharedMemorySize, FL_SMEM);

    // 1) Split x into fp16 hi/lo
    prep_split<<<MROWS * CC / 4 / 256, 256>>>(x, xh, xl);

    // 2) Transpose weights to fp16 [N,K]
    {
        dim3 blk(32, 8);
        prep_wt<<<dim3(3 * CC / 32, CC / 32), blk>>>(W_attn, wa, CC, 3 * CC);
        prep_wt<<<dim3(CC / 32, CC / 32), blk>>>(W_proj, wp, CC, CC);
    }

    // 3) QKV GEMM (A split-2) -> q (scaled), k, v^T — all single fp16
    mma_gemm<1, 2><<<dim3(3 * CC / 128, MROWS / 128), 128, SM_QKV>>>(
        xh, xl, wa, b_attn, nullptr, q, k, v, 3 * CC, CC);

    // 4) Flash attention -> att fp16
    flash_mma<<<dim3(TT / 64, BB * HH), 128, FL_SMEM>>>(q, k, v, at);

    // 5) Projection GEMM (A single) -> out (fp32)
    mma_gemm<0, 1><<<dim3(CC / 128, MROWS / 128), 128, SM_PRJ>>>(
        at, nullptr, wp, b_proj, out, nullptr, nullptr, nullptr, CC, CC);
}

// round 10
// speedup vs baseline: 17.7924x; 1.3275x over previous
#include <cuda_runtime.h>
#include <cuda_bf16.h>
#include <cuda_fp16.h>
#include <math.h>
#include <stdint.h>

// Problem constants
#define BB 4
#define TT 2048
#define CC 1024
#define HH 16
#define DD 64
#define MROWS (BB * TT)   // 8192
#define QSC (0.125f * 1.44269504088896f)   // 1/sqrt(D) * log2(e), folded into Q

// ---------------------------------------------------------------------------
// Scratch (device globals)
// ---------------------------------------------------------------------------
__device__ __half g_x[MROWS * CC];                        // x fp16 [M,K]
__device__ __half g_wa[3 * CC * CC];                      // W_attn^T [3072,K]
__device__ __half g_wp[CC * CC];                          // W_proj^T [1024,K]
__device__ __half g_q[BB * HH * TT * DD];                 // [B,H,T,D] scaled fp16
__device__ __half g_k[BB * HH * TT * DD];                 // [B,H,T,D]
__device__ __half g_v[BB * HH * DD * TT];                 // [B,H,D,T] (V^T)
__device__ __half g_at[MROWS * CC];                       // att fp16 [M,K]

// ---------------------------------------------------------------------------
// PTX helpers
// ---------------------------------------------------------------------------
__device__ __forceinline__ void mma_f16(float* c, const uint32_t* a,
                                        const uint32_t* b) {
    asm volatile(
        "mma.sync.aligned.m16n8k16.row.col.f32.f16.f16.f32 "
        "{%0,%1,%2,%3}, {%4,%5,%6,%7}, {%8,%9}, {%0,%1,%2,%3};"
        : "+f"(c[0]), "+f"(c[1]), "+f"(c[2]), "+f"(c[3])
        : "r"(a[0]), "r"(a[1]), "r"(a[2]), "r"(a[3]), "r"(b[0]), "r"(b[1]));
}
__device__ __forceinline__ void ldsm4(uint32_t* r, uint32_t addr) {
    asm volatile("ldmatrix.sync.aligned.m8n8.x4.shared.b16 {%0,%1,%2,%3}, [%4];"
                 : "=r"(r[0]), "=r"(r[1]), "=r"(r[2]), "=r"(r[3]) : "r"(addr));
}
__device__ __forceinline__ float ex2f(float x) {
    float y;
    asm("ex2.approx.f32 %0, %1;" : "=f"(y) : "f"(x));
    return y;
}
__device__ __forceinline__ uint32_t pack_f16(float lo, float hi) {
    __half2 h = __float22half2_rn(make_float2(lo, hi));
    return *(uint32_t*)&h;
}
__device__ __forceinline__ void cp16(uint32_t s, const void* g) {
    asm volatile("cp.async.cg.shared.global [%0], [%1], 16;" :: "r"(s), "l"(g));
}
__device__ __forceinline__ void cp_commit() {
    asm volatile("cp.async.commit_group;" ::: "memory");
}
__device__ __forceinline__ void cp_wait1() {
    asm volatile("cp.async.wait_group 1;" ::: "memory");
}
__device__ __forceinline__ void cp_wait0() {
    asm volatile("cp.async.wait_group 0;" ::: "memory");
}

// ---------------------------------------------------------------------------
// Prep kernels
// ---------------------------------------------------------------------------
__global__ void prep_convert(const float* __restrict__ src,
                             __half* __restrict__ dst) {
    int idx = blockIdx.x * blockDim.x + threadIdx.x;
    float4 v = ((const float4*)src)[idx];
    *(uint32_t*)(dst + (size_t)idx * 4)     = pack_f16(v.x, v.y);
    *(uint32_t*)(dst + (size_t)idx * 4 + 2) = pack_f16(v.z, v.w);
}

__global__ void prep_wt(const float* __restrict__ W,
                        __half* __restrict__ Wt, int K, int N) {
    __shared__ float t[32][33];
    const int tx = threadIdx.x, ty = threadIdx.y;
    const int n0 = blockIdx.x * 32, k0 = blockIdx.y * 32;
#pragma unroll
    for (int i = 0; i < 4; i++)
        t[ty + i * 8][tx] = W[(size_t)(k0 + ty + i * 8) * N + n0 + tx];
    __syncthreads();
#pragma unroll
    for (int i = 0; i < 4; i++)
        Wt[(size_t)(n0 + ty + i * 8) * K + k0 + tx] = __float2half(t[tx][ty + i * 8]);
}

// ---------------------------------------------------------------------------
// fp16 GEMM: C = A @ B^T + bias (single fp16 A and B).
// CTA 128x128, 4 warps (2x2), warp tile 64x64, K-chunk 32, 3-stage cp.async.
// MODE 0: fp32 row-major out. MODE 1: QKV epilogue (fp16 q/k/v^T outputs).
// ---------------------------------------------------------------------------
#define ROWB 80
#define TILE_B (128 * ROWB)           // 10240
#define NSTG 3
#define STAGE_B (2 * TILE_B)          // 20480 (A, B)
#define GEMM_SMEM (NSTG * STAGE_B)    // 61440

template <int MODE>
__global__ void __launch_bounds__(128, 2) mma_gemm(
    const __half* __restrict__ A_, const __half* __restrict__ B_,
    const float* __restrict__ bias,
    float* __restrict__ Cout,
    __half* __restrict__ Q_o, __half* __restrict__ K_o, __half* __restrict__ V_o,
    int N, int K)
{
    extern __shared__ char smg[];
    const uint32_t sbase = (uint32_t)__cvta_generic_to_shared(smg);
    const int tid = threadIdx.x;
    const int wid = tid >> 5, lane = tid & 31;
    const int wm = wid >> 1, wn = wid & 1;
    const int g = lane >> 2, tg = lane & 3;
    const int lrow = lane & 15, lhalf = lane >> 4;
    const int m0 = blockIdx.y * 128, n0 = blockIdx.x * 128;

    const __half* A = A_ + (size_t)m0 * K;
    const __half* B = B_ + (size_t)n0 * K;
    const __half* tp[2] = { A, B };

    const uint32_t aoff = (uint32_t)((wm * 64 + lrow) * ROWB + lhalf * 16);
    const uint32_t boff = (uint32_t)((wn * 64 + lrow) * ROWB + lhalf * 16) + TILE_B;

    float acc[4][8][4];
#pragma unroll
    for (int mt = 0; mt < 4; mt++)
#pragma unroll
        for (int nt = 0; nt < 8; nt++)
#pragma unroll
            for (int i = 0; i < 4; i++) acc[mt][nt][i] = 0.0f;

#define GEMM_ISSUE(chunk) do {                                                 \
    const uint32_t _sb = sbase + ((chunk) % NSTG) * STAGE_B;                   \
    const int _kc = (chunk) * 32;                                              \
    _Pragma("unroll")                                                          \
    for (int _i = 0; _i < 8; _i++) {                                           \
        int _e = _i * 128 + tid;                                               \
        int _t = _e >> 9, _r = (_e & 511) >> 2, _h = _e & 3;                   \
        cp16(_sb + _t * TILE_B + _r * ROWB + _h * 16,                          \
             tp[_t] + (size_t)_r * K + _kc + _h * 8);                          \
    }                                                                          \
} while (0)

    const int NCH = K / 32;
    GEMM_ISSUE(0); cp_commit();
    GEMM_ISSUE(1); cp_commit();

    for (int c = 0; c < NCH; c++) {
        cp_wait1();
        __syncthreads();

        const uint32_t st = sbase + (c % NSTG) * STAGE_B;

#pragma unroll
        for (int ks = 0; ks < 2; ks++) {
            uint32_t ah[4][4];
#pragma unroll
            for (int mt = 0; mt < 4; mt++)
                ldsm4(ah[mt], st + aoff + mt * 16 * ROWB + ks * 32);
#pragma unroll
            for (int p = 0; p < 4; p++) {
                uint32_t rb[4];
                ldsm4(rb, st + boff + p * 16 * ROWB + ks * 32);
                uint32_t bE[2] = { rb[0], rb[2] }, bO[2] = { rb[1], rb[3] };
#pragma unroll
                for (int mt = 0; mt < 4; mt++) mma_f16(acc[mt][2 * p],     ah[mt], bE);
#pragma unroll
                for (int mt = 0; mt < 4; mt++) mma_f16(acc[mt][2 * p + 1], ah[mt], bO);
            }
        }

        if (c + 2 < NCH) GEMM_ISSUE(c + 2);
        cp_commit();   // empty group at tail keeps wait accounting uniform
    }
#undef GEMM_ISSUE

    // Epilogue
#pragma unroll
    for (int mt = 0; mt < 4; mt++) {
#pragma unroll
        for (int nt = 0; nt < 8; nt++) {
            const int cg = n0 + wn * 64 + nt * 8 + tg * 2;
            const int r0g = m0 + wm * 64 + mt * 16 + g;
            const float b0 = __ldg(bias + cg);
            const float b1 = __ldg(bias + cg + 1);
            float f00 = acc[mt][nt][0] + b0, f01 = acc[mt][nt][1] + b1;
            float f10 = acc[mt][nt][2] + b0, f11 = acc[mt][nt][3] + b1;
            if (MODE == 0) {
                *(float2*)(Cout + (size_t)r0g * N + cg) = make_float2(f00, f01);
                *(float2*)(Cout + (size_t)(r0g + 8) * N + cg) = make_float2(f10, f11);
            } else {
                const int which = cg >> 10;
                const int c10 = cg & 1023;
                const int h = c10 >> 6;
                const int d = c10 & 63;
                const int br = r0g >> 11, tr = r0g & 2047;
                if (which == 0) {
                    size_t i0 = ((((size_t)br * HH + h) * TT) + tr) * DD + d;
                    *(uint32_t*)(Q_o + i0)          = pack_f16(f00 * QSC, f01 * QSC);
                    *(uint32_t*)(Q_o + i0 + 8 * DD) = pack_f16(f10 * QSC, f11 * QSC);
                } else if (which == 1) {
                    size_t i0 = ((((size_t)br * HH + h) * TT) + tr) * DD + d;
                    *(uint32_t*)(K_o + i0)          = pack_f16(f00, f01);
                    *(uint32_t*)(K_o + i0 + 8 * DD) = pack_f16(f10, f11);
                } else {
                    size_t i0 = (((size_t)br * HH + h) * DD + d) * TT + tr;
                    V_o[i0]          = __float2half(f00);
                    V_o[i0 + TT]     = __float2half(f01);
                    V_o[i0 + 8]      = __float2half(f10);
                    V_o[i0 + TT + 8] = __float2half(f11);
                }
            }
        }
    }
}

// ---------------------------------------------------------------------------
// Flash attention: fp16 mma, Q/K/V single fp16 (Q pre-scaled).
// CTA = 64 queries (4 warps x 16 rows), KV tiles of 64, 2-stage cp.async.
// ---------------------------------------------------------------------------
#define ROWF 144
#define TILEF (64 * ROWF)   // 9216
#define FL_QH 0
#define FL_ST(s) (TILEF + (s) * 2 * TILEF)
#define FL_SMEM (5 * TILEF)  // 46080

__global__ void __launch_bounds__(128, 3) flash_mma(
    const __half* __restrict__ Qg,
    const __half* __restrict__ Kg, const __half* __restrict__ Vg,
    __half* __restrict__ at_o)
{
    extern __shared__ char smf[];
    const uint32_t sbase = (uint32_t)__cvta_generic_to_shared(smf);
    const int tid = threadIdx.x, wid = tid >> 5, lane = tid & 31;
    const int g = lane >> 2, tg = lane & 3;
    const int qt = 31 - blockIdx.x;
    const int bh = blockIdx.y;

    const __half* Qb = Qg + (size_t)bh * TT * DD;
    const __half* Kb = Kg + (size_t)bh * TT * DD;
    const __half* Vb = Vg + (size_t)bh * DD * TT;

    const int lrow = lane & 15, lhalf = lane >> 4;

#define ISSUE_KV(stg, kvi) do {                                                \
    const uint32_t _sb = sbase + FL_ST(stg);                                   \
    _Pragma("unroll")                                                          \
    for (int _i = 0; _i < 4; _i++) {                                           \
        int _ch = _i * 128 + tid;                                              \
        int _row = _ch >> 3, _c = _ch & 7;                                     \
        cp16(_sb + _row * ROWF + _c * 16,                                      \
             Kb + (size_t)(kvi) * 4096 + _ch * 8);                             \
        cp16(_sb + TILEF + _row * ROWF + _c * 16,                              \
             Vb + (size_t)_row * TT + (size_t)(kvi) * 64 + _c * 8);            \
    }                                                                          \
} while (0)

    // Prologue: Q tile (group 0), KV tile 0 (group 1)
#pragma unroll
    for (int i = 0; i < 4; i++) {
        int ch = i * 128 + tid;
        int row = ch >> 3, c = ch & 7;
        cp16(sbase + FL_QH + row * ROWF + c * 16, Qb + (size_t)qt * 4096 + ch * 8);
    }
    cp_commit();
    ISSUE_KV(0, 0);
    cp_commit();
    cp_wait1();
    __syncthreads();

    // Q fragments via ldmatrix (held for whole kernel)
    uint32_t qf[4][4];
    {
        const uint32_t qoff = sbase + (uint32_t)((wid * 16 + lrow) * ROWF + lhalf * 16);
#pragma unroll
        for (int j = 0; j < 4; j++) ldsm4(qf[j], qoff + FL_QH + j * 32);
    }

    float oacc[8][4];
#pragma unroll
    for (int i = 0; i < 8; i++)
#pragma unroll
        for (int jj = 0; jj < 4; jj++) oacc[i][jj] = 0.0f;
    float m0 = -1e30f, m1 = -1e30f, l0 = 0.0f, l1 = 0.0f;

    const uint32_t foff = (uint32_t)(lrow * ROWF + lhalf * 16);

    for (int kv = 0; kv <= qt; kv++) {
        const int s = kv & 1;
        if (kv < qt) { ISSUE_KV(s ^ 1, kv + 1); cp_commit(); cp_wait1(); }
        else cp_wait0();
        __syncthreads();

        const uint32_t KHs = sbase + FL_ST(s) + foff;
        const uint32_t VHs = KHs + TILEF;

        // S = Q @ K^T
        float sa[8][4];
#pragma unroll
        for (int nt = 0; nt < 8; nt++)
#pragma unroll
            for (int jj = 0; jj < 4; jj++) sa[nt][jj] = 0.0f;

#pragma unroll
        for (int j = 0; j < 4; j++) {
            uint32_t rk[4][4];
#pragma unroll
            for (int p = 0; p < 4; p++) ldsm4(rk[p], KHs + p * 16 * ROWF + j * 32);
#pragma unroll
            for (int p = 0; p < 4; p++) {
                uint32_t bE[2] = { rk[p][0], rk[p][2] }, bO[2] = { rk[p][1], rk[p][3] };
                mma_f16(sa[2 * p],     qf[j], bE);
                mma_f16(sa[2 * p + 1], qf[j], bO);
            }
        }

        // Causal mask (diagonal tile only)
        if (kv == qt) {
            const int r0 = wid * 16 + g, r1 = r0 + 8;
#pragma unroll
            for (int nt = 0; nt < 8; nt++) {
                int c0 = nt * 8 + tg * 2;
                if (c0 > r0)     sa[nt][0] = -1e30f;
                if (c0 + 1 > r0) sa[nt][1] = -1e30f;
                if (c0 > r1)     sa[nt][2] = -1e30f;
                if (c0 + 1 > r1) sa[nt][3] = -1e30f;
            }
        }

        // Online softmax (log2 domain)
        float mt0 = sa[0][0], mt1 = sa[0][2];
#pragma unroll
        for (int nt = 0; nt < 8; nt++) {
            mt0 = fmaxf(mt0, fmaxf(sa[nt][0], sa[nt][1]));
            mt1 = fmaxf(mt1, fmaxf(sa[nt][2], sa[nt][3]));
        }
        mt0 = fmaxf(mt0, __shfl_xor_sync(0xffffffffu, mt0, 1));
        mt0 = fmaxf(mt0, __shfl_xor_sync(0xffffffffu, mt0, 2));
        mt1 = fmaxf(mt1, __shfl_xor_sync(0xffffffffu, mt1, 1));
        mt1 = fmaxf(mt1, __shfl_xor_sync(0xffffffffu, mt1, 2));

        float mn0 = fmaxf(m0, mt0), mn1 = fmaxf(m1, mt1);
        float cr0 = ex2f(m0 - mn0), cr1 = ex2f(m1 - mn1);
        m0 = mn0; m1 = mn1;

        float s0 = 0.0f, s1 = 0.0f;
#pragma unroll
        for (int nt = 0; nt < 8; nt++) {
            sa[nt][0] = ex2f(sa[nt][0] - mn0);
            sa[nt][1] = ex2f(sa[nt][1] - mn0);
            sa[nt][2] = ex2f(sa[nt][2] - mn1);
            sa[nt][3] = ex2f(sa[nt][3] - mn1);
            s0 += sa[nt][0] + sa[nt][1];
            s1 += sa[nt][2] + sa[nt][3];
        }
        s0 += __shfl_xor_sync(0xffffffffu, s0, 1);
        s0 += __shfl_xor_sync(0xffffffffu, s0, 2);
        s1 += __shfl_xor_sync(0xffffffffu, s1, 1);
        s1 += __shfl_xor_sync(0xffffffffu, s1, 2);
        l0 = l0 * cr0 + s0;
        l1 = l1 * cr1 + s1;

#pragma unroll
        for (int nt = 0; nt < 8; nt++) {
            oacc[nt][0] *= cr0; oacc[nt][1] *= cr0;
            oacc[nt][2] *= cr1; oacc[nt][3] *= cr1;
        }

        // Pack P to fp16 A-fragments
        uint32_t pa[4][4];
#pragma unroll
        for (int j = 0; j < 4; j++) {
            pa[j][0] = pack_f16(sa[2 * j][0], sa[2 * j][1]);
            pa[j][1] = pack_f16(sa[2 * j][2], sa[2 * j][3]);
            pa[j][2] = pack_f16(sa[2 * j + 1][0], sa[2 * j + 1][1]);
            pa[j][3] = pack_f16(sa[2 * j + 1][2], sa[2 * j + 1][3]);
        }

        // O += P @ V
#pragma unroll
        for (int j = 0; j < 4; j++) {
            uint32_t rv[4][4];
#pragma unroll
            for (int p = 0; p < 4; p++) ldsm4(rv[p], VHs + p * 16 * ROWF + j * 32);
#pragma unroll
            for (int p = 0; p < 4; p++) {
                uint32_t bE[2] = { rv[p][0], rv[p][2] }, bO[2] = { rv[p][1], rv[p][3] };
                mma_f16(oacc[2 * p],     pa[j], bE);
                mma_f16(oacc[2 * p + 1], pa[j], bO);
            }
        }
        __syncthreads();
    }

    // Epilogue: normalize, write att fp16 [M=B*T, C] (c = h*64+d)
    const float i0 = 1.0f / l0, i1 = 1.0f / l1;
    const int b = bh >> 4, h = bh & 15;
    const int t0 = qt * 64 + wid * 16 + g;
    const size_t row0 = ((size_t)b * TT + t0) * CC + h * DD;
    const size_t row1 = row0 + (size_t)8 * CC;
#pragma unroll
    for (int nt = 0; nt < 8; nt++) {
        const int d = nt * 8 + tg * 2;
        *(uint32_t*)(at_o + row0 + d) = pack_f16(oacc[nt][0] * i0, oacc[nt][1] * i0);
        *(uint32_t*)(at_o + row1 + d) = pack_f16(oacc[nt][2] * i1, oacc[nt][3] * i1);
    }
#undef ISSUE_KV
}

// ---------------------------------------------------------------------------
extern "C" void kernel_launch(void* const* d_in, const int* in_sizes, int n_in,
                              void* d_out, int out_size)
{
    (void)in_sizes; (void)n_in; (void)out_size;
    const float* x      = (const float*)d_in[0];
    const float* W_attn = (const float*)d_in[1];
    const float* b_attn = (const float*)d_in[2];
    const float* W_proj = (const float*)d_in[3];
    const float* b_proj = (const float*)d_in[4];
    float* out = (float*)d_out;

    __half *xp, *wa, *wp, *at, *q, *k, *v;
    cudaGetSymbolAddress((void**)&xp, g_x);
    cudaGetSymbolAddress((void**)&wa, g_wa);
    cudaGetSymbolAddress((void**)&wp, g_wp);
    cudaGetSymbolAddress((void**)&at, g_at);
    cudaGetSymbolAddress((void**)&q, g_q);
    cudaGetSymbolAddress((void**)&k, g_k);
    cudaGetSymbolAddress((void**)&v, g_v);

    cudaFuncSetAttribute((const void*)mma_gemm<1>,
                         cudaFuncAttributeMaxDynamicSharedMemorySize, GEMM_SMEM);
    cudaFuncSetAttribute((const void*)mma_gemm<0>,
                         cudaFuncAttributeMaxDynamicSharedMemorySize, GEMM_SMEM);
    cudaFuncSetAttribute((const void*)flash_mma,
                         cudaFuncAttributeMaxDynamicSharedMemorySize, FL_SMEM);

    // 1) Convert x to fp16
    prep_convert<<<MROWS * CC / 4 / 256, 256>>>(x, xp);

    // 2) Transpose weights to fp16 [N,K]
    {
        dim3 blk(32, 8);
        prep_wt<<<dim3(3 * CC / 32, CC / 32), blk>>>(W_attn, wa, CC, 3 * CC);
        prep_wt<<<dim3(CC / 32, CC / 32), blk>>>(W_proj, wp, CC, CC);
    }

    // 3) QKV GEMM -> q (scaled), k, v^T — all single fp16
    mma_gemm<1><<<dim3(3 * CC / 128, MROWS / 128), 128, GEMM_SMEM>>>(
        xp, wa, b_attn, nullptr, q, k, v, 3 * CC, CC);

    // 4) Flash attention -> att fp16
    flash_mma<<<dim3(TT / 64, BB * HH), 128, FL_SMEM>>>(q, k, v, at);

    // 5) Projection GEMM -> out (fp32)
    mma_gemm<0><<<dim3(CC / 128, MROWS / 128), 128, GEMM_SMEM>>>(
        at, wp, b_proj, out, nullptr, nullptr, nullptr, CC, CC);
}